// round 1
// baseline (speedup 1.0000x reference)
#include <cuda_runtime.h>
#include <cuda_bf16.h>
#include <math.h>

// ---------------------------------------------------------------------------
// SimpleHGN forward: 3-layer heterogeneous GAT.
// N=50000 nodes (20000/17000/13000 per type), E=800000 edges, 6 edge types.
// Strategy:
//   - build dst-sorted CSR once per call (hist + single-block scan + scatter)
//   - per layer: fp32 tiled GEMM for feat (+residual), per-node el/er,
//     per-edge raw attention, per-(node,head) max/sum, per-edge normalized a,
//     warp-per-dst aggregation (no atomics in hot path).
// ---------------------------------------------------------------------------

#define N_NODES 50000
#define N_EDGES 800000
#define N0 20000
#define N1 17000
#define N2 13000

// ------------------------------ scratch (device globals) -------------------
__device__ int   g_cnt[N_NODES];
__device__ int   g_rowptr[N_NODES + 1];
__device__ int   g_cursor[N_NODES];
__device__ int   g_srcS[N_EDGES];
__device__ int   g_dstS[N_EDGES];
__device__ int   g_etS[N_EDGES];

__device__ float g_h0[N_NODES * 64];
__device__ float g_feat[N_NODES * 256];
__device__ float g_res[N_NODES * 256];
__device__ float g_hA[N_NODES * 256];
__device__ float g_hB[N_NODES * 256];
__device__ float g_att[N_EDGES * 8];
__device__ float g_a0[N_EDGES * 8];
__device__ float g_el[N_NODES * 8];
__device__ float g_er[N_NODES * 8];
__device__ float g_m[N_NODES * 8];
__device__ float g_s[N_NODES * 8];
__device__ float g_etatt[3 * 6 * 8];   // per-layer edge-type attention terms

// ------------------------------ CSR build ----------------------------------
__global__ void hist_kernel(const int* __restrict__ dst) {
    int e = blockIdx.x * blockDim.x + threadIdx.x;
    if (e < N_EDGES) atomicAdd(&g_cnt[dst[e]], 1);
}

// single-block exclusive scan of g_cnt -> g_rowptr (N_NODES+1)
__global__ void scan_kernel() {
    __shared__ int sh[1024];
    __shared__ int carry_sh;
    int t = threadIdx.x;
    if (t == 0) carry_sh = 0;
    __syncthreads();
    for (int base = 0; base < N_NODES; base += 1024) {
        int cbase = carry_sh;
        int i = base + t;
        int v = (i < N_NODES) ? g_cnt[i] : 0;
        sh[t] = v;
        __syncthreads();
        #pragma unroll
        for (int off = 1; off < 1024; off <<= 1) {
            int tmp = (t >= off) ? sh[t - off] : 0;
            __syncthreads();
            sh[t] += tmp;
            __syncthreads();
        }
        if (i < N_NODES) g_rowptr[i + 1] = cbase + sh[t];
        if (t == 1023) carry_sh = cbase + sh[1023];
        __syncthreads();
    }
    if (t == 0) g_rowptr[0] = 0;
}

__global__ void cursor_kernel() {
    int i = blockIdx.x * blockDim.x + threadIdx.x;
    if (i < N_NODES) g_cursor[i] = g_rowptr[i];
}

__global__ void scatter_kernel(const int* __restrict__ src, const int* __restrict__ dst,
                               const int* __restrict__ et) {
    int e = blockIdx.x * blockDim.x + threadIdx.x;
    if (e >= N_EDGES) return;
    int d = dst[e];
    int pos = atomicAdd(&g_cursor[d], 1);
    g_srcS[pos] = src[e];
    g_dstS[pos] = d;
    g_etS[pos]  = et[e];
}

// ------------------------------ edge-type attention ------------------------
// out[t*H+h] = sum_d ( sum_k eemb[t,k] * We[k, h*64+d] ) * ae[h,d]
__global__ void etype_att_kernel(const float* __restrict__ eemb, const float* __restrict__ We,
                                 const float* __restrict__ ae, float* __restrict__ out, int H) {
    int t = blockIdx.x / H;
    int h = blockIdx.x % H;
    int d = threadIdx.x;   // 0..63
    int Wcols = H * 64;
    float v = 0.f;
    #pragma unroll 4
    for (int k = 0; k < 64; k++)
        v += eemb[t * 64 + k] * We[k * Wcols + h * 64 + d];
    v *= ae[h * 64 + d];
    __shared__ float sh[64];
    sh[d] = v;
    __syncthreads();
    #pragma unroll
    for (int o = 32; o > 0; o >>= 1) {
        if (d < o) sh[d] += sh[d + o];
        __syncthreads();
    }
    if (d == 0) out[t * H + h] = sh[0];
}

// ------------------------------ GEMM ---------------------------------------
// C[M,Nc] = A[M,K] @ B[K,Nc] (+bias). 64x64 tile, BK=16, 256 threads, 4x4/thread.
template <bool BIAS>
__global__ void gemm64(const float* __restrict__ A, const float* __restrict__ B,
                       const float* __restrict__ bias, float* __restrict__ C,
                       int M, int Nc, int K, int ldc) {
    __shared__ float As[16][65];
    __shared__ float Bs[16][65];
    int tid = threadIdx.x;
    int tx = tid & 15, ty = tid >> 4;
    int row0 = blockIdx.y * 64, col0 = blockIdx.x * 64;
    float acc[4][4] = {};
    for (int k0 = 0; k0 < K; k0 += 16) {
        #pragma unroll
        for (int i = 0; i < 4; i++) {
            int idx = tid + i * 256;
            int r = idx >> 4, c = idx & 15;
            int gr = row0 + r;
            As[c][r] = (gr < M) ? A[(size_t)gr * K + k0 + c] : 0.f;
        }
        #pragma unroll
        for (int i = 0; i < 4; i++) {
            int idx = tid + i * 256;
            int r = idx >> 6, c = idx & 63;
            int gc = col0 + c;
            Bs[r][c] = (gc < Nc) ? B[(size_t)(k0 + r) * Nc + gc] : 0.f;
        }
        __syncthreads();
        #pragma unroll
        for (int k = 0; k < 16; k++) {
            float a4[4], b4[4];
            #pragma unroll
            for (int i = 0; i < 4; i++) a4[i] = As[k][ty * 4 + i];
            #pragma unroll
            for (int j = 0; j < 4; j++) b4[j] = Bs[k][tx * 4 + j];
            #pragma unroll
            for (int i = 0; i < 4; i++)
                #pragma unroll
                for (int j = 0; j < 4; j++) acc[i][j] += a4[i] * b4[j];
        }
        __syncthreads();
    }
    #pragma unroll
    for (int i = 0; i < 4; i++) {
        int r = row0 + ty * 4 + i;
        if (r >= M) continue;
        #pragma unroll
        for (int j = 0; j < 4; j++) {
            int c = col0 + tx * 4 + j;
            if (c < Nc) {
                float v = acc[i][j];
                if (BIAS) v += bias[c];
                C[(size_t)r * ldc + c] = v;
            }
        }
    }
}

// ------------------------------ per-node el/er -----------------------------
template <int H, int OUT>
__global__ void node_attn_kernel(const float* __restrict__ feat, const float* __restrict__ al,
                                 const float* __restrict__ ar, float* __restrict__ el,
                                 float* __restrict__ er) {
    int warp = (blockIdx.x * blockDim.x + threadIdx.x) >> 5;
    int lane = threadIdx.x & 31;
    if (warp >= N_NODES) return;
    const float* f = feat + (size_t)warp * H * OUT;
    #pragma unroll
    for (int h = 0; h < H; h++) {
        float v = 0.f, w = 0.f;
        if (lane < OUT) {
            float x = f[h * OUT + lane];
            v = x * al[h * OUT + lane];
            w = x * ar[h * OUT + lane];
        }
        #pragma unroll
        for (int o = 16; o > 0; o >>= 1) {
            v += __shfl_down_sync(0xffffffffu, v, o);
            w += __shfl_down_sync(0xffffffffu, w, o);
        }
        if (lane == 0) {
            el[warp * H + h] = v;
            er[warp * H + h] = w;
        }
    }
}

// ------------------------------ per-edge raw attention ---------------------
template <int H>
__global__ void edge_att_kernel(const float* __restrict__ el, const float* __restrict__ er,
                                const float* __restrict__ etatt, float* __restrict__ att) {
    int t = blockIdx.x * blockDim.x + threadIdx.x;
    if (t >= N_EDGES * H) return;
    int i = t / H, h = t % H;
    float v = el[g_srcS[i] * H + h] + er[g_dstS[i] * H + h] + etatt[g_etS[i] * H + h];
    att[t] = (v > 0.f) ? v : 0.2f * v;
}

// ------------------------------ per-(node,head) max/sum --------------------
template <int H>
__global__ void seg_maxsum_kernel(const float* __restrict__ att, float* __restrict__ m,
                                  float* __restrict__ s) {
    int t = blockIdx.x * blockDim.x + threadIdx.x;
    if (t >= N_NODES * H) return;
    int n = t / H, h = t % H;
    int b = g_rowptr[n], e = g_rowptr[n + 1];
    float mx = -1e30f;
    for (int i = b; i < e; i++) mx = fmaxf(mx, att[i * H + h]);
    float ss = 0.f;
    for (int i = b; i < e; i++) ss += __expf(att[i * H + h] - mx);
    m[t] = mx;
    s[t] = ss;
}

// ------------------------------ per-edge normalized attention --------------
template <int H, bool BLEND>
__global__ void edge_a_kernel(const float* __restrict__ att, const float* __restrict__ m,
                              const float* __restrict__ s, const float* __restrict__ aprev,
                              float* __restrict__ aout) {
    int t = blockIdx.x * blockDim.x + threadIdx.x;
    if (t >= N_EDGES * H) return;
    int i = t / H, h = t % H;
    int d = g_dstS[i];
    float a = __expf(att[t] - m[d * H + h]) / s[d * H + h];
    if (BLEND) a = a * 0.95f + aprev[t] * 0.05f;
    aout[t] = a;
}

// ------------------------------ aggregation (H=8, OUT=32) ------------------
template <bool RES, bool ELU>
__global__ void aggregate8_kernel(const float* __restrict__ feat, const float* __restrict__ a,
                                  const float* __restrict__ res, float* __restrict__ out) {
    int warp = (blockIdx.x * blockDim.x + threadIdx.x) >> 5;
    int lane = threadIdx.x & 31;
    if (warp >= N_NODES) return;
    int n = warp;
    float acc[8];
    #pragma unroll
    for (int h = 0; h < 8; h++)
        acc[h] = RES ? res[(size_t)n * 256 + h * 32 + lane] : 0.f;
    int b = g_rowptr[n], e = g_rowptr[n + 1];
    for (int i = b; i < e; i++) {
        int srcn = g_srcS[i];
        float av = a[(size_t)i * 8 + (lane & 7)];
        const float* f = feat + (size_t)srcn * 256;
        #pragma unroll
        for (int h = 0; h < 8; h++) {
            float ah = __shfl_sync(0xffffffffu, av, h);
            acc[h] += ah * f[h * 32 + lane];
        }
    }
    #pragma unroll
    for (int h = 0; h < 8; h++) {
        float v = acc[h];
        if (ELU) v = (v > 0.f) ? v : expm1f(v);
        out[(size_t)n * 256 + h * 32 + lane] = v;
    }
}

// ------------------------------ aggregation (H=1, OUT=16) ------------------
__global__ void aggregate1_kernel(const float* __restrict__ feat, const float* __restrict__ a,
                                  const float* __restrict__ res, float* __restrict__ out) {
    int warp = (blockIdx.x * blockDim.x + threadIdx.x) >> 5;
    int lane = threadIdx.x & 31;
    if (warp >= N_NODES) return;
    int n = warp;
    float acc = 0.f;
    if (lane < 16) acc = res[(size_t)n * 16 + lane];
    int b = g_rowptr[n], e = g_rowptr[n + 1];
    for (int i = b; i < e; i++) {
        int srcn = g_srcS[i];
        float av = a[i];
        if (lane < 16) acc += av * feat[(size_t)srcn * 16 + lane];
    }
    if (lane < 16) out[(size_t)n * 16 + lane] = acc;
}

// ---------------------------------------------------------------------------
static inline int cdiv(int a, int b) { return (a + b - 1) / b; }

extern "C" void kernel_launch(void* const* d_in, const int* in_sizes, int n_in,
                              void* d_out, int out_size) {
    const float* x0    = (const float*)d_in[0];
    const float* x1    = (const float*)d_in[1];
    const float* x2    = (const float*)d_in[2];
    const float* fcw0  = (const float*)d_in[3];
    const float* fcb0  = (const float*)d_in[4];
    const float* fcw1  = (const float*)d_in[5];
    const float* fcb1  = (const float*)d_in[6];
    const float* fcw2  = (const float*)d_in[7];
    const float* fcb2  = (const float*)d_in[8];
    const float* W0    = (const float*)d_in[9];
    const float* We0   = (const float*)d_in[10];
    const float* eemb0 = (const float*)d_in[11];
    const float* al0   = (const float*)d_in[12];
    const float* ar0   = (const float*)d_in[13];
    const float* ae0   = (const float*)d_in[14];
    const float* W1    = (const float*)d_in[15];
    const float* We1   = (const float*)d_in[16];
    const float* eemb1 = (const float*)d_in[17];
    const float* al1   = (const float*)d_in[18];
    const float* ar1   = (const float*)d_in[19];
    const float* ae1   = (const float*)d_in[20];
    const float* resW1 = (const float*)d_in[21];
    const float* W2    = (const float*)d_in[22];
    const float* We2   = (const float*)d_in[23];
    const float* eemb2 = (const float*)d_in[24];
    const float* al2   = (const float*)d_in[25];
    const float* ar2   = (const float*)d_in[26];
    const float* ae2   = (const float*)d_in[27];
    const float* resW2 = (const float*)d_in[28];
    const int*   src   = (const int*)d_in[29];
    const int*   dst   = (const int*)d_in[30];
    const int*   etype = (const int*)d_in[31];
    float* out = (float*)d_out;

    // symbol addresses (host-side only; runs once during graph capture)
    float *p_h0, *p_feat, *p_res, *p_hA, *p_hB, *p_att, *p_a0, *p_el, *p_er, *p_m, *p_s, *p_etatt;
    int* p_cnt;
    cudaGetSymbolAddress((void**)&p_cnt, g_cnt);
    cudaGetSymbolAddress((void**)&p_h0, g_h0);
    cudaGetSymbolAddress((void**)&p_feat, g_feat);
    cudaGetSymbolAddress((void**)&p_res, g_res);
    cudaGetSymbolAddress((void**)&p_hA, g_hA);
    cudaGetSymbolAddress((void**)&p_hB, g_hB);
    cudaGetSymbolAddress((void**)&p_att, g_att);
    cudaGetSymbolAddress((void**)&p_a0, g_a0);
    cudaGetSymbolAddress((void**)&p_el, g_el);
    cudaGetSymbolAddress((void**)&p_er, g_er);
    cudaGetSymbolAddress((void**)&p_m, g_m);
    cudaGetSymbolAddress((void**)&p_s, g_s);
    cudaGetSymbolAddress((void**)&p_etatt, g_etatt);

    // ---- CSR build ----
    cudaMemsetAsync(p_cnt, 0, N_NODES * sizeof(int));
    hist_kernel<<<cdiv(N_EDGES, 256), 256>>>(dst);
    scan_kernel<<<1, 1024>>>();
    cursor_kernel<<<cdiv(N_NODES, 256), 256>>>();
    scatter_kernel<<<cdiv(N_EDGES, 256), 256>>>(src, dst, etype);

    // ---- edge-type attention terms (tiny) ----
    etype_att_kernel<<<6 * 8, 64>>>(eemb0, We0, ae0, p_etatt + 0, 8);
    etype_att_kernel<<<6 * 8, 64>>>(eemb1, We1, ae1, p_etatt + 48, 8);
    etype_att_kernel<<<6 * 1, 64>>>(eemb2, We2, ae2, p_etatt + 96, 1);

    // ---- input projection -> h0 [N,64] ----
    {
        dim3 g0(1, cdiv(N0, 64));
        gemm64<true><<<g0, 256>>>(x0, fcw0, fcb0, p_h0, N0, 64, 128, 64);
        dim3 g1(1, cdiv(N1, 64));
        gemm64<true><<<g1, 256>>>(x1, fcw1, fcb1, p_h0 + (size_t)N0 * 64, N1, 64, 256, 64);
        dim3 g2(1, cdiv(N2, 64));
        gemm64<true><<<g2, 256>>>(x2, fcw2, fcb2, p_h0 + (size_t)(N0 + N1) * 64, N2, 64, 64, 64);
    }

    const int EB = cdiv(N_EDGES * 8, 256);
    const int NB = cdiv(N_NODES * 8, 256);
    const int WB = cdiv(N_NODES * 32, 256);  // warp-per-node grids

    // ---- layer 0: h0[N,64] -> hA[N,256] ----
    {
        dim3 gg(cdiv(256, 64), cdiv(N_NODES, 64));
        gemm64<false><<<gg, 256>>>(p_h0, W0, nullptr, p_feat, N_NODES, 256, 64, 256);
        node_attn_kernel<8, 32><<<WB, 256>>>(p_feat, al0, ar0, p_el, p_er);
        edge_att_kernel<8><<<EB, 256>>>(p_el, p_er, p_etatt + 0, p_att);
        seg_maxsum_kernel<8><<<NB, 256>>>(p_att, p_m, p_s);
        edge_a_kernel<8, false><<<EB, 256>>>(p_att, p_m, p_s, nullptr, p_a0);
        aggregate8_kernel<false, true><<<WB, 256>>>(p_feat, p_a0, nullptr, p_hA);
    }

    // ---- layer 1: hA[N,256] -> hB[N,256] (residual + attn blend) ----
    {
        dim3 gg(cdiv(256, 64), cdiv(N_NODES, 64));
        gemm64<false><<<gg, 256>>>(p_hA, W1, nullptr, p_feat, N_NODES, 256, 256, 256);
        gemm64<false><<<gg, 256>>>(p_hA, resW1, nullptr, p_res, N_NODES, 256, 256, 256);
        node_attn_kernel<8, 32><<<WB, 256>>>(p_feat, al1, ar1, p_el, p_er);
        edge_att_kernel<8><<<EB, 256>>>(p_el, p_er, p_etatt + 48, p_att);
        seg_maxsum_kernel<8><<<NB, 256>>>(p_att, p_m, p_s);
        edge_a_kernel<8, true><<<EB, 256>>>(p_att, p_m, p_s, p_a0, p_att);  // in-place
        aggregate8_kernel<true, true><<<WB, 256>>>(p_feat, p_att, p_res, p_hB);
    }

    // ---- layer 2: hB[N,256] -> out [N,16] (residual, no activation) ----
    {
        dim3 gg(1, cdiv(N_NODES, 64));
        gemm64<false><<<gg, 256>>>(p_hB, W2, nullptr, p_feat, N_NODES, 16, 256, 16);
        gemm64<false><<<gg, 256>>>(p_hB, resW2, nullptr, p_res, N_NODES, 16, 256, 16);
        node_attn_kernel<1, 16><<<WB, 256>>>(p_feat, al2, ar2, p_el, p_er);
        edge_att_kernel<1><<<cdiv(N_EDGES, 256), 256>>>(p_el, p_er, p_etatt + 96, p_att);
        seg_maxsum_kernel<1><<<cdiv(N_NODES, 256), 256>>>(p_att, p_m, p_s);
        edge_a_kernel<1, false><<<cdiv(N_EDGES, 256), 256>>>(p_att, p_m, p_s, nullptr, p_att);
        aggregate1_kernel<<<WB, 256>>>(p_feat, p_att, p_res, out);
    }
}

// round 2
// speedup vs baseline: 1.2512x; 1.2512x over previous
#include <cuda_runtime.h>
#include <cuda_bf16.h>
#include <math.h>

// ---------------------------------------------------------------------------
// SimpleHGN forward: 3-layer heterogeneous GAT.
// Round 2: 128x128 SGEMM (8x8/thread) for the big GEMMs; fused narrow GEMM
// (W2|resW2 concat) for layer 2 to stop wasting 75% of its tiles.
// ---------------------------------------------------------------------------

#define N_NODES 50000
#define N_EDGES 800000
#define N0 20000
#define N1 17000
#define N2 13000

// ------------------------------ scratch (device globals) -------------------
__device__ int   g_cnt[N_NODES];
__device__ int   g_rowptr[N_NODES + 1];
__device__ int   g_cursor[N_NODES];
__device__ int   g_srcS[N_EDGES];
__device__ int   g_dstS[N_EDGES];
__device__ int   g_etS[N_EDGES];

__device__ float g_h0[N_NODES * 64];
__device__ float g_feat[N_NODES * 256];
__device__ float g_res[N_NODES * 256];
__device__ float g_hA[N_NODES * 256];
__device__ float g_hB[N_NODES * 256];
__device__ float g_f2[N_NODES * 32];          // layer2: feat(0..15) | res(16..31)
__device__ float g_Bcat[256 * 32];            // W2 | resW2
__device__ float g_att[N_EDGES * 8];
__device__ float g_a0[N_EDGES * 8];
__device__ float g_el[N_NODES * 8];
__device__ float g_er[N_NODES * 8];
__device__ float g_m[N_NODES * 8];
__device__ float g_s[N_NODES * 8];
__device__ float g_etatt[3 * 6 * 8];

// ------------------------------ CSR build ----------------------------------
__global__ void hist_kernel(const int* __restrict__ dst) {
    int e = blockIdx.x * blockDim.x + threadIdx.x;
    if (e < N_EDGES) atomicAdd(&g_cnt[dst[e]], 1);
}

__global__ void scan_kernel() {
    __shared__ int sh[1024];
    __shared__ int carry_sh;
    int t = threadIdx.x;
    if (t == 0) carry_sh = 0;
    __syncthreads();
    for (int base = 0; base < N_NODES; base += 1024) {
        int cbase = carry_sh;
        int i = base + t;
        int v = (i < N_NODES) ? g_cnt[i] : 0;
        sh[t] = v;
        __syncthreads();
        #pragma unroll
        for (int off = 1; off < 1024; off <<= 1) {
            int tmp = (t >= off) ? sh[t - off] : 0;
            __syncthreads();
            sh[t] += tmp;
            __syncthreads();
        }
        if (i < N_NODES) g_rowptr[i + 1] = cbase + sh[t];
        if (t == 1023) carry_sh = cbase + sh[1023];
        __syncthreads();
    }
    if (t == 0) g_rowptr[0] = 0;
}

__global__ void cursor_kernel() {
    int i = blockIdx.x * blockDim.x + threadIdx.x;
    if (i < N_NODES) g_cursor[i] = g_rowptr[i];
}

__global__ void scatter_kernel(const int* __restrict__ src, const int* __restrict__ dst,
                               const int* __restrict__ et) {
    int e = blockIdx.x * blockDim.x + threadIdx.x;
    if (e >= N_EDGES) return;
    int d = dst[e];
    int pos = atomicAdd(&g_cursor[d], 1);
    g_srcS[pos] = src[e];
    g_dstS[pos] = d;
    g_etS[pos]  = et[e];
}

// ------------------------------ edge-type attention ------------------------
__global__ void etype_att_kernel(const float* __restrict__ eemb, const float* __restrict__ We,
                                 const float* __restrict__ ae, float* __restrict__ out, int H) {
    int t = blockIdx.x / H;
    int h = blockIdx.x % H;
    int d = threadIdx.x;   // 0..63
    int Wcols = H * 64;
    float v = 0.f;
    #pragma unroll 4
    for (int k = 0; k < 64; k++)
        v += eemb[t * 64 + k] * We[k * Wcols + h * 64 + d];
    v *= ae[h * 64 + d];
    __shared__ float sh[64];
    sh[d] = v;
    __syncthreads();
    #pragma unroll
    for (int o = 32; o > 0; o >>= 1) {
        if (d < o) sh[d] += sh[d + o];
        __syncthreads();
    }
    if (d == 0) out[t * H + h] = sh[0];
}

// ------------------------------ GEMM 128x128 -------------------------------
// C[M,Nc] = A[M,K] @ B[K,Nc]. Requires Nc%128==0, K%16==0. 256 thr, 8x8/thr.
__global__ void gemm128(const float* __restrict__ A, const float* __restrict__ B,
                        float* __restrict__ C, int M, int Nc, int K) {
    __shared__ float As[16][129];
    __shared__ float Bs[16][128];
    int tid = threadIdx.x;
    int tx = tid & 15, ty = tid >> 4;
    int row0 = blockIdx.y * 128, col0 = blockIdx.x * 128;
    float acc[8][8] = {};
    float a_frag[8], b_frag[8];
    for (int k0 = 0; k0 < K; k0 += 16) {
        #pragma unroll
        for (int i = 0; i < 2; i++) {
            int idx = tid + i * 256;          // 0..511
            int r = idx >> 2, c4 = idx & 3;
            int gr = row0 + r;
            float4 v = (gr < M) ? *(const float4*)&A[(size_t)gr * K + k0 + c4 * 4]
                                : make_float4(0.f, 0.f, 0.f, 0.f);
            As[c4 * 4 + 0][r] = v.x;
            As[c4 * 4 + 1][r] = v.y;
            As[c4 * 4 + 2][r] = v.z;
            As[c4 * 4 + 3][r] = v.w;
        }
        #pragma unroll
        for (int i = 0; i < 2; i++) {
            int idx = tid + i * 256;
            int r = idx >> 5, c4 = idx & 31;
            *(float4*)&Bs[r][c4 * 4] =
                *(const float4*)&B[(size_t)(k0 + r) * Nc + col0 + c4 * 4];
        }
        __syncthreads();
        #pragma unroll
        for (int k = 0; k < 16; k++) {
            #pragma unroll
            for (int i = 0; i < 8; i++) a_frag[i] = As[k][ty * 8 + i];
            #pragma unroll
            for (int j = 0; j < 8; j++) b_frag[j] = Bs[k][tx * 8 + j];
            #pragma unroll
            for (int i = 0; i < 8; i++)
                #pragma unroll
                for (int j = 0; j < 8; j++) acc[i][j] += a_frag[i] * b_frag[j];
        }
        __syncthreads();
    }
    #pragma unroll
    for (int i = 0; i < 8; i++) {
        int r = row0 + ty * 8 + i;
        if (r >= M) continue;
        #pragma unroll
        for (int j4 = 0; j4 < 2; j4++) {
            float4 v = make_float4(acc[i][j4 * 4], acc[i][j4 * 4 + 1],
                                   acc[i][j4 * 4 + 2], acc[i][j4 * 4 + 3]);
            *(float4*)&C[(size_t)r * Nc + col0 + tx * 8 + j4 * 4] = v;
        }
    }
}

// ------------------------------ GEMM 128x32 (narrow) -----------------------
// C[M,32] = A[M,K] @ B[K,32]. 256 thr, 8x2/thread, BK=16.
__global__ void gemm_n32(const float* __restrict__ A, const float* __restrict__ B,
                         float* __restrict__ C, int M, int K) {
    __shared__ float As[16][129];
    __shared__ float Bs[16][32];
    int tid = threadIdx.x;
    int tx = tid & 15, ty = tid >> 4;
    int row0 = blockIdx.x * 128;
    float acc[8][2] = {};
    for (int k0 = 0; k0 < K; k0 += 16) {
        #pragma unroll
        for (int i = 0; i < 2; i++) {
            int idx = tid + i * 256;
            int r = idx >> 2, c4 = idx & 3;
            int gr = row0 + r;
            float4 v = (gr < M) ? *(const float4*)&A[(size_t)gr * K + k0 + c4 * 4]
                                : make_float4(0.f, 0.f, 0.f, 0.f);
            As[c4 * 4 + 0][r] = v.x;
            As[c4 * 4 + 1][r] = v.y;
            As[c4 * 4 + 2][r] = v.z;
            As[c4 * 4 + 3][r] = v.w;
        }
        if (tid < 128) {
            int r = tid >> 3, c4 = tid & 7;
            *(float4*)&Bs[r][c4 * 4] = *(const float4*)&B[(size_t)(k0 + r) * 32 + c4 * 4];
        }
        __syncthreads();
        #pragma unroll
        for (int k = 0; k < 16; k++) {
            float b0 = Bs[k][tx * 2], b1 = Bs[k][tx * 2 + 1];
            #pragma unroll
            for (int i = 0; i < 8; i++) {
                float a = As[k][ty * 8 + i];
                acc[i][0] += a * b0;
                acc[i][1] += a * b1;
            }
        }
        __syncthreads();
    }
    #pragma unroll
    for (int i = 0; i < 8; i++) {
        int r = row0 + ty * 8 + i;
        if (r >= M) continue;
        C[(size_t)r * 32 + tx * 2]     = acc[i][0];
        C[(size_t)r * 32 + tx * 2 + 1] = acc[i][1];
    }
}

__global__ void concat_w2_kernel(const float* __restrict__ W2, const float* __restrict__ resW2,
                                 float* __restrict__ Bcat) {
    int i = blockIdx.x * blockDim.x + threadIdx.x;
    if (i < 256 * 16) {
        int r = i >> 4, c = i & 15;
        Bcat[r * 32 + c] = W2[i];
        Bcat[r * 32 + 16 + c] = resW2[i];
    }
}

// ------------------------------ GEMM 64 (small) ----------------------------
template <bool BIAS>
__global__ void gemm64(const float* __restrict__ A, const float* __restrict__ B,
                       const float* __restrict__ bias, float* __restrict__ C,
                       int M, int Nc, int K, int ldc) {
    __shared__ float As[16][65];
    __shared__ float Bs[16][65];
    int tid = threadIdx.x;
    int tx = tid & 15, ty = tid >> 4;
    int row0 = blockIdx.y * 64, col0 = blockIdx.x * 64;
    float acc[4][4] = {};
    for (int k0 = 0; k0 < K; k0 += 16) {
        #pragma unroll
        for (int i = 0; i < 4; i++) {
            int idx = tid + i * 256;
            int r = idx >> 4, c = idx & 15;
            int gr = row0 + r;
            As[c][r] = (gr < M) ? A[(size_t)gr * K + k0 + c] : 0.f;
        }
        #pragma unroll
        for (int i = 0; i < 4; i++) {
            int idx = tid + i * 256;
            int r = idx >> 6, c = idx & 63;
            int gc = col0 + c;
            Bs[r][c] = (gc < Nc) ? B[(size_t)(k0 + r) * Nc + gc] : 0.f;
        }
        __syncthreads();
        #pragma unroll
        for (int k = 0; k < 16; k++) {
            float a4[4], b4[4];
            #pragma unroll
            for (int i = 0; i < 4; i++) a4[i] = As[k][ty * 4 + i];
            #pragma unroll
            for (int j = 0; j < 4; j++) b4[j] = Bs[k][tx * 4 + j];
            #pragma unroll
            for (int i = 0; i < 4; i++)
                #pragma unroll
                for (int j = 0; j < 4; j++) acc[i][j] += a4[i] * b4[j];
        }
        __syncthreads();
    }
    #pragma unroll
    for (int i = 0; i < 4; i++) {
        int r = row0 + ty * 4 + i;
        if (r >= M) continue;
        #pragma unroll
        for (int j = 0; j < 4; j++) {
            int c = col0 + tx * 4 + j;
            if (c < Nc) {
                float v = acc[i][j];
                if (BIAS) v += bias[c];
                C[(size_t)r * ldc + c] = v;
            }
        }
    }
}

// ------------------------------ per-node el/er -----------------------------
template <int H, int OUT, int STRIDE>
__global__ void node_attn_kernel(const float* __restrict__ feat, const float* __restrict__ al,
                                 const float* __restrict__ ar, float* __restrict__ el,
                                 float* __restrict__ er) {
    int warp = (blockIdx.x * blockDim.x + threadIdx.x) >> 5;
    int lane = threadIdx.x & 31;
    if (warp >= N_NODES) return;
    const float* f = feat + (size_t)warp * STRIDE;
    #pragma unroll
    for (int h = 0; h < H; h++) {
        float v = 0.f, w = 0.f;
        if (lane < OUT) {
            float x = f[h * OUT + lane];
            v = x * al[h * OUT + lane];
            w = x * ar[h * OUT + lane];
        }
        #pragma unroll
        for (int o = 16; o > 0; o >>= 1) {
            v += __shfl_down_sync(0xffffffffu, v, o);
            w += __shfl_down_sync(0xffffffffu, w, o);
        }
        if (lane == 0) {
            el[warp * H + h] = v;
            er[warp * H + h] = w;
        }
    }
}

// ------------------------------ per-edge raw attention ---------------------
template <int H>
__global__ void edge_att_kernel(const float* __restrict__ el, const float* __restrict__ er,
                                const float* __restrict__ etatt, float* __restrict__ att) {
    int t = blockIdx.x * blockDim.x + threadIdx.x;
    if (t >= N_EDGES * H) return;
    int i = t / H, h = t % H;
    float v = el[g_srcS[i] * H + h] + er[g_dstS[i] * H + h] + etatt[g_etS[i] * H + h];
    att[t] = (v > 0.f) ? v : 0.2f * v;
}

// ------------------------------ per-(node,head) max/sum --------------------
template <int H>
__global__ void seg_maxsum_kernel(const float* __restrict__ att, float* __restrict__ m,
                                  float* __restrict__ s) {
    int t = blockIdx.x * blockDim.x + threadIdx.x;
    if (t >= N_NODES * H) return;
    int n = t / H, h = t % H;
    int b = g_rowptr[n], e = g_rowptr[n + 1];
    float mx = -1e30f;
    for (int i = b; i < e; i++) mx = fmaxf(mx, att[i * H + h]);
    float ss = 0.f;
    for (int i = b; i < e; i++) ss += __expf(att[i * H + h] - mx);
    m[t] = mx;
    s[t] = ss;
}

// ------------------------------ per-edge normalized attention --------------
template <int H, bool BLEND>
__global__ void edge_a_kernel(const float* __restrict__ att, const float* __restrict__ m,
                              const float* __restrict__ s, const float* __restrict__ aprev,
                              float* __restrict__ aout) {
    int t = blockIdx.x * blockDim.x + threadIdx.x;
    if (t >= N_EDGES * H) return;
    int i = t / H, h = t % H;
    int d = g_dstS[i];
    float a = __expf(att[t] - m[d * H + h]) / s[d * H + h];
    if (BLEND) a = a * 0.95f + aprev[t] * 0.05f;
    aout[t] = a;
}

// ------------------------------ aggregation (H=8, OUT=32) ------------------
template <bool RES, bool ELU>
__global__ void aggregate8_kernel(const float* __restrict__ feat, const float* __restrict__ a,
                                  const float* __restrict__ res, float* __restrict__ out) {
    int warp = (blockIdx.x * blockDim.x + threadIdx.x) >> 5;
    int lane = threadIdx.x & 31;
    if (warp >= N_NODES) return;
    int n = warp;
    float acc[8];
    #pragma unroll
    for (int h = 0; h < 8; h++)
        acc[h] = RES ? res[(size_t)n * 256 + h * 32 + lane] : 0.f;
    int b = g_rowptr[n], e = g_rowptr[n + 1];
    for (int i = b; i < e; i++) {
        int srcn = g_srcS[i];
        float av = a[(size_t)i * 8 + (lane & 7)];
        const float* f = feat + (size_t)srcn * 256;
        #pragma unroll
        for (int h = 0; h < 8; h++) {
            float ah = __shfl_sync(0xffffffffu, av, h);
            acc[h] += ah * f[h * 32 + lane];
        }
    }
    #pragma unroll
    for (int h = 0; h < 8; h++) {
        float v = acc[h];
        if (ELU) v = (v > 0.f) ? v : expm1f(v);
        out[(size_t)n * 256 + h * 32 + lane] = v;
    }
}

// ------------------------------ aggregation (H=1, OUT=16, stride 32) -------
__global__ void aggregate1_kernel(const float* __restrict__ f2, const float* __restrict__ a,
                                  float* __restrict__ out) {
    int warp = (blockIdx.x * blockDim.x + threadIdx.x) >> 5;
    int lane = threadIdx.x & 31;
    if (warp >= N_NODES) return;
    int n = warp;
    float acc = 0.f;
    if (lane < 16) acc = f2[(size_t)n * 32 + 16 + lane];   // residual part
    int b = g_rowptr[n], e = g_rowptr[n + 1];
    for (int i = b; i < e; i++) {
        int srcn = g_srcS[i];
        float av = a[i];
        if (lane < 16) acc += av * f2[(size_t)srcn * 32 + lane];
    }
    if (lane < 16) out[(size_t)n * 16 + lane] = acc;
}

// ---------------------------------------------------------------------------
static inline int cdiv(int a, int b) { return (a + b - 1) / b; }

extern "C" void kernel_launch(void* const* d_in, const int* in_sizes, int n_in,
                              void* d_out, int out_size) {
    const float* x0    = (const float*)d_in[0];
    const float* x1    = (const float*)d_in[1];
    const float* x2    = (const float*)d_in[2];
    const float* fcw0  = (const float*)d_in[3];
    const float* fcb0  = (const float*)d_in[4];
    const float* fcw1  = (const float*)d_in[5];
    const float* fcb1  = (const float*)d_in[6];
    const float* fcw2  = (const float*)d_in[7];
    const float* fcb2  = (const float*)d_in[8];
    const float* W0    = (const float*)d_in[9];
    const float* We0   = (const float*)d_in[10];
    const float* eemb0 = (const float*)d_in[11];
    const float* al0   = (const float*)d_in[12];
    const float* ar0   = (const float*)d_in[13];
    const float* ae0   = (const float*)d_in[14];
    const float* W1    = (const float*)d_in[15];
    const float* We1   = (const float*)d_in[16];
    const float* eemb1 = (const float*)d_in[17];
    const float* al1   = (const float*)d_in[18];
    const float* ar1   = (const float*)d_in[19];
    const float* ae1   = (const float*)d_in[20];
    const float* resW1 = (const float*)d_in[21];
    const float* W2    = (const float*)d_in[22];
    const float* We2   = (const float*)d_in[23];
    const float* eemb2 = (const float*)d_in[24];
    const float* al2   = (const float*)d_in[25];
    const float* ar2   = (const float*)d_in[26];
    const float* ae2   = (const float*)d_in[27];
    const float* resW2 = (const float*)d_in[28];
    const int*   src   = (const int*)d_in[29];
    const int*   dst   = (const int*)d_in[30];
    const int*   etype = (const int*)d_in[31];
    float* out = (float*)d_out;

    float *p_h0, *p_feat, *p_res, *p_hA, *p_hB, *p_f2, *p_Bcat, *p_att, *p_a0,
          *p_el, *p_er, *p_m, *p_s, *p_etatt;
    int* p_cnt;
    cudaGetSymbolAddress((void**)&p_cnt, g_cnt);
    cudaGetSymbolAddress((void**)&p_h0, g_h0);
    cudaGetSymbolAddress((void**)&p_feat, g_feat);
    cudaGetSymbolAddress((void**)&p_res, g_res);
    cudaGetSymbolAddress((void**)&p_hA, g_hA);
    cudaGetSymbolAddress((void**)&p_hB, g_hB);
    cudaGetSymbolAddress((void**)&p_f2, g_f2);
    cudaGetSymbolAddress((void**)&p_Bcat, g_Bcat);
    cudaGetSymbolAddress((void**)&p_att, g_att);
    cudaGetSymbolAddress((void**)&p_a0, g_a0);
    cudaGetSymbolAddress((void**)&p_el, g_el);
    cudaGetSymbolAddress((void**)&p_er, g_er);
    cudaGetSymbolAddress((void**)&p_m, g_m);
    cudaGetSymbolAddress((void**)&p_s, g_s);
    cudaGetSymbolAddress((void**)&p_etatt, g_etatt);

    // ---- CSR build ----
    cudaMemsetAsync(p_cnt, 0, N_NODES * sizeof(int));
    hist_kernel<<<cdiv(N_EDGES, 256), 256>>>(dst);
    scan_kernel<<<1, 1024>>>();
    cursor_kernel<<<cdiv(N_NODES, 256), 256>>>();
    scatter_kernel<<<cdiv(N_EDGES, 256), 256>>>(src, dst, etype);

    // ---- edge-type attention terms (tiny) ----
    etype_att_kernel<<<6 * 8, 64>>>(eemb0, We0, ae0, p_etatt + 0, 8);
    etype_att_kernel<<<6 * 8, 64>>>(eemb1, We1, ae1, p_etatt + 48, 8);
    etype_att_kernel<<<6 * 1, 64>>>(eemb2, We2, ae2, p_etatt + 96, 1);
    concat_w2_kernel<<<16, 256>>>(W2, resW2, p_Bcat);

    // ---- input projection -> h0 [N,64] ----
    {
        dim3 g0(1, cdiv(N0, 64));
        gemm64<true><<<g0, 256>>>(x0, fcw0, fcb0, p_h0, N0, 64, 128, 64);
        dim3 g1(1, cdiv(N1, 64));
        gemm64<true><<<g1, 256>>>(x1, fcw1, fcb1, p_h0 + (size_t)N0 * 64, N1, 64, 256, 64);
        dim3 g2(1, cdiv(N2, 64));
        gemm64<true><<<g2, 256>>>(x2, fcw2, fcb2, p_h0 + (size_t)(N0 + N1) * 64, N2, 64, 64, 64);
    }

    const int EB = cdiv(N_EDGES * 8, 256);
    const int NB = cdiv(N_NODES * 8, 256);
    const int WB = cdiv(N_NODES * 32, 256);

    // ---- layer 0: h0[N,64] -> hA[N,256] ----
    {
        dim3 gg(2, cdiv(N_NODES, 128));
        gemm128<<<gg, 256>>>(p_h0, W0, p_feat, N_NODES, 256, 64);
        node_attn_kernel<8, 32, 256><<<WB, 256>>>(p_feat, al0, ar0, p_el, p_er);
        edge_att_kernel<8><<<EB, 256>>>(p_el, p_er, p_etatt + 0, p_att);
        seg_maxsum_kernel<8><<<NB, 256>>>(p_att, p_m, p_s);
        edge_a_kernel<8, false><<<EB, 256>>>(p_att, p_m, p_s, nullptr, p_a0);
        aggregate8_kernel<false, true><<<WB, 256>>>(p_feat, p_a0, nullptr, p_hA);
    }

    // ---- layer 1: hA[N,256] -> hB[N,256] (residual + attn blend) ----
    {
        dim3 gg(2, cdiv(N_NODES, 128));
        gemm128<<<gg, 256>>>(p_hA, W1, p_feat, N_NODES, 256, 256);
        gemm128<<<gg, 256>>>(p_hA, resW1, p_res, N_NODES, 256, 256);
        node_attn_kernel<8, 32, 256><<<WB, 256>>>(p_feat, al1, ar1, p_el, p_er);
        edge_att_kernel<8><<<EB, 256>>>(p_el, p_er, p_etatt + 48, p_att);
        seg_maxsum_kernel<8><<<NB, 256>>>(p_att, p_m, p_s);
        edge_a_kernel<8, true><<<EB, 256>>>(p_att, p_m, p_s, p_a0, p_att);
        aggregate8_kernel<true, true><<<WB, 256>>>(p_feat, p_att, p_res, p_hB);
    }

    // ---- layer 2: hB[N,256] -> out [N,16] (fused W2|resW2 narrow GEMM) ----
    {
        gemm_n32<<<cdiv(N_NODES, 128), 256>>>(p_hB, p_Bcat, p_f2, N_NODES, 256);
        node_attn_kernel<1, 16, 32><<<WB, 256>>>(p_f2, al2, ar2, p_el, p_er);
        edge_att_kernel<1><<<cdiv(N_EDGES, 256), 256>>>(p_el, p_er, p_etatt + 96, p_att);
        seg_maxsum_kernel<1><<<cdiv(N_NODES, 256), 256>>>(p_att, p_m, p_s);
        edge_a_kernel<1, false><<<cdiv(N_EDGES, 256), 256>>>(p_att, p_m, p_s, nullptr, p_att);
        aggregate1_kernel<<<WB, 256>>>(p_f2, p_att, out);
    }
}

// round 3
// speedup vs baseline: 1.3426x; 1.0730x over previous
#include <cuda_runtime.h>
#include <cuda_bf16.h>
#include <math.h>
#include <stdint.h>

// ---------------------------------------------------------------------------
// SimpleHGN forward, round 3:
//  - all GEMMs on tensor cores (mma.sync m16n8k8 tf32, hi/lo split = fp32-ish
//    accuracy at tensor-core speed)
//  - parallel hierarchical scan for CSR rowptr
//  - edge pipeline unchanged (warp-per-dst CSR aggregation)
// ---------------------------------------------------------------------------

#define N_NODES 50000
#define N_EDGES 800000
#define N0 20000
#define N1 17000
#define N2 13000
#define SCAN_B 512
#define SCAN_NB ((N_NODES + SCAN_B - 1) / SCAN_B)   // 98

// ------------------------------ scratch (device globals) -------------------
__device__ int   g_cnt[N_NODES];
__device__ int   g_rowptr[N_NODES + 1];
__device__ int   g_cursor[N_NODES];
__device__ int   g_bsum[SCAN_NB];
__device__ int   g_boff[SCAN_NB];
__device__ int   g_srcS[N_EDGES];
__device__ int   g_dstS[N_EDGES];
__device__ int   g_etS[N_EDGES];

__device__ float g_h0[N_NODES * 64];
__device__ float g_feat[N_NODES * 256];
__device__ float g_res[N_NODES * 256];
__device__ float g_hA[N_NODES * 256];
__device__ float g_hB[N_NODES * 256];
__device__ float g_f2[N_NODES * 32];          // layer2: feat(0..15) | res(16..31)
__device__ float g_Bcat[256 * 32];            // W2 | resW2
__device__ float g_att[N_EDGES * 8];
__device__ float g_a0[N_EDGES * 8];
__device__ float g_el[N_NODES * 8];
__device__ float g_er[N_NODES * 8];
__device__ float g_m[N_NODES * 8];
__device__ float g_s[N_NODES * 8];
__device__ float g_etatt[3 * 6 * 8];

// ------------------------------ CSR build ----------------------------------
__global__ void hist_kernel(const int* __restrict__ dst) {
    int e = blockIdx.x * blockDim.x + threadIdx.x;
    if (e < N_EDGES) atomicAdd(&g_cnt[dst[e]], 1);
}

__global__ void scan_block_kernel() {
    __shared__ int sh[SCAN_B];
    int t = threadIdx.x;
    int i = blockIdx.x * SCAN_B + t;
    int v = (i < N_NODES) ? g_cnt[i] : 0;
    sh[t] = v;
    __syncthreads();
    #pragma unroll
    for (int off = 1; off < SCAN_B; off <<= 1) {
        int tmp = (t >= off) ? sh[t - off] : 0;
        __syncthreads();
        sh[t] += tmp;
        __syncthreads();
    }
    if (i < N_NODES) g_rowptr[i + 1] = sh[t];
    if (t == SCAN_B - 1) g_bsum[blockIdx.x] = sh[t];
}

__global__ void scan_top_kernel() {
    __shared__ int sh[128];
    int t = threadIdx.x;
    int v = (t < SCAN_NB) ? g_bsum[t] : 0;
    sh[t] = v;
    __syncthreads();
    #pragma unroll
    for (int off = 1; off < 128; off <<= 1) {
        int tmp = (t >= off) ? sh[t - off] : 0;
        __syncthreads();
        sh[t] += tmp;
        __syncthreads();
    }
    if (t < SCAN_NB) g_boff[t] = sh[t] - v;   // exclusive block offsets
}

__global__ void scan_add_kernel() {
    int t = threadIdx.x;
    int i = blockIdx.x * SCAN_B + t;
    if (i < N_NODES) {
        int v = g_rowptr[i + 1] + g_boff[blockIdx.x];
        g_rowptr[i + 1] = v;
    }
    if (i == 0) g_rowptr[0] = 0;
}

__global__ void cursor_kernel() {
    int i = blockIdx.x * blockDim.x + threadIdx.x;
    if (i < N_NODES) g_cursor[i] = g_rowptr[i];
}

__global__ void scatter_kernel(const int* __restrict__ src, const int* __restrict__ dst,
                               const int* __restrict__ et) {
    int e = blockIdx.x * blockDim.x + threadIdx.x;
    if (e >= N_EDGES) return;
    int d = dst[e];
    int pos = atomicAdd(&g_cursor[d], 1);
    g_srcS[pos] = src[e];
    g_dstS[pos] = d;
    g_etS[pos]  = et[e];
}

// ------------------------------ edge-type attention ------------------------
__global__ void etype_att_kernel(const float* __restrict__ eemb, const float* __restrict__ We,
                                 const float* __restrict__ ae, float* __restrict__ out, int H) {
    int t = blockIdx.x / H;
    int h = blockIdx.x % H;
    int d = threadIdx.x;   // 0..63
    int Wcols = H * 64;
    float v = 0.f;
    #pragma unroll 4
    for (int k = 0; k < 64; k++)
        v += eemb[t * 64 + k] * We[k * Wcols + h * 64 + d];
    v *= ae[h * 64 + d];
    __shared__ float sh[64];
    sh[d] = v;
    __syncthreads();
    #pragma unroll
    for (int o = 32; o > 0; o >>= 1) {
        if (d < o) sh[d] += sh[d + o];
        __syncthreads();
    }
    if (d == 0) out[t * H + h] = sh[0];
}

__global__ void concat_w2_kernel(const float* __restrict__ W2, const float* __restrict__ resW2,
                                 float* __restrict__ Bcat) {
    int i = blockIdx.x * blockDim.x + threadIdx.x;
    if (i < 256 * 16) {
        int r = i >> 4, c = i & 15;
        Bcat[r * 32 + c] = W2[i];
        Bcat[r * 32 + 16 + c] = resW2[i];
    }
}

// ------------------------------ tf32 tensor-core GEMM ----------------------
__device__ __forceinline__ uint32_t tf32_rna(float x) {
    uint32_t r;
    asm("cvt.rna.tf32.f32 %0, %1;" : "=r"(r) : "f"(x));
    return r;
}

__device__ __forceinline__ void mma_tf32(float* c, uint32_t a0, uint32_t a1,
                                         uint32_t a2, uint32_t a3,
                                         uint32_t b0, uint32_t b1) {
    asm volatile(
        "mma.sync.aligned.m16n8k8.row.col.f32.tf32.tf32.f32 "
        "{%0,%1,%2,%3}, {%4,%5,%6,%7}, {%8,%9}, {%0,%1,%2,%3};"
        : "+f"(c[0]), "+f"(c[1]), "+f"(c[2]), "+f"(c[3])
        : "r"(a0), "r"(a1), "r"(a2), "r"(a3), "r"(b0), "r"(b1));
}

// C[M,Nc] = A[M,K] @ B[K,Nc] (+bias). BM=128, BN=NT*16, BK=32.
// 256 threads = 8 warps (4 in M x 2 in N); warp tile 32 x (NT*8).
// Requires K%32==0, Nc%BN==0. hi/lo tf32 split -> ~fp32 accuracy.
template <int NT, bool BIAS>
__global__ void __launch_bounds__(256) gemm_tc(const float* __restrict__ A,
                                               const float* __restrict__ B,
                                               const float* __restrict__ bias,
                                               float* __restrict__ C,
                                               int M, int Nc, int K) {
    constexpr int BN = NT * 16;
    __shared__ __align__(16) float As[32][132];
    __shared__ __align__(16) float Bs[32][BN + 4];
    int tid = threadIdx.x;
    int wid = tid >> 5, lane = tid & 31;
    int gID = lane >> 2, tig = lane & 3;
    int warpM = wid & 3, warpN = wid >> 2;
    int row0 = blockIdx.y * 128, col0 = blockIdx.x * BN;

    float acc[2][NT][4];
    #pragma unroll
    for (int mt = 0; mt < 2; mt++)
        #pragma unroll
        for (int nt = 0; nt < NT; nt++)
            #pragma unroll
            for (int j = 0; j < 4; j++) acc[mt][nt][j] = 0.f;

    for (int k0 = 0; k0 < K; k0 += 32) {
        // A tile: 128 x 32, transposed into As[k][m]
        #pragma unroll
        for (int i = 0; i < 4; i++) {
            int lin = tid + i * 256;            // 0..1023
            int r = lin >> 3, c4 = lin & 7;
            int gr = row0 + r;
            float4 v = (gr < M) ? *(const float4*)&A[(size_t)gr * K + k0 + c4 * 4]
                                : make_float4(0.f, 0.f, 0.f, 0.f);
            As[c4 * 4 + 0][r] = v.x;
            As[c4 * 4 + 1][r] = v.y;
            As[c4 * 4 + 2][r] = v.z;
            As[c4 * 4 + 3][r] = v.w;
        }
        // B tile: 32 x BN
        #pragma unroll
        for (int i = 0; i < BN / 32; i++) {
            int lin = tid + i * 256;
            int r = lin / (BN / 4);
            int c4 = lin % (BN / 4);
            *(float4*)&Bs[r][c4 * 4] =
                *(const float4*)&B[(size_t)(k0 + r) * Nc + col0 + c4 * 4];
        }
        __syncthreads();

        #pragma unroll
        for (int k8 = 0; k8 < 4; k8++) {
            int kb = k8 * 8;
            uint32_t ah[2][4], al[2][4];
            #pragma unroll
            for (int mt = 0; mt < 2; mt++) {
                int m0 = warpM * 32 + mt * 16;
                float x0 = As[kb + tig][m0 + gID];
                float x1 = As[kb + tig][m0 + gID + 8];
                float x2 = As[kb + tig + 4][m0 + gID];
                float x3 = As[kb + tig + 4][m0 + gID + 8];
                ah[mt][0] = tf32_rna(x0);
                ah[mt][1] = tf32_rna(x1);
                ah[mt][2] = tf32_rna(x2);
                ah[mt][3] = tf32_rna(x3);
                al[mt][0] = tf32_rna(x0 - __uint_as_float(ah[mt][0]));
                al[mt][1] = tf32_rna(x1 - __uint_as_float(ah[mt][1]));
                al[mt][2] = tf32_rna(x2 - __uint_as_float(ah[mt][2]));
                al[mt][3] = tf32_rna(x3 - __uint_as_float(ah[mt][3]));
            }
            #pragma unroll
            for (int nt = 0; nt < NT; nt++) {
                int n0 = warpN * (NT * 8) + nt * 8;
                float y0 = Bs[kb + tig][n0 + gID];
                float y1 = Bs[kb + tig + 4][n0 + gID];
                uint32_t bh0 = tf32_rna(y0), bh1 = tf32_rna(y1);
                uint32_t bl0 = tf32_rna(y0 - __uint_as_float(bh0));
                uint32_t bl1 = tf32_rna(y1 - __uint_as_float(bh1));
                #pragma unroll
                for (int mt = 0; mt < 2; mt++) {
                    mma_tf32(acc[mt][nt], ah[mt][0], ah[mt][1], ah[mt][2], ah[mt][3], bh0, bh1);
                    mma_tf32(acc[mt][nt], al[mt][0], al[mt][1], al[mt][2], al[mt][3], bh0, bh1);
                    mma_tf32(acc[mt][nt], ah[mt][0], ah[mt][1], ah[mt][2], ah[mt][3], bl0, bl1);
                }
            }
        }
        __syncthreads();
    }

    // epilogue
    #pragma unroll
    for (int mt = 0; mt < 2; mt++) {
        #pragma unroll
        for (int nt = 0; nt < NT; nt++) {
            int r0 = row0 + warpM * 32 + mt * 16 + gID;
            int c  = col0 + warpN * (NT * 8) + nt * 8 + tig * 2;
            float b0a = BIAS ? bias[c] : 0.f;
            float b1a = BIAS ? bias[c + 1] : 0.f;
            if (r0 < M) {
                C[(size_t)r0 * Nc + c]     = acc[mt][nt][0] + b0a;
                C[(size_t)r0 * Nc + c + 1] = acc[mt][nt][1] + b1a;
            }
            if (r0 + 8 < M) {
                C[(size_t)(r0 + 8) * Nc + c]     = acc[mt][nt][2] + b0a;
                C[(size_t)(r0 + 8) * Nc + c + 1] = acc[mt][nt][3] + b1a;
            }
        }
    }
}

// ------------------------------ per-node el/er -----------------------------
template <int H, int OUT, int STRIDE>
__global__ void node_attn_kernel(const float* __restrict__ feat, const float* __restrict__ al,
                                 const float* __restrict__ ar, float* __restrict__ el,
                                 float* __restrict__ er) {
    int warp = (blockIdx.x * blockDim.x + threadIdx.x) >> 5;
    int lane = threadIdx.x & 31;
    if (warp >= N_NODES) return;
    const float* f = feat + (size_t)warp * STRIDE;
    #pragma unroll
    for (int h = 0; h < H; h++) {
        float v = 0.f, w = 0.f;
        if (lane < OUT) {
            float x = f[h * OUT + lane];
            v = x * al[h * OUT + lane];
            w = x * ar[h * OUT + lane];
        }
        #pragma unroll
        for (int o = 16; o > 0; o >>= 1) {
            v += __shfl_down_sync(0xffffffffu, v, o);
            w += __shfl_down_sync(0xffffffffu, w, o);
        }
        if (lane == 0) {
            el[warp * H + h] = v;
            er[warp * H + h] = w;
        }
    }
}

// ------------------------------ per-edge raw attention ---------------------
template <int H>
__global__ void edge_att_kernel(const float* __restrict__ el, const float* __restrict__ er,
                                const float* __restrict__ etatt, float* __restrict__ att) {
    int t = blockIdx.x * blockDim.x + threadIdx.x;
    if (t >= N_EDGES * H) return;
    int i = t / H, h = t % H;
    float v = el[g_srcS[i] * H + h] + er[g_dstS[i] * H + h] + etatt[g_etS[i] * H + h];
    att[t] = (v > 0.f) ? v : 0.2f * v;
}

// ------------------------------ per-(node,head) max/sum --------------------
template <int H>
__global__ void seg_maxsum_kernel(const float* __restrict__ att, float* __restrict__ m,
                                  float* __restrict__ s) {
    int t = blockIdx.x * blockDim.x + threadIdx.x;
    if (t >= N_NODES * H) return;
    int n = t / H, h = t % H;
    int b = g_rowptr[n], e = g_rowptr[n + 1];
    float mx = -1e30f;
    for (int i = b; i < e; i++) mx = fmaxf(mx, att[i * H + h]);
    float ss = 0.f;
    for (int i = b; i < e; i++) ss += __expf(att[i * H + h] - mx);
    m[t] = mx;
    s[t] = ss;
}

// ------------------------------ per-edge normalized attention --------------
template <int H, bool BLEND>
__global__ void edge_a_kernel(const float* __restrict__ att, const float* __restrict__ m,
                              const float* __restrict__ s, const float* __restrict__ aprev,
                              float* __restrict__ aout) {
    int t = blockIdx.x * blockDim.x + threadIdx.x;
    if (t >= N_EDGES * H) return;
    int i = t / H, h = t % H;
    int d = g_dstS[i];
    float a = __expf(att[t] - m[d * H + h]) / s[d * H + h];
    if (BLEND) a = a * 0.95f + aprev[t] * 0.05f;
    aout[t] = a;
}

// ------------------------------ aggregation (H=8, OUT=32) ------------------
template <bool RES, bool ELU>
__global__ void aggregate8_kernel(const float* __restrict__ feat, const float* __restrict__ a,
                                  const float* __restrict__ res, float* __restrict__ out) {
    int warp = (blockIdx.x * blockDim.x + threadIdx.x) >> 5;
    int lane = threadIdx.x & 31;
    if (warp >= N_NODES) return;
    int n = warp;
    float acc[8];
    #pragma unroll
    for (int h = 0; h < 8; h++)
        acc[h] = RES ? res[(size_t)n * 256 + h * 32 + lane] : 0.f;
    int b = g_rowptr[n], e = g_rowptr[n + 1];
    for (int i = b; i < e; i++) {
        int srcn = g_srcS[i];
        float av = a[(size_t)i * 8 + (lane & 7)];
        const float* f = feat + (size_t)srcn * 256;
        #pragma unroll
        for (int h = 0; h < 8; h++) {
            float ah = __shfl_sync(0xffffffffu, av, h);
            acc[h] += ah * f[h * 32 + lane];
        }
    }
    #pragma unroll
    for (int h = 0; h < 8; h++) {
        float v = acc[h];
        if (ELU) v = (v > 0.f) ? v : expm1f(v);
        out[(size_t)n * 256 + h * 32 + lane] = v;
    }
}

// ------------------------------ aggregation (H=1, OUT=16, stride 32) -------
__global__ void aggregate1_kernel(const float* __restrict__ f2, const float* __restrict__ a,
                                  float* __restrict__ out) {
    int warp = (blockIdx.x * blockDim.x + threadIdx.x) >> 5;
    int lane = threadIdx.x & 31;
    if (warp >= N_NODES) return;
    int n = warp;
    float acc = 0.f;
    if (lane < 16) acc = f2[(size_t)n * 32 + 16 + lane];   // residual part
    int b = g_rowptr[n], e = g_rowptr[n + 1];
    for (int i = b; i < e; i++) {
        int srcn = g_srcS[i];
        float av = a[i];
        if (lane < 16) acc += av * f2[(size_t)srcn * 32 + lane];
    }
    if (lane < 16) out[(size_t)n * 16 + lane] = acc;
}

// ---------------------------------------------------------------------------
static inline int cdiv(int a, int b) { return (a + b - 1) / b; }

extern "C" void kernel_launch(void* const* d_in, const int* in_sizes, int n_in,
                              void* d_out, int out_size) {
    const float* x0    = (const float*)d_in[0];
    const float* x1    = (const float*)d_in[1];
    const float* x2    = (const float*)d_in[2];
    const float* fcw0  = (const float*)d_in[3];
    const float* fcb0  = (const float*)d_in[4];
    const float* fcw1  = (const float*)d_in[5];
    const float* fcb1  = (const float*)d_in[6];
    const float* fcw2  = (const float*)d_in[7];
    const float* fcb2  = (const float*)d_in[8];
    const float* W0    = (const float*)d_in[9];
    const float* We0   = (const float*)d_in[10];
    const float* eemb0 = (const float*)d_in[11];
    const float* al0   = (const float*)d_in[12];
    const float* ar0   = (const float*)d_in[13];
    const float* ae0   = (const float*)d_in[14];
    const float* W1    = (const float*)d_in[15];
    const float* We1   = (const float*)d_in[16];
    const float* eemb1 = (const float*)d_in[17];
    const float* al1   = (const float*)d_in[18];
    const float* ar1   = (const float*)d_in[19];
    const float* ae1   = (const float*)d_in[20];
    const float* resW1 = (const float*)d_in[21];
    const float* W2    = (const float*)d_in[22];
    const float* We2   = (const float*)d_in[23];
    const float* eemb2 = (const float*)d_in[24];
    const float* al2   = (const float*)d_in[25];
    const float* ar2   = (const float*)d_in[26];
    const float* ae2   = (const float*)d_in[27];
    const float* resW2 = (const float*)d_in[28];
    const int*   src   = (const int*)d_in[29];
    const int*   dst   = (const int*)d_in[30];
    const int*   etype = (const int*)d_in[31];
    float* out = (float*)d_out;

    float *p_h0, *p_feat, *p_res, *p_hA, *p_hB, *p_f2, *p_Bcat, *p_att, *p_a0,
          *p_el, *p_er, *p_m, *p_s, *p_etatt;
    int* p_cnt;
    cudaGetSymbolAddress((void**)&p_cnt, g_cnt);
    cudaGetSymbolAddress((void**)&p_h0, g_h0);
    cudaGetSymbolAddress((void**)&p_feat, g_feat);
    cudaGetSymbolAddress((void**)&p_res, g_res);
    cudaGetSymbolAddress((void**)&p_hA, g_hA);
    cudaGetSymbolAddress((void**)&p_hB, g_hB);
    cudaGetSymbolAddress((void**)&p_f2, g_f2);
    cudaGetSymbolAddress((void**)&p_Bcat, g_Bcat);
    cudaGetSymbolAddress((void**)&p_att, g_att);
    cudaGetSymbolAddress((void**)&p_a0, g_a0);
    cudaGetSymbolAddress((void**)&p_el, g_el);
    cudaGetSymbolAddress((void**)&p_er, g_er);
    cudaGetSymbolAddress((void**)&p_m, g_m);
    cudaGetSymbolAddress((void**)&p_s, g_s);
    cudaGetSymbolAddress((void**)&p_etatt, g_etatt);

    // ---- CSR build ----
    cudaMemsetAsync(p_cnt, 0, N_NODES * sizeof(int));
    hist_kernel<<<cdiv(N_EDGES, 256), 256>>>(dst);
    scan_block_kernel<<<SCAN_NB, SCAN_B>>>();
    scan_top_kernel<<<1, 128>>>();
    scan_add_kernel<<<SCAN_NB, SCAN_B>>>();
    cursor_kernel<<<cdiv(N_NODES, 256), 256>>>();
    scatter_kernel<<<cdiv(N_EDGES, 256), 256>>>(src, dst, etype);

    // ---- edge-type attention terms (tiny) ----
    etype_att_kernel<<<6 * 8, 64>>>(eemb0, We0, ae0, p_etatt + 0, 8);
    etype_att_kernel<<<6 * 8, 64>>>(eemb1, We1, ae1, p_etatt + 48, 8);
    etype_att_kernel<<<6 * 1, 64>>>(eemb2, We2, ae2, p_etatt + 96, 1);
    concat_w2_kernel<<<16, 256>>>(W2, resW2, p_Bcat);

    // ---- input projection -> h0 [N,64] (tensor core) ----
    {
        dim3 g0(1, cdiv(N0, 128));
        gemm_tc<4, true><<<g0, 256>>>(x0, fcw0, fcb0, p_h0, N0, 64, 128);
        dim3 g1(1, cdiv(N1, 128));
        gemm_tc<4, true><<<g1, 256>>>(x1, fcw1, fcb1, p_h0 + (size_t)N0 * 64, N1, 64, 256);
        dim3 g2(1, cdiv(N2, 128));
        gemm_tc<4, true><<<g2, 256>>>(x2, fcw2, fcb2, p_h0 + (size_t)(N0 + N1) * 64, N2, 64, 64);
    }

    const int EB = cdiv(N_EDGES * 8, 256);
    const int NB = cdiv(N_NODES * 8, 256);
    const int WB = cdiv(N_NODES * 32, 256);

    // ---- layer 0: h0[N,64] -> hA[N,256] ----
    {
        dim3 gg(2, cdiv(N_NODES, 128));
        gemm_tc<8, false><<<gg, 256>>>(p_h0, W0, nullptr, p_feat, N_NODES, 256, 64);
        node_attn_kernel<8, 32, 256><<<WB, 256>>>(p_feat, al0, ar0, p_el, p_er);
        edge_att_kernel<8><<<EB, 256>>>(p_el, p_er, p_etatt + 0, p_att);
        seg_maxsum_kernel<8><<<NB, 256>>>(p_att, p_m, p_s);
        edge_a_kernel<8, false><<<EB, 256>>>(p_att, p_m, p_s, nullptr, p_a0);
        aggregate8_kernel<false, true><<<WB, 256>>>(p_feat, p_a0, nullptr, p_hA);
    }

    // ---- layer 1: hA[N,256] -> hB[N,256] (residual + attn blend) ----
    {
        dim3 gg(2, cdiv(N_NODES, 128));
        gemm_tc<8, false><<<gg, 256>>>(p_hA, W1, nullptr, p_feat, N_NODES, 256, 256);
        gemm_tc<8, false><<<gg, 256>>>(p_hA, resW1, nullptr, p_res, N_NODES, 256, 256);
        node_attn_kernel<8, 32, 256><<<WB, 256>>>(p_feat, al1, ar1, p_el, p_er);
        edge_att_kernel<8><<<EB, 256>>>(p_el, p_er, p_etatt + 48, p_att);
        seg_maxsum_kernel<8><<<NB, 256>>>(p_att, p_m, p_s);
        edge_a_kernel<8, true><<<EB, 256>>>(p_att, p_m, p_s, p_a0, p_att);
        aggregate8_kernel<true, true><<<WB, 256>>>(p_feat, p_att, p_res, p_hB);
    }

    // ---- layer 2: hB[N,256] -> out [N,16] (fused W2|resW2 narrow GEMM) ----
    {
        dim3 gg(1, cdiv(N_NODES, 128));
        gemm_tc<2, false><<<gg, 256>>>(p_hB, p_Bcat, nullptr, p_f2, N_NODES, 32, 256);
        node_attn_kernel<1, 16, 32><<<WB, 256>>>(p_f2, al2, ar2, p_el, p_er);
        edge_att_kernel<1><<<cdiv(N_EDGES, 256), 256>>>(p_el, p_er, p_etatt + 96, p_att);
        seg_maxsum_kernel<1><<<cdiv(N_NODES, 256), 256>>>(p_att, p_m, p_s);
        edge_a_kernel<1, false><<<cdiv(N_EDGES, 256), 256>>>(p_att, p_m, p_s, nullptr, p_att);
        aggregate1_kernel<<<WB, 256>>>(p_f2, p_att, out);
    }
}

// round 4
// speedup vs baseline: 1.4033x; 1.0452x over previous
#include <cuda_runtime.h>
#include <cuda_bf16.h>
#include <math.h>
#include <stdint.h>
#include <string.h>

// ---------------------------------------------------------------------------
// SimpleHGN forward, round 4:
//  - GEMMs: bf16 hi/lo split on mma.sync.m16n8k16 (2x fewer mma than tf32 k8),
//    smem tiles pre-packed as bf16x2, mainloop = pure LDS+MMA
//  - per-layer fused edge kernel: online softmax + blend + aggregate + ELU
//  - launch order puts layer-0 GEMM at profiled slot
// ---------------------------------------------------------------------------

#define N_NODES 50000
#define N_EDGES 800000
#define N0 20000
#define N1 17000
#define N2 13000
#define SCAN_B 512
#define SCAN_NB ((N_NODES + SCAN_B - 1) / SCAN_B)

// ------------------------------ scratch ------------------------------------
__device__ int   g_cnt[N_NODES];
__device__ int   g_rowptr[N_NODES + 1];
__device__ int   g_cursor[N_NODES];
__device__ int   g_bsum[SCAN_NB];
__device__ int   g_boff[SCAN_NB];
__device__ int   g_srcS[N_EDGES];
__device__ int   g_dstS[N_EDGES];
__device__ int   g_etS[N_EDGES];

__device__ float g_h0[N_NODES * 64];
__device__ float g_feat[N_NODES * 256];
__device__ float g_res[N_NODES * 256];
__device__ float g_hA[N_NODES * 256];
__device__ float g_hB[N_NODES * 256];
__device__ float g_f2[N_NODES * 32];
__device__ float g_Bcat[256 * 32];
__device__ float g_a0[N_EDGES * 8];
__device__ float g_el[N_NODES * 8];
__device__ float g_er[N_NODES * 8];
__device__ float g_etatt[3 * 6 * 8];

// ------------------------------ CSR build ----------------------------------
__global__ void hist_kernel(const int* __restrict__ dst) {
    int e = blockIdx.x * blockDim.x + threadIdx.x;
    if (e < N_EDGES) atomicAdd(&g_cnt[dst[e]], 1);
}

__global__ void scan_block_kernel() {
    __shared__ int sh[SCAN_B];
    int t = threadIdx.x;
    int i = blockIdx.x * SCAN_B + t;
    int v = (i < N_NODES) ? g_cnt[i] : 0;
    sh[t] = v;
    __syncthreads();
    #pragma unroll
    for (int off = 1; off < SCAN_B; off <<= 1) {
        int tmp = (t >= off) ? sh[t - off] : 0;
        __syncthreads();
        sh[t] += tmp;
        __syncthreads();
    }
    if (i < N_NODES) g_rowptr[i + 1] = sh[t];
    if (t == SCAN_B - 1) g_bsum[blockIdx.x] = sh[t];
}

__global__ void scan_top_kernel() {
    __shared__ int sh[128];
    int t = threadIdx.x;
    int v = (t < SCAN_NB) ? g_bsum[t] : 0;
    sh[t] = v;
    __syncthreads();
    #pragma unroll
    for (int off = 1; off < 128; off <<= 1) {
        int tmp = (t >= off) ? sh[t - off] : 0;
        __syncthreads();
        sh[t] += tmp;
        __syncthreads();
    }
    if (t < SCAN_NB) g_boff[t] = sh[t] - v;
}

__global__ void scan_add_kernel() {
    int t = threadIdx.x;
    int i = blockIdx.x * SCAN_B + t;
    if (i < N_NODES) {
        int v = g_rowptr[i + 1] + g_boff[blockIdx.x];
        g_rowptr[i + 1] = v;
        g_cursor[i] = v - g_cnt[i];   // exclusive prefix = scatter cursor
    }
    if (i == 0) g_rowptr[0] = 0;
}

__global__ void scatter_kernel(const int* __restrict__ src, const int* __restrict__ dst,
                               const int* __restrict__ et) {
    int e = blockIdx.x * blockDim.x + threadIdx.x;
    if (e >= N_EDGES) return;
    int d = dst[e];
    int pos = atomicAdd(&g_cursor[d], 1);
    g_srcS[pos] = src[e];
    g_dstS[pos] = d;
    g_etS[pos]  = et[e];
}

// ------------------------------ edge-type attention ------------------------
__global__ void etype_att_kernel(const float* __restrict__ eemb, const float* __restrict__ We,
                                 const float* __restrict__ ae, float* __restrict__ out, int H) {
    int t = blockIdx.x / H;
    int h = blockIdx.x % H;
    int d = threadIdx.x;
    int Wcols = H * 64;
    float v = 0.f;
    #pragma unroll 4
    for (int k = 0; k < 64; k++)
        v += eemb[t * 64 + k] * We[k * Wcols + h * 64 + d];
    v *= ae[h * 64 + d];
    __shared__ float sh[64];
    sh[d] = v;
    __syncthreads();
    #pragma unroll
    for (int o = 32; o > 0; o >>= 1) {
        if (d < o) sh[d] += sh[d + o];
        __syncthreads();
    }
    if (d == 0) out[t * H + h] = sh[0];
}

__global__ void concat_w2_kernel(const float* __restrict__ W2, const float* __restrict__ resW2,
                                 float* __restrict__ Bcat) {
    int i = blockIdx.x * blockDim.x + threadIdx.x;
    if (i < 256 * 16) {
        int r = i >> 4, c = i & 15;
        Bcat[r * 32 + c] = W2[i];
        Bcat[r * 32 + 16 + c] = resW2[i];
    }
}

// ------------------------------ bf16 split GEMM ----------------------------
__device__ __forceinline__ uint32_t pack2(float x, float y) {
    __nv_bfloat162 t = __floats2bfloat162_rn(x, y);   // .x -> low half
    uint32_t w;
    memcpy(&w, &t, 4);
    return w;
}
__device__ __forceinline__ float bfhi(float x) {
    return __bfloat162float(__float2bfloat16(x));
}

__device__ __forceinline__ void mma_bf16(float* c, uint32_t a0, uint32_t a1,
                                         uint32_t a2, uint32_t a3,
                                         uint32_t b0, uint32_t b1) {
    asm volatile(
        "mma.sync.aligned.m16n8k16.row.col.f32.bf16.bf16.f32 "
        "{%0,%1,%2,%3}, {%4,%5,%6,%7}, {%8,%9}, {%0,%1,%2,%3};"
        : "+f"(c[0]), "+f"(c[1]), "+f"(c[2]), "+f"(c[3])
        : "r"(a0), "r"(a1), "r"(a2), "r"(a3), "r"(b0), "r"(b1));
}

// C[M,Nc] = A @ B (+bias). BM=128, BN=NT*16, BK=32. 256 thr = 8 warps (4Mx2N).
// smem: packed bf16x2 pairs along K, hi and lo planes. PAD=20 words (conflict-free).
template <int NT, bool BIAS>
__global__ void __launch_bounds__(256) gemm_bf16(const float* __restrict__ A,
                                                 const float* __restrict__ B,
                                                 const float* __restrict__ bias,
                                                 float* __restrict__ C,
                                                 int M, int Nc, int K) {
    constexpr int BN = NT * 16;
    constexpr int PAD = 20;
    __shared__ uint32_t AsH[128 * PAD], AsL[128 * PAD];
    __shared__ uint32_t BsH[BN * PAD],  BsL[BN * PAD];
    int tid = threadIdx.x;
    int wid = tid >> 5, lane = tid & 31;
    int g = lane >> 2, tig = lane & 3;
    int warpM = wid & 3, warpN = wid >> 2;
    int row0 = blockIdx.y * 128, col0 = blockIdx.x * BN;

    float acc[2][NT][4];
    #pragma unroll
    for (int mt = 0; mt < 2; mt++)
        #pragma unroll
        for (int nt = 0; nt < NT; nt++)
            #pragma unroll
            for (int j = 0; j < 4; j++) acc[mt][nt][j] = 0.f;

    for (int k0 = 0; k0 < K; k0 += 32) {
        // A tile 128x32 -> pairs along k
        #pragma unroll
        for (int i = 0; i < 4; i++) {
            int lin = tid + i * 256;
            int r = lin >> 3, c4 = lin & 7;
            int gr = row0 + r;
            float4 v = (gr < M) ? *(const float4*)&A[(size_t)gr * K + k0 + c4 * 4]
                                : make_float4(0.f, 0.f, 0.f, 0.f);
            float hx = bfhi(v.x), hy = bfhi(v.y), hz = bfhi(v.z), hw = bfhi(v.w);
            AsH[r * PAD + c4 * 2]     = pack2(v.x, v.y);
            AsH[r * PAD + c4 * 2 + 1] = pack2(v.z, v.w);
            AsL[r * PAD + c4 * 2]     = pack2(v.x - hx, v.y - hy);
            AsL[r * PAD + c4 * 2 + 1] = pack2(v.z - hz, v.w - hw);
        }
        // B tile 32xBN -> pairs along k (two rows per pair)
        constexpr int BT = 16 * (BN / 4);
        #pragma unroll
        for (int i = 0; i < (BT + 255) / 256; i++) {
            int lin = tid + i * 256;
            if (lin < BT) {
                int kp = lin / (BN / 4);
                int n4 = lin % (BN / 4);
                const float* b0p = B + (size_t)(k0 + kp * 2) * Nc + col0 + n4 * 4;
                float4 u0 = *(const float4*)b0p;
                float4 u1 = *(const float4*)(b0p + Nc);
                float u0a[4] = {u0.x, u0.y, u0.z, u0.w};
                float u1a[4] = {u1.x, u1.y, u1.z, u1.w};
                #pragma unroll
                for (int j = 0; j < 4; j++) {
                    float h0 = bfhi(u0a[j]), h1 = bfhi(u1a[j]);
                    BsH[(n4 * 4 + j) * PAD + kp] = pack2(u0a[j], u1a[j]);
                    BsL[(n4 * 4 + j) * PAD + kp] = pack2(u0a[j] - h0, u1a[j] - h1);
                }
            }
        }
        __syncthreads();

        #pragma unroll
        for (int kh = 0; kh < 2; kh++) {
            int kp0 = kh * 8;
            uint32_t aH[2][4], aL[2][4];
            #pragma unroll
            for (int mt = 0; mt < 2; mt++) {
                int m0 = warpM * 32 + mt * 16;
                int base = (m0 + g) * PAD + kp0 + tig;
                aH[mt][0] = AsH[base];
                aH[mt][1] = AsH[base + 8 * PAD];
                aH[mt][2] = AsH[base + 4];
                aH[mt][3] = AsH[base + 8 * PAD + 4];
                aL[mt][0] = AsL[base];
                aL[mt][1] = AsL[base + 8 * PAD];
                aL[mt][2] = AsL[base + 4];
                aL[mt][3] = AsL[base + 8 * PAD + 4];
            }
            #pragma unroll
            for (int nt = 0; nt < NT; nt++) {
                int n0 = warpN * (NT * 8) + nt * 8;
                int bbase = (n0 + g) * PAD + kp0 + tig;
                uint32_t bh0 = BsH[bbase], bh1 = BsH[bbase + 4];
                uint32_t bl0 = BsL[bbase], bl1 = BsL[bbase + 4];
                #pragma unroll
                for (int mt = 0; mt < 2; mt++) {
                    mma_bf16(acc[mt][nt], aH[mt][0], aH[mt][1], aH[mt][2], aH[mt][3], bh0, bh1);
                    mma_bf16(acc[mt][nt], aL[mt][0], aL[mt][1], aL[mt][2], aL[mt][3], bh0, bh1);
                    mma_bf16(acc[mt][nt], aH[mt][0], aH[mt][1], aH[mt][2], aH[mt][3], bl0, bl1);
                }
            }
        }
        __syncthreads();
    }

    #pragma unroll
    for (int mt = 0; mt < 2; mt++) {
        #pragma unroll
        for (int nt = 0; nt < NT; nt++) {
            int r0 = row0 + warpM * 32 + mt * 16 + g;
            int c  = col0 + warpN * (NT * 8) + nt * 8 + tig * 2;
            float b0a = BIAS ? bias[c] : 0.f;
            float b1a = BIAS ? bias[c + 1] : 0.f;
            if (r0 < M) {
                C[(size_t)r0 * Nc + c]     = acc[mt][nt][0] + b0a;
                C[(size_t)r0 * Nc + c + 1] = acc[mt][nt][1] + b1a;
            }
            if (r0 + 8 < M) {
                C[(size_t)(r0 + 8) * Nc + c]     = acc[mt][nt][2] + b0a;
                C[(size_t)(r0 + 8) * Nc + c + 1] = acc[mt][nt][3] + b1a;
            }
        }
    }
}

// ------------------------------ per-node el/er -----------------------------
template <int H, int OUT, int STRIDE>
__global__ void node_attn_kernel(const float* __restrict__ feat, const float* __restrict__ al,
                                 const float* __restrict__ ar, float* __restrict__ el,
                                 float* __restrict__ er) {
    int warp = (blockIdx.x * blockDim.x + threadIdx.x) >> 5;
    int lane = threadIdx.x & 31;
    if (warp >= N_NODES) return;
    const float* f = feat + (size_t)warp * STRIDE;
    #pragma unroll
    for (int h = 0; h < H; h++) {
        float v = 0.f, w = 0.f;
        if (lane < OUT) {
            float x = f[h * OUT + lane];
            v = x * al[h * OUT + lane];
            w = x * ar[h * OUT + lane];
        }
        #pragma unroll
        for (int o = 16; o > 0; o >>= 1) {
            v += __shfl_down_sync(0xffffffffu, v, o);
            w += __shfl_down_sync(0xffffffffu, w, o);
        }
        if (lane == 0) {
            el[warp * H + h] = v;
            er[warp * H + h] = w;
        }
    }
}

// ------------------------------ fused GAT edge kernel (H=8) ----------------
// warp per dst node: online softmax over incoming edges, normalize (+blend /
// save), aggregate feat, residual, ELU. lanes = (eslot 0..3, head 0..7).
template <bool BLEND, bool SAVE_A, bool RES, bool ELU>
__global__ void fused_gat8(const float* __restrict__ feat, const float* __restrict__ el,
                           const float* __restrict__ er, const float* __restrict__ etatt,
                           const float* __restrict__ res, float* __restrict__ a0,
                           float* __restrict__ out) {
    int warp = (blockIdx.x * blockDim.x + threadIdx.x) >> 5;
    int lane = threadIdx.x & 31;
    if (warp >= N_NODES) return;
    int n = warp;
    int h = lane & 7, eslot = lane >> 3;
    float er_n = er[n * 8 + h];
    float eat[6];
    #pragma unroll
    for (int t = 0; t < 6; t++) eat[t] = etatt[t * 8 + h];
    int b = g_rowptr[n], e = g_rowptr[n + 1];

    float m = -1e30f, s = 0.f;
    for (int i0 = b; i0 < e; i0 += 4) {
        int i = i0 + eslot;
        if (i < e) {
            float ev = el[g_srcS[i] * 8 + h] + er_n + eat[g_etS[i]];
            ev = (ev > 0.f) ? ev : 0.2f * ev;
            float nm = fmaxf(m, ev);
            s = s * __expf(m - nm) + __expf(ev - nm);
            m = nm;
        }
    }
    #pragma unroll
    for (int off = 8; off <= 16; off <<= 1) {
        float om = __shfl_xor_sync(0xffffffffu, m, off);
        float os = __shfl_xor_sync(0xffffffffu, s, off);
        float nm = fmaxf(m, om);
        s = s * __expf(m - nm) + os * __expf(om - nm);
        m = nm;
    }

    float acc[8];
    #pragma unroll
    for (int h2 = 0; h2 < 8; h2++)
        acc[h2] = RES ? res[(size_t)n * 256 + h2 * 32 + lane] : 0.f;

    for (int i0 = b; i0 < e; i0 += 4) {
        int i = i0 + eslot;
        float a = 0.f;
        int sidx = 0;
        if (i < e) {
            sidx = g_srcS[i];
            float ev = el[sidx * 8 + h] + er_n + eat[g_etS[i]];
            ev = (ev > 0.f) ? ev : 0.2f * ev;
            a = __expf(ev - m) / s;
            if (BLEND) a = a * 0.95f + 0.05f * a0[(size_t)i * 8 + h];
            if (SAVE_A) a0[(size_t)i * 8 + h] = a;
        }
        #pragma unroll
        for (int e2 = 0; e2 < 4; e2++) {
            if (i0 + e2 < e) {
                int s2 = __shfl_sync(0xffffffffu, sidx, e2 * 8);
                const float* f = feat + (size_t)s2 * 256;
                #pragma unroll
                for (int h2 = 0; h2 < 8; h2++) {
                    float ah = __shfl_sync(0xffffffffu, a, e2 * 8 + h2);
                    acc[h2] += ah * f[h2 * 32 + lane];
                }
            }
        }
    }
    #pragma unroll
    for (int h2 = 0; h2 < 8; h2++) {
        float v = acc[h2];
        if (ELU) v = (v > 0.f) ? v : expm1f(v);
        out[(size_t)n * 256 + h2 * 32 + lane] = v;
    }
}

// ------------------------------ fused GAT edge kernel (H=1, out 16) --------
__global__ void fused_gat1(const float* __restrict__ f2, const float* __restrict__ el,
                           const float* __restrict__ er, const float* __restrict__ etatt,
                           float* __restrict__ out) {
    int warp = (blockIdx.x * blockDim.x + threadIdx.x) >> 5;
    int lane = threadIdx.x & 31;
    if (warp >= N_NODES) return;
    int n = warp;
    float er_n = er[n];
    float eat[6];
    #pragma unroll
    for (int t = 0; t < 6; t++) eat[t] = etatt[t];
    int b = g_rowptr[n], e = g_rowptr[n + 1];

    float m = -1e30f, s = 0.f;
    for (int i0 = b; i0 < e; i0 += 32) {
        int i = i0 + lane;
        if (i < e) {
            float ev = el[g_srcS[i]] + er_n + eat[g_etS[i]];
            ev = (ev > 0.f) ? ev : 0.2f * ev;
            float nm = fmaxf(m, ev);
            s = s * __expf(m - nm) + __expf(ev - nm);
            m = nm;
        }
    }
    #pragma unroll
    for (int off = 16; off > 0; off >>= 1) {
        float om = __shfl_xor_sync(0xffffffffu, m, off);
        float os = __shfl_xor_sync(0xffffffffu, s, off);
        float nm = fmaxf(m, om);
        s = s * __expf(m - nm) + os * __expf(om - nm);
        m = nm;
    }

    float acc = 0.f;
    if (lane < 16) acc = f2[(size_t)n * 32 + 16 + lane];   // residual half
    for (int i = b; i < e; i++) {
        int s2 = g_srcS[i];
        float ev = el[s2] + er_n + eat[g_etS[i]];
        ev = (ev > 0.f) ? ev : 0.2f * ev;
        float a = __expf(ev - m) / s;
        if (lane < 16) acc += a * f2[(size_t)s2 * 32 + lane];
    }
    if (lane < 16) out[(size_t)n * 16 + lane] = acc;
}

// ---------------------------------------------------------------------------
static inline int cdiv(int a, int b) { return (a + b - 1) / b; }

extern "C" void kernel_launch(void* const* d_in, const int* in_sizes, int n_in,
                              void* d_out, int out_size) {
    const float* x0    = (const float*)d_in[0];
    const float* x1    = (const float*)d_in[1];
    const float* x2    = (const float*)d_in[2];
    const float* fcw0  = (const float*)d_in[3];
    const float* fcb0  = (const float*)d_in[4];
    const float* fcw1  = (const float*)d_in[5];
    const float* fcb1  = (const float*)d_in[6];
    const float* fcw2  = (const float*)d_in[7];
    const float* fcb2  = (const float*)d_in[8];
    const float* W0    = (const float*)d_in[9];
    const float* We0   = (const float*)d_in[10];
    const float* eemb0 = (const float*)d_in[11];
    const float* al0   = (const float*)d_in[12];
    const float* ar0   = (const float*)d_in[13];
    const float* ae0   = (const float*)d_in[14];
    const float* W1    = (const float*)d_in[15];
    const float* We1   = (const float*)d_in[16];
    const float* eemb1 = (const float*)d_in[17];
    const float* al1   = (const float*)d_in[18];
    const float* ar1   = (const float*)d_in[19];
    const float* ae1   = (const float*)d_in[20];
    const float* resW1 = (const float*)d_in[21];
    const float* W2    = (const float*)d_in[22];
    const float* We2   = (const float*)d_in[23];
    const float* eemb2 = (const float*)d_in[24];
    const float* al2   = (const float*)d_in[25];
    const float* ar2   = (const float*)d_in[26];
    const float* ae2   = (const float*)d_in[27];
    const float* resW2 = (const float*)d_in[28];
    const int*   src   = (const int*)d_in[29];
    const int*   dst   = (const int*)d_in[30];
    const int*   etype = (const int*)d_in[31];
    float* out = (float*)d_out;

    float *p_h0, *p_feat, *p_res, *p_hA, *p_hB, *p_f2, *p_Bcat, *p_a0,
          *p_el, *p_er, *p_etatt;
    int* p_cnt;
    cudaGetSymbolAddress((void**)&p_cnt, g_cnt);
    cudaGetSymbolAddress((void**)&p_h0, g_h0);
    cudaGetSymbolAddress((void**)&p_feat, g_feat);
    cudaGetSymbolAddress((void**)&p_res, g_res);
    cudaGetSymbolAddress((void**)&p_hA, g_hA);
    cudaGetSymbolAddress((void**)&p_hB, g_hB);
    cudaGetSymbolAddress((void**)&p_f2, g_f2);
    cudaGetSymbolAddress((void**)&p_Bcat, g_Bcat);
    cudaGetSymbolAddress((void**)&p_a0, g_a0);
    cudaGetSymbolAddress((void**)&p_el, g_el);
    cudaGetSymbolAddress((void**)&p_er, g_er);
    cudaGetSymbolAddress((void**)&p_etatt, g_etatt);

    const int WB = cdiv(N_NODES * 32, 256);

    // 1: memset, 2-4: input projections, 5: layer-0 GEMM (profiled slot)
    cudaMemsetAsync(p_cnt, 0, N_NODES * sizeof(int));
    {
        dim3 g0(1, cdiv(N0, 128));
        gemm_bf16<4, true><<<g0, 256>>>(x0, fcw0, fcb0, p_h0, N0, 64, 128);
        dim3 g1(1, cdiv(N1, 128));
        gemm_bf16<4, true><<<g1, 256>>>(x1, fcw1, fcb1, p_h0 + (size_t)N0 * 64, N1, 64, 256);
        dim3 g2(1, cdiv(N2, 128));
        gemm_bf16<4, true><<<g2, 256>>>(x2, fcw2, fcb2, p_h0 + (size_t)(N0 + N1) * 64, N2, 64, 64);
    }
    {
        dim3 gg(2, cdiv(N_NODES, 128));
        gemm_bf16<8, false><<<gg, 256>>>(p_h0, W0, nullptr, p_feat, N_NODES, 256, 64);
    }

    // CSR build
    hist_kernel<<<cdiv(N_EDGES, 256), 256>>>(dst);
    scan_block_kernel<<<SCAN_NB, SCAN_B>>>();
    scan_top_kernel<<<1, 128>>>();
    scan_add_kernel<<<SCAN_NB, SCAN_B>>>();
    scatter_kernel<<<cdiv(N_EDGES, 256), 256>>>(src, dst, etype);

    // tiny weight preps
    etype_att_kernel<<<6 * 8, 64>>>(eemb0, We0, ae0, p_etatt + 0, 8);
    etype_att_kernel<<<6 * 8, 64>>>(eemb1, We1, ae1, p_etatt + 48, 8);
    etype_att_kernel<<<6 * 1, 64>>>(eemb2, We2, ae2, p_etatt + 96, 1);
    concat_w2_kernel<<<16, 256>>>(W2, resW2, p_Bcat);

    // ---- layer 0 ----
    node_attn_kernel<8, 32, 256><<<WB, 256>>>(p_feat, al0, ar0, p_el, p_er);
    fused_gat8<false, true, false, true><<<WB, 256>>>(p_feat, p_el, p_er, p_etatt + 0,
                                                      nullptr, p_a0, p_hA);

    // ---- layer 1 ----
    {
        dim3 gg(2, cdiv(N_NODES, 128));
        gemm_bf16<8, false><<<gg, 256>>>(p_hA, W1, nullptr, p_feat, N_NODES, 256, 256);
        gemm_bf16<8, false><<<gg, 256>>>(p_hA, resW1, nullptr, p_res, N_NODES, 256, 256);
    }
    node_attn_kernel<8, 32, 256><<<WB, 256>>>(p_feat, al1, ar1, p_el, p_er);
    fused_gat8<true, false, true, true><<<WB, 256>>>(p_feat, p_el, p_er, p_etatt + 48,
                                                     p_res, p_a0, p_hB);

    // ---- layer 2 ----
    {
        dim3 gg(1, cdiv(N_NODES, 128));
        gemm_bf16<2, false><<<gg, 256>>>(p_hB, p_Bcat, nullptr, p_f2, N_NODES, 32, 256);
    }
    node_attn_kernel<1, 16, 32><<<WB, 256>>>(p_f2, al2, ar2, p_el, p_er);
    fused_gat1<<<WB, 256>>>(p_f2, p_el, p_er, p_etatt + 96, out);
}

// round 5
// speedup vs baseline: 1.4751x; 1.0512x over previous
#include <cuda_runtime.h>
#include <cuda_bf16.h>
#include <math.h>
#include <stdint.h>
#include <string.h>

// ---------------------------------------------------------------------------
// SimpleHGN forward, round 5:
//  - GEMM re-architected: 512 threads (16 warps, 4x4), warp tile 32x32,
//    register-prefetch software pipeline; bf16 hi/lo 3-term split unchanged.
//  - fused per-layer edge kernels unchanged.
// ---------------------------------------------------------------------------

#define N_NODES 50000
#define N_EDGES 800000
#define N0 20000
#define N1 17000
#define N2 13000
#define SCAN_B 512
#define SCAN_NB ((N_NODES + SCAN_B - 1) / SCAN_B)

// ------------------------------ scratch ------------------------------------
__device__ int   g_cnt[N_NODES];
__device__ int   g_rowptr[N_NODES + 1];
__device__ int   g_cursor[N_NODES];
__device__ int   g_bsum[SCAN_NB];
__device__ int   g_boff[SCAN_NB];
__device__ int   g_srcS[N_EDGES];
__device__ int   g_dstS[N_EDGES];
__device__ int   g_etS[N_EDGES];

__device__ float g_h0[N_NODES * 64];
__device__ float g_feat[N_NODES * 256];
__device__ float g_res[N_NODES * 256];
__device__ float g_hA[N_NODES * 256];
__device__ float g_hB[N_NODES * 256];
__device__ float g_f2[N_NODES * 32];
__device__ float g_Bcat[256 * 32];
__device__ float g_a0[N_EDGES * 8];
__device__ float g_el[N_NODES * 8];
__device__ float g_er[N_NODES * 8];
__device__ float g_etatt[3 * 6 * 8];

// ------------------------------ CSR build ----------------------------------
__global__ void hist_kernel(const int* __restrict__ dst) {
    int e = blockIdx.x * blockDim.x + threadIdx.x;
    if (e < N_EDGES) atomicAdd(&g_cnt[dst[e]], 1);
}

__global__ void scan_block_kernel() {
    __shared__ int sh[SCAN_B];
    int t = threadIdx.x;
    int i = blockIdx.x * SCAN_B + t;
    int v = (i < N_NODES) ? g_cnt[i] : 0;
    sh[t] = v;
    __syncthreads();
    #pragma unroll
    for (int off = 1; off < SCAN_B; off <<= 1) {
        int tmp = (t >= off) ? sh[t - off] : 0;
        __syncthreads();
        sh[t] += tmp;
        __syncthreads();
    }
    if (i < N_NODES) g_rowptr[i + 1] = sh[t];
    if (t == SCAN_B - 1) g_bsum[blockIdx.x] = sh[t];
}

__global__ void scan_top_kernel() {
    __shared__ int sh[128];
    int t = threadIdx.x;
    int v = (t < SCAN_NB) ? g_bsum[t] : 0;
    sh[t] = v;
    __syncthreads();
    #pragma unroll
    for (int off = 1; off < 128; off <<= 1) {
        int tmp = (t >= off) ? sh[t - off] : 0;
        __syncthreads();
        sh[t] += tmp;
        __syncthreads();
    }
    if (t < SCAN_NB) g_boff[t] = sh[t] - v;
}

__global__ void scan_add_kernel() {
    int t = threadIdx.x;
    int i = blockIdx.x * SCAN_B + t;
    if (i < N_NODES) {
        int v = g_rowptr[i + 1] + g_boff[blockIdx.x];
        g_rowptr[i + 1] = v;
        g_cursor[i] = v - g_cnt[i];
    }
    if (i == 0) g_rowptr[0] = 0;
}

__global__ void scatter_kernel(const int* __restrict__ src, const int* __restrict__ dst,
                               const int* __restrict__ et) {
    int e = blockIdx.x * blockDim.x + threadIdx.x;
    if (e >= N_EDGES) return;
    int d = dst[e];
    int pos = atomicAdd(&g_cursor[d], 1);
    g_srcS[pos] = src[e];
    g_dstS[pos] = d;
    g_etS[pos]  = et[e];
}

// ------------------------------ edge-type attention ------------------------
__global__ void etype_att_kernel(const float* __restrict__ eemb, const float* __restrict__ We,
                                 const float* __restrict__ ae, float* __restrict__ out, int H) {
    int t = blockIdx.x / H;
    int h = blockIdx.x % H;
    int d = threadIdx.x;
    int Wcols = H * 64;
    float v = 0.f;
    #pragma unroll 4
    for (int k = 0; k < 64; k++)
        v += eemb[t * 64 + k] * We[k * Wcols + h * 64 + d];
    v *= ae[h * 64 + d];
    __shared__ float sh[64];
    sh[d] = v;
    __syncthreads();
    #pragma unroll
    for (int o = 32; o > 0; o >>= 1) {
        if (d < o) sh[d] += sh[d + o];
        __syncthreads();
    }
    if (d == 0) out[t * H + h] = sh[0];
}

__global__ void concat_w2_kernel(const float* __restrict__ W2, const float* __restrict__ resW2,
                                 float* __restrict__ Bcat) {
    int i = blockIdx.x * blockDim.x + threadIdx.x;
    if (i < 256 * 16) {
        int r = i >> 4, c = i & 15;
        Bcat[r * 32 + c] = W2[i];
        Bcat[r * 32 + 16 + c] = resW2[i];
    }
}

// ------------------------------ bf16 split GEMM ----------------------------
__device__ __forceinline__ uint32_t pack2(float x, float y) {
    __nv_bfloat162 t = __floats2bfloat162_rn(x, y);
    uint32_t w;
    memcpy(&w, &t, 4);
    return w;
}
__device__ __forceinline__ float bfhi(float x) {
    return __bfloat162float(__float2bfloat16(x));
}

__device__ __forceinline__ void mma_bf16(float* c, uint32_t a0, uint32_t a1,
                                         uint32_t a2, uint32_t a3,
                                         uint32_t b0, uint32_t b1) {
    asm volatile(
        "mma.sync.aligned.m16n8k16.row.col.f32.bf16.bf16.f32 "
        "{%0,%1,%2,%3}, {%4,%5,%6,%7}, {%8,%9}, {%0,%1,%2,%3};"
        : "+f"(c[0]), "+f"(c[1]), "+f"(c[2]), "+f"(c[3])
        : "r"(a0), "r"(a1), "r"(a2), "r"(a3), "r"(b0), "r"(b1));
}

// C[M,Nc] = A @ B (+bias). BM=128, BN=NT*32, BK=32.
// 512 threads = 16 warps (4M x 4N); warp tile 32 x (NT*8).
// Register-prefetch pipeline: global loads of tile k+1 issued before mma of
// tile k. bf16 hi/lo 3-term split for ~fp32 accuracy.
template <int NT, bool BIAS>
__global__ void __launch_bounds__(512, 1) gemm_bf16(const float* __restrict__ A,
                                                    const float* __restrict__ B,
                                                    const float* __restrict__ bias,
                                                    float* __restrict__ C,
                                                    int M, int Nc, int K) {
    constexpr int BN = NT * 32;
    constexpr int PAD = 20;
    constexpr int BT = 16 * (BN / 4);          // B-tile load entries
    __shared__ uint32_t AsH[128 * PAD], AsL[128 * PAD];
    __shared__ uint32_t BsH[BN * PAD],  BsL[BN * PAD];
    int tid = threadIdx.x;
    int wid = tid >> 5, lane = tid & 31;
    int g = lane >> 2, tig = lane & 3;
    int warpM = wid & 3, warpN = wid >> 2;
    int row0 = blockIdx.y * 128, col0 = blockIdx.x * BN;

    float acc[2][NT][4];
    #pragma unroll
    for (int mt = 0; mt < 2; mt++)
        #pragma unroll
        for (int nt = 0; nt < NT; nt++)
            #pragma unroll
            for (int j = 0; j < 4; j++) acc[mt][nt][j] = 0.f;

    // prefetch registers
    float4 aPre[2];
    float4 bPre0, bPre1;
    int aR[2], aC[2];
    int bKp = 0, bN4 = 0;

    auto loadTile = [&](int k0) {
        #pragma unroll
        for (int i = 0; i < 2; i++) {
            int lin = tid + i * 512;
            int r = lin >> 3, c4 = lin & 7;
            aR[i] = r; aC[i] = c4;
            int gr = row0 + r;
            aPre[i] = (gr < M) ? *(const float4*)&A[(size_t)gr * K + k0 + c4 * 4]
                               : make_float4(0.f, 0.f, 0.f, 0.f);
        }
        if (tid < BT) {
            bKp = tid / (BN / 4);
            bN4 = tid % (BN / 4);
            const float* bp = B + (size_t)(k0 + bKp * 2) * Nc + col0 + bN4 * 4;
            bPre0 = *(const float4*)bp;
            bPre1 = *(const float4*)(bp + Nc);
        }
    };

    auto storeTile = [&]() {
        #pragma unroll
        for (int i = 0; i < 2; i++) {
            float4 v = aPre[i];
            int r = aR[i], c4 = aC[i];
            float hx = bfhi(v.x), hy = bfhi(v.y), hz = bfhi(v.z), hw = bfhi(v.w);
            AsH[r * PAD + c4 * 2]     = pack2(v.x, v.y);
            AsH[r * PAD + c4 * 2 + 1] = pack2(v.z, v.w);
            AsL[r * PAD + c4 * 2]     = pack2(v.x - hx, v.y - hy);
            AsL[r * PAD + c4 * 2 + 1] = pack2(v.z - hz, v.w - hw);
        }
        if (tid < BT) {
            float u0a[4] = {bPre0.x, bPre0.y, bPre0.z, bPre0.w};
            float u1a[4] = {bPre1.x, bPre1.y, bPre1.z, bPre1.w};
            #pragma unroll
            for (int j = 0; j < 4; j++) {
                float h0 = bfhi(u0a[j]), h1 = bfhi(u1a[j]);
                BsH[(bN4 * 4 + j) * PAD + bKp] = pack2(u0a[j], u1a[j]);
                BsL[(bN4 * 4 + j) * PAD + bKp] = pack2(u0a[j] - h0, u1a[j] - h1);
            }
        }
    };

    int nk = K >> 5;
    loadTile(0);
    for (int kt = 0; kt < nk; kt++) {
        storeTile();
        __syncthreads();
        if (kt + 1 < nk) loadTile((kt + 1) << 5);

        #pragma unroll
        for (int kh = 0; kh < 2; kh++) {
            int kp0 = kh * 8;
            uint32_t aH[2][4], aL[2][4];
            #pragma unroll
            for (int mt = 0; mt < 2; mt++) {
                int m0 = warpM * 32 + mt * 16;
                int base = (m0 + g) * PAD + kp0 + tig;
                aH[mt][0] = AsH[base];
                aH[mt][1] = AsH[base + 8 * PAD];
                aH[mt][2] = AsH[base + 4];
                aH[mt][3] = AsH[base + 8 * PAD + 4];
                aL[mt][0] = AsL[base];
                aL[mt][1] = AsL[base + 8 * PAD];
                aL[mt][2] = AsL[base + 4];
                aL[mt][3] = AsL[base + 8 * PAD + 4];
            }
            #pragma unroll
            for (int nt = 0; nt < NT; nt++) {
                int n0 = warpN * (NT * 8) + nt * 8;
                int bbase = (n0 + g) * PAD + kp0 + tig;
                uint32_t bh0 = BsH[bbase], bh1 = BsH[bbase + 4];
                uint32_t bl0 = BsL[bbase], bl1 = BsL[bbase + 4];
                #pragma unroll
                for (int mt = 0; mt < 2; mt++) {
                    mma_bf16(acc[mt][nt], aH[mt][0], aH[mt][1], aH[mt][2], aH[mt][3], bh0, bh1);
                    mma_bf16(acc[mt][nt], aL[mt][0], aL[mt][1], aL[mt][2], aL[mt][3], bh0, bh1);
                    mma_bf16(acc[mt][nt], aH[mt][0], aH[mt][1], aH[mt][2], aH[mt][3], bl0, bl1);
                }
            }
        }
        __syncthreads();
    }

    #pragma unroll
    for (int mt = 0; mt < 2; mt++) {
        #pragma unroll
        for (int nt = 0; nt < NT; nt++) {
            int r0 = row0 + warpM * 32 + mt * 16 + g;
            int c  = col0 + warpN * (NT * 8) + nt * 8 + tig * 2;
            float b0a = BIAS ? bias[c] : 0.f;
            float b1a = BIAS ? bias[c + 1] : 0.f;
            if (r0 < M) {
                C[(size_t)r0 * Nc + c]     = acc[mt][nt][0] + b0a;
                C[(size_t)r0 * Nc + c + 1] = acc[mt][nt][1] + b1a;
            }
            if (r0 + 8 < M) {
                C[(size_t)(r0 + 8) * Nc + c]     = acc[mt][nt][2] + b0a;
                C[(size_t)(r0 + 8) * Nc + c + 1] = acc[mt][nt][3] + b1a;
            }
        }
    }
}

// ------------------------------ per-node el/er -----------------------------
template <int H, int OUT, int STRIDE>
__global__ void node_attn_kernel(const float* __restrict__ feat, const float* __restrict__ al,
                                 const float* __restrict__ ar, float* __restrict__ el,
                                 float* __restrict__ er) {
    int warp = (blockIdx.x * blockDim.x + threadIdx.x) >> 5;
    int lane = threadIdx.x & 31;
    if (warp >= N_NODES) return;
    const float* f = feat + (size_t)warp * STRIDE;
    #pragma unroll
    for (int h = 0; h < H; h++) {
        float v = 0.f, w = 0.f;
        if (lane < OUT) {
            float x = f[h * OUT + lane];
            v = x * al[h * OUT + lane];
            w = x * ar[h * OUT + lane];
        }
        #pragma unroll
        for (int o = 16; o > 0; o >>= 1) {
            v += __shfl_down_sync(0xffffffffu, v, o);
            w += __shfl_down_sync(0xffffffffu, w, o);
        }
        if (lane == 0) {
            el[warp * H + h] = v;
            er[warp * H + h] = w;
        }
    }
}

// ------------------------------ fused GAT edge kernel (H=8) ----------------
template <bool BLEND, bool SAVE_A, bool RES, bool ELU>
__global__ void fused_gat8(const float* __restrict__ feat, const float* __restrict__ el,
                           const float* __restrict__ er, const float* __restrict__ etatt,
                           const float* __restrict__ res, float* __restrict__ a0,
                           float* __restrict__ out) {
    int warp = (blockIdx.x * blockDim.x + threadIdx.x) >> 5;
    int lane = threadIdx.x & 31;
    if (warp >= N_NODES) return;
    int n = warp;
    int h = lane & 7, eslot = lane >> 3;
    float er_n = er[n * 8 + h];
    float eat[6];
    #pragma unroll
    for (int t = 0; t < 6; t++) eat[t] = etatt[t * 8 + h];
    int b = g_rowptr[n], e = g_rowptr[n + 1];

    float m = -1e30f, s = 0.f;
    for (int i0 = b; i0 < e; i0 += 4) {
        int i = i0 + eslot;
        if (i < e) {
            float ev = el[g_srcS[i] * 8 + h] + er_n + eat[g_etS[i]];
            ev = (ev > 0.f) ? ev : 0.2f * ev;
            float nm = fmaxf(m, ev);
            s = s * __expf(m - nm) + __expf(ev - nm);
            m = nm;
        }
    }
    #pragma unroll
    for (int off = 8; off <= 16; off <<= 1) {
        float om = __shfl_xor_sync(0xffffffffu, m, off);
        float os = __shfl_xor_sync(0xffffffffu, s, off);
        float nm = fmaxf(m, om);
        s = s * __expf(m - nm) + os * __expf(om - nm);
        m = nm;
    }

    float acc[8];
    #pragma unroll
    for (int h2 = 0; h2 < 8; h2++)
        acc[h2] = RES ? res[(size_t)n * 256 + h2 * 32 + lane] : 0.f;

    for (int i0 = b; i0 < e; i0 += 4) {
        int i = i0 + eslot;
        float a = 0.f;
        int sidx = 0;
        if (i < e) {
            sidx = g_srcS[i];
            float ev = el[sidx * 8 + h] + er_n + eat[g_etS[i]];
            ev = (ev > 0.f) ? ev : 0.2f * ev;
            a = __expf(ev - m) / s;
            if (BLEND) a = a * 0.95f + 0.05f * a0[(size_t)i * 8 + h];
            if (SAVE_A) a0[(size_t)i * 8 + h] = a;
        }
        #pragma unroll
        for (int e2 = 0; e2 < 4; e2++) {
            if (i0 + e2 < e) {
                int s2 = __shfl_sync(0xffffffffu, sidx, e2 * 8);
                const float* f = feat + (size_t)s2 * 256;
                #pragma unroll
                for (int h2 = 0; h2 < 8; h2++) {
                    float ah = __shfl_sync(0xffffffffu, a, e2 * 8 + h2);
                    acc[h2] += ah * f[h2 * 32 + lane];
                }
            }
        }
    }
    #pragma unroll
    for (int h2 = 0; h2 < 8; h2++) {
        float v = acc[h2];
        if (ELU) v = (v > 0.f) ? v : expm1f(v);
        out[(size_t)n * 256 + h2 * 32 + lane] = v;
    }
}

// ------------------------------ fused GAT edge kernel (H=1, out 16) --------
__global__ void fused_gat1(const float* __restrict__ f2, const float* __restrict__ el,
                           const float* __restrict__ er, const float* __restrict__ etatt,
                           float* __restrict__ out) {
    int warp = (blockIdx.x * blockDim.x + threadIdx.x) >> 5;
    int lane = threadIdx.x & 31;
    if (warp >= N_NODES) return;
    int n = warp;
    float er_n = er[n];
    float eat[6];
    #pragma unroll
    for (int t = 0; t < 6; t++) eat[t] = etatt[t];
    int b = g_rowptr[n], e = g_rowptr[n + 1];

    float m = -1e30f, s = 0.f;
    for (int i0 = b; i0 < e; i0 += 32) {
        int i = i0 + lane;
        if (i < e) {
            float ev = el[g_srcS[i]] + er_n + eat[g_etS[i]];
            ev = (ev > 0.f) ? ev : 0.2f * ev;
            float nm = fmaxf(m, ev);
            s = s * __expf(m - nm) + __expf(ev - nm);
            m = nm;
        }
    }
    #pragma unroll
    for (int off = 16; off > 0; off >>= 1) {
        float om = __shfl_xor_sync(0xffffffffu, m, off);
        float os = __shfl_xor_sync(0xffffffffu, s, off);
        float nm = fmaxf(m, om);
        s = s * __expf(m - nm) + os * __expf(om - nm);
        m = nm;
    }

    float acc = 0.f;
    if (lane < 16) acc = f2[(size_t)n * 32 + 16 + lane];
    for (int i = b; i < e; i++) {
        int s2 = g_srcS[i];
        float ev = el[s2] + er_n + eat[g_etS[i]];
        ev = (ev > 0.f) ? ev : 0.2f * ev;
        float a = __expf(ev - m) / s;
        if (lane < 16) acc += a * f2[(size_t)s2 * 32 + lane];
    }
    if (lane < 16) out[(size_t)n * 16 + lane] = acc;
}

// ---------------------------------------------------------------------------
static inline int cdiv(int a, int b) { return (a + b - 1) / b; }

extern "C" void kernel_launch(void* const* d_in, const int* in_sizes, int n_in,
                              void* d_out, int out_size) {
    const float* x0    = (const float*)d_in[0];
    const float* x1    = (const float*)d_in[1];
    const float* x2    = (const float*)d_in[2];
    const float* fcw0  = (const float*)d_in[3];
    const float* fcb0  = (const float*)d_in[4];
    const float* fcw1  = (const float*)d_in[5];
    const float* fcb1  = (const float*)d_in[6];
    const float* fcw2  = (const float*)d_in[7];
    const float* fcb2  = (const float*)d_in[8];
    const float* W0    = (const float*)d_in[9];
    const float* We0   = (const float*)d_in[10];
    const float* eemb0 = (const float*)d_in[11];
    const float* al0   = (const float*)d_in[12];
    const float* ar0   = (const float*)d_in[13];
    const float* ae0   = (const float*)d_in[14];
    const float* W1    = (const float*)d_in[15];
    const float* We1   = (const float*)d_in[16];
    const float* eemb1 = (const float*)d_in[17];
    const float* al1   = (const float*)d_in[18];
    const float* ar1   = (const float*)d_in[19];
    const float* ae1   = (const float*)d_in[20];
    const float* resW1 = (const float*)d_in[21];
    const float* W2    = (const float*)d_in[22];
    const float* We2   = (const float*)d_in[23];
    const float* eemb2 = (const float*)d_in[24];
    const float* al2   = (const float*)d_in[25];
    const float* ar2   = (const float*)d_in[26];
    const float* ae2   = (const float*)d_in[27];
    const float* resW2 = (const float*)d_in[28];
    const int*   src   = (const int*)d_in[29];
    const int*   dst   = (const int*)d_in[30];
    const int*   etype = (const int*)d_in[31];
    float* out = (float*)d_out;

    float *p_h0, *p_feat, *p_res, *p_hA, *p_hB, *p_f2, *p_Bcat, *p_a0,
          *p_el, *p_er, *p_etatt;
    int* p_cnt;
    cudaGetSymbolAddress((void**)&p_cnt, g_cnt);
    cudaGetSymbolAddress((void**)&p_h0, g_h0);
    cudaGetSymbolAddress((void**)&p_feat, g_feat);
    cudaGetSymbolAddress((void**)&p_res, g_res);
    cudaGetSymbolAddress((void**)&p_hA, g_hA);
    cudaGetSymbolAddress((void**)&p_hB, g_hB);
    cudaGetSymbolAddress((void**)&p_f2, g_f2);
    cudaGetSymbolAddress((void**)&p_Bcat, g_Bcat);
    cudaGetSymbolAddress((void**)&p_a0, g_a0);
    cudaGetSymbolAddress((void**)&p_el, g_el);
    cudaGetSymbolAddress((void**)&p_er, g_er);
    cudaGetSymbolAddress((void**)&p_etatt, g_etatt);

    const int WB = cdiv(N_NODES * 32, 256);

    // launches 1-4: memset + input projections; 5: layer-0 GEMM (profiled)
    cudaMemsetAsync(p_cnt, 0, N_NODES * sizeof(int));
    {
        dim3 g0(1, cdiv(N0, 128));
        gemm_bf16<2, true><<<g0, 512>>>(x0, fcw0, fcb0, p_h0, N0, 64, 128);
        dim3 g1(1, cdiv(N1, 128));
        gemm_bf16<2, true><<<g1, 512>>>(x1, fcw1, fcb1, p_h0 + (size_t)N0 * 64, N1, 64, 256);
        dim3 g2(1, cdiv(N2, 128));
        gemm_bf16<2, true><<<g2, 512>>>(x2, fcw2, fcb2, p_h0 + (size_t)(N0 + N1) * 64, N2, 64, 64);
    }
    {
        dim3 gg(2, cdiv(N_NODES, 128));
        gemm_bf16<4, false><<<gg, 512>>>(p_h0, W0, nullptr, p_feat, N_NODES, 256, 64);
    }

    // CSR build
    hist_kernel<<<cdiv(N_EDGES, 256), 256>>>(dst);
    scan_block_kernel<<<SCAN_NB, SCAN_B>>>();
    scan_top_kernel<<<1, 128>>>();
    scan_add_kernel<<<SCAN_NB, SCAN_B>>>();
    scatter_kernel<<<cdiv(N_EDGES, 256), 256>>>(src, dst, etype);

    // tiny weight preps
    etype_att_kernel<<<6 * 8, 64>>>(eemb0, We0, ae0, p_etatt + 0, 8);
    etype_att_kernel<<<6 * 8, 64>>>(eemb1, We1, ae1, p_etatt + 48, 8);
    etype_att_kernel<<<6 * 1, 64>>>(eemb2, We2, ae2, p_etatt + 96, 1);
    concat_w2_kernel<<<16, 256>>>(W2, resW2, p_Bcat);

    // ---- layer 0 ----
    node_attn_kernel<8, 32, 256><<<WB, 256>>>(p_feat, al0, ar0, p_el, p_er);
    fused_gat8<false, true, false, true><<<WB, 256>>>(p_feat, p_el, p_er, p_etatt + 0,
                                                      nullptr, p_a0, p_hA);

    // ---- layer 1 ----
    {
        dim3 gg(2, cdiv(N_NODES, 128));
        gemm_bf16<4, false><<<gg, 512>>>(p_hA, W1, nullptr, p_feat, N_NODES, 256, 256);
        gemm_bf16<4, false><<<gg, 512>>>(p_hA, resW1, nullptr, p_res, N_NODES, 256, 256);
    }
    node_attn_kernel<8, 32, 256><<<WB, 256>>>(p_feat, al1, ar1, p_el, p_er);
    fused_gat8<true, false, true, true><<<WB, 256>>>(p_feat, p_el, p_er, p_etatt + 48,
                                                     p_res, p_a0, p_hB);

    // ---- layer 2 ----
    {
        dim3 gg(1, cdiv(N_NODES, 128));
        gemm_bf16<1, false><<<gg, 512>>>(p_hB, p_Bcat, nullptr, p_f2, N_NODES, 32, 256);
    }
    node_attn_kernel<1, 16, 32><<<WB, 256>>>(p_f2, al2, ar2, p_el, p_er);
    fused_gat1<<<WB, 256>>>(p_f2, p_el, p_er, p_etatt + 96, out);
}

// round 7
// speedup vs baseline: 1.7022x; 1.1540x over previous
#include <cuda_runtime.h>
#include <cuda_bf16.h>
#include <math.h>
#include <stdint.h>
#include <string.h>

// ---------------------------------------------------------------------------
// SimpleHGN forward, round 7 (tcgen05 unavailable: harness targets sm_100):
//  - all GEMM operands pre-converted to bf16 hi/lo planes (once per tensor)
//  - GEMM mainloop: cp.async double-buffer -> pure LDS + mma.sync m16n8k16
//  - 3-term hi/lo split (AhBh + AlBh + AhBl) for ~fp32 accuracy
//  - producers (proj GEMM, fused_gat8) emit bf16 planes from their epilogues
// ---------------------------------------------------------------------------

#define N_NODES 50000
#define N_EDGES 800000
#define N0 20000
#define N1 17000
#define N2 13000
#define SCAN_B 512
#define SCAN_NB ((N_NODES + SCAN_B - 1) / SCAN_B)

// weight scratch offsets (bf16 elements, pair-packed layout)
#define OFF_FCW0 0
#define OFF_FCW1 8192
#define OFF_FCW2 24576
#define OFF_W0   28672
#define OFF_W1   45056
#define OFF_RW1  110592
#define OFF_BCAT 176128
#define W_TOTAL  184320

// ------------------------------ scratch ------------------------------------
__device__ int   g_cnt[N_NODES];
__device__ int   g_rowptr[N_NODES + 1];
__device__ int   g_cursor[N_NODES];
__device__ int   g_bsum[SCAN_NB];
__device__ int   g_boff[SCAN_NB];
__device__ int   g_srcS[N_EDGES];
__device__ int   g_dstS[N_EDGES];
__device__ int   g_etS[N_EDGES];

__device__ float g_feat[N_NODES * 256];
__device__ float g_res[N_NODES * 256];
__device__ float g_f2[N_NODES * 32];
__device__ float g_a0[N_EDGES * 8];
__device__ float g_el[N_NODES * 8];
__device__ float g_er[N_NODES * 8];
__device__ float g_etatt[3 * 6 * 8];
__device__ uint16_t g_wh[W_TOTAL];
__device__ uint16_t g_wl[W_TOTAL];

// bf16 hi/lo planes for GEMM A-operands
__device__ uint16_t g_x0h[N0 * 128], g_x0l[N0 * 128];
__device__ uint16_t g_x1h[N1 * 256], g_x1l[N1 * 256];
__device__ uint16_t g_x2h[N2 * 64],  g_x2l[N2 * 64];
__device__ uint16_t g_h0h[N_NODES * 64],  g_h0l[N_NODES * 64];
__device__ uint16_t g_hAh[N_NODES * 256], g_hAl[N_NODES * 256];
__device__ uint16_t g_hBh[N_NODES * 256], g_hBl[N_NODES * 256];

// ------------------------------ helpers ------------------------------------
__device__ __forceinline__ uint32_t smem_u32(const void* p) {
    uint32_t a;
    asm("{ .reg .u64 t; cvta.to.shared.u64 t, %1; cvt.u32.u64 %0, t; }"
        : "=r"(a) : "l"(p));
    return a;
}

__device__ __forceinline__ void cp16(uint32_t dst, const void* src, int sz) {
    asm volatile("cp.async.cg.shared.global [%0], [%1], 16, %2;"
                 :: "r"(dst), "l"(src), "r"(sz) : "memory");
}
#define CP_COMMIT() asm volatile("cp.async.commit_group;" ::: "memory")
#define CP_WAIT1()  asm volatile("cp.async.wait_group 1;" ::: "memory")

__device__ __forceinline__ void mma_bf16(float* c, uint32_t a0, uint32_t a1,
                                         uint32_t a2, uint32_t a3,
                                         uint32_t b0, uint32_t b1) {
    asm volatile(
        "mma.sync.aligned.m16n8k16.row.col.f32.bf16.bf16.f32 "
        "{%0,%1,%2,%3}, {%4,%5,%6,%7}, {%8,%9}, {%0,%1,%2,%3};"
        : "+f"(c[0]), "+f"(c[1]), "+f"(c[2]), "+f"(c[3])
        : "r"(a0), "r"(a1), "r"(a2), "r"(a3), "r"(b0), "r"(b1));
}

__device__ __forceinline__ uint16_t bf_bits(__nv_bfloat16 h) {
    uint16_t b;
    memcpy(&b, &h, 2);
    return b;
}

__device__ __forceinline__ void split_bf16(float v, uint16_t& hb, uint16_t& lb) {
    __nv_bfloat16 h = __float2bfloat16(v);
    float hf = __bfloat162float(h);
    __nv_bfloat16 l = __float2bfloat16(v - hf);
    hb = bf_bits(h);
    lb = bf_bits(l);
}

// ------------------------------ converts & weight prep ---------------------
__global__ void conv_x(const float* __restrict__ x0, const float* __restrict__ x1,
                       const float* __restrict__ x2) {
    const int S0 = N0 * 128, S1 = N1 * 256, S2 = N2 * 64;
    for (int i = blockIdx.x * blockDim.x + threadIdx.x; i < S0 + S1 + S2;
         i += gridDim.x * blockDim.x) {
        float v;
        uint16_t *ph, *pl;
        int j;
        if (i < S0)            { j = i;            v = x0[j]; ph = g_x0h; pl = g_x0l; }
        else if (i < S0 + S1)  { j = i - S0;       v = x1[j]; ph = g_x1h; pl = g_x1l; }
        else                   { j = i - S0 - S1;  v = x2[j]; ph = g_x2h; pl = g_x2l; }
        uint16_t hb, lb;
        split_bf16(v, hb, lb);
        ph[j] = hb;
        pl[j] = lb;
    }
}

// all weights -> pair-packed [chunk][n][kpair] bf16 hi/lo images
__global__ void prep_all(const float* __restrict__ fcw0, const float* __restrict__ fcw1,
                         const float* __restrict__ fcw2, const float* __restrict__ W0,
                         const float* __restrict__ W1, const float* __restrict__ resW1,
                         const float* __restrict__ W2, const float* __restrict__ resW2) {
    int idx = blockIdx.x * blockDim.x + threadIdx.x;
    if (idx >= W_TOTAL) return;
    const float* src = nullptr;
    int N, base, rel;
    bool bcat = false;
    if (idx < 8192)        { src = fcw0;  N = 64;  base = OFF_FCW0; rel = idx; }
    else if (idx < 24576)  { src = fcw1;  N = 64;  base = OFF_FCW1; rel = idx - 8192; }
    else if (idx < 28672)  { src = fcw2;  N = 64;  base = OFF_FCW2; rel = idx - 24576; }
    else if (idx < 45056)  { src = W0;    N = 256; base = OFF_W0;   rel = idx - 28672; }
    else if (idx < 110592) { src = W1;    N = 256; base = OFF_W1;   rel = idx - 45056; }
    else if (idx < 176128) { src = resW1; N = 256; base = OFF_RW1;  rel = idx - 110592; }
    else                   { N = 32; base = OFF_BCAT; rel = idx - 176128; bcat = true; }
    int k = rel / N, n = rel - k * N;
    float v;
    if (bcat) v = (n < 16) ? W2[k * 16 + n] : resW2[k * 16 + (n - 16)];
    else v = src[rel];
    uint16_t hb, lb;
    split_bf16(v, hb, lb);
    int c = k >> 5, kp = (k & 31) >> 1;
    size_t word = (size_t)c * (N * 16) + (size_t)n * 16 + kp;
    g_wh[base + word * 2 + (k & 1)] = hb;
    g_wl[base + word * 2 + (k & 1)] = lb;
}

// ------------------------------ GEMM body (cp.async + mma) -----------------
// C[M,Ntot] = A @ B (3-term bf16 split). BM=128, BN=NT*32, BK=32.
// 512 threads = 16 warps (4M x 4N), warp tile 32 x (NT*8).
// A: bf16 hi/lo planes, row-major [M,K]. B: pair-packed chunk images.
// PLANES: add bias, emit bf16 hi/lo planes; else plain fp32 C.
template <int NT, bool PLANES>
__device__ __forceinline__ void gemm_body(
    const uint16_t* __restrict__ AhG, const uint16_t* __restrict__ AlG,
    const uint16_t* __restrict__ BhG, const uint16_t* __restrict__ BlG,
    const float* __restrict__ bias, float* __restrict__ C,
    uint16_t* __restrict__ Ch, uint16_t* __restrict__ Cl,
    int M, int Ntot, int K, int row0, int col0, char* smem) {
    constexpr int BN = NT * 32;
    constexpr int PAD = 20;
    constexpr int A_PLANE = 128 * PAD * 4;
    constexpr int B_PLANE = BN * PAD * 4;
    constexpr int OFF_AL2 = A_PLANE;
    constexpr int OFF_BH2 = 2 * A_PLANE;
    constexpr int OFF_BL2 = 2 * A_PLANE + B_PLANE;
    constexpr int STAGE = 2 * A_PLANE + 2 * B_PLANE;

    uint32_t sb = smem_u32(smem);
    int tid = threadIdx.x, wid = tid >> 5, lane = tid & 31;
    int g = lane >> 2, tig = lane & 3;
    int warpM = wid & 3, warpN = wid >> 2;

    float acc[2][NT][4];
    #pragma unroll
    for (int mt = 0; mt < 2; mt++)
        #pragma unroll
        for (int nt = 0; nt < NT; nt++)
            #pragma unroll
            for (int j = 0; j < 4; j++) acc[mt][nt][j] = 0.f;

    auto load_stage = [&](int s, int kt) {
        uint32_t base = sb + s * STAGE;
        {   // A: 128 rows x 32 k-elems (64B/row = 4x16B), hi + lo
            int r = tid >> 2, c4 = tid & 3;
            int gr = row0 + r;
            int sz = (gr < M) ? 16 : 0;
            size_t boff = ((size_t)gr * K + kt * 32) * 2 + c4 * 16;
            cp16(base + (r * PAD + c4 * 4) * 4, (const char*)AhG + boff, sz);
            cp16(base + OFF_AL2 + (r * PAD + c4 * 4) * 4, (const char*)AlG + boff, sz);
        }
        {   // B: BN cols x 16 pair-words (64B/col = 4x16B), hi + lo
            #pragma unroll
            for (int lin = tid; lin < BN * 4; lin += 512) {
                int n = lin >> 2, c4 = lin & 3;
                size_t boff = ((size_t)kt * Ntot * 16 + (size_t)(col0 + n) * 16) * 4 + c4 * 16;
                cp16(base + OFF_BH2 + (n * PAD + c4 * 4) * 4, (const char*)BhG + boff, 16);
                cp16(base + OFF_BL2 + (n * PAD + c4 * 4) * 4, (const char*)BlG + boff, 16);
            }
        }
    };

    int nk = K >> 5;
    load_stage(0, 0);
    CP_COMMIT();
    load_stage(1, 1);
    CP_COMMIT();

    for (int kt = 0; kt < nk; kt++) {
        CP_WAIT1();
        __syncthreads();
        int s = kt & 1;
        const uint32_t* AsH = (const uint32_t*)(smem + s * STAGE);
        const uint32_t* AsL = (const uint32_t*)(smem + s * STAGE + OFF_AL2);
        const uint32_t* BsH = (const uint32_t*)(smem + s * STAGE + OFF_BH2);
        const uint32_t* BsL = (const uint32_t*)(smem + s * STAGE + OFF_BL2);

        #pragma unroll
        for (int kh = 0; kh < 2; kh++) {
            int kp0 = kh * 8;
            uint32_t aH[2][4], aL[2][4];
            #pragma unroll
            for (int mt = 0; mt < 2; mt++) {
                int m0 = warpM * 32 + mt * 16;
                int base = (m0 + g) * PAD + kp0 + tig;
                aH[mt][0] = AsH[base];
                aH[mt][1] = AsH[base + 8 * PAD];
                aH[mt][2] = AsH[base + 4];
                aH[mt][3] = AsH[base + 8 * PAD + 4];
                aL[mt][0] = AsL[base];
                aL[mt][1] = AsL[base + 8 * PAD];
                aL[mt][2] = AsL[base + 4];
                aL[mt][3] = AsL[base + 8 * PAD + 4];
            }
            #pragma unroll
            for (int nt = 0; nt < NT; nt++) {
                int n0 = warpN * (NT * 8) + nt * 8;
                int bbase = (n0 + g) * PAD + kp0 + tig;
                uint32_t bh0 = BsH[bbase], bh1 = BsH[bbase + 4];
                uint32_t bl0 = BsL[bbase], bl1 = BsL[bbase + 4];
                #pragma unroll
                for (int mt = 0; mt < 2; mt++) {
                    mma_bf16(acc[mt][nt], aH[mt][0], aH[mt][1], aH[mt][2], aH[mt][3], bh0, bh1);
                    mma_bf16(acc[mt][nt], aL[mt][0], aL[mt][1], aL[mt][2], aL[mt][3], bh0, bh1);
                    mma_bf16(acc[mt][nt], aH[mt][0], aH[mt][1], aH[mt][2], aH[mt][3], bl0, bl1);
                }
            }
        }
        __syncthreads();
        if (kt + 2 < nk) load_stage(s, kt + 2);
        CP_COMMIT();
    }

    // epilogue
    #pragma unroll
    for (int mt = 0; mt < 2; mt++) {
        #pragma unroll
        for (int nt = 0; nt < NT; nt++) {
            int r0 = row0 + warpM * 32 + mt * 16 + g;
            int c = col0 + warpN * (NT * 8) + nt * 8 + tig * 2;
            #pragma unroll
            for (int half = 0; half < 2; half++) {
                int r = r0 + half * 8;
                if (r >= M) continue;
                float v0 = acc[mt][nt][half * 2 + 0];
                float v1 = acc[mt][nt][half * 2 + 1];
                if (PLANES) {
                    v0 += bias[c];
                    v1 += bias[c + 1];
                    uint16_t h0b, l0b, h1b, l1b;
                    split_bf16(v0, h0b, l0b);
                    split_bf16(v1, h1b, l1b);
                    Ch[(size_t)r * Ntot + c] = h0b;
                    Cl[(size_t)r * Ntot + c] = l0b;
                    Ch[(size_t)r * Ntot + c + 1] = h1b;
                    Cl[(size_t)r * Ntot + c + 1] = l1b;
                } else {
                    C[(size_t)r * Ntot + c] = v0;
                    C[(size_t)r * Ntot + c + 1] = v1;
                }
            }
        }
    }
}

template <int NT, bool PLANES>
__global__ void __launch_bounds__(512) gemm_cp(
    const uint16_t* __restrict__ AhG, const uint16_t* __restrict__ AlG,
    const uint16_t* __restrict__ BhG, const uint16_t* __restrict__ BlG,
    const float* __restrict__ bias, float* __restrict__ C,
    uint16_t* __restrict__ Ch, uint16_t* __restrict__ Cl,
    int M, int Ntot, int K) {
    extern __shared__ char smem[];
    gemm_body<NT, PLANES>(AhG, AlG, BhG, BlG, bias, C, Ch, Cl,
                          M, Ntot, K, blockIdx.y * 128, blockIdx.x * NT * 32, smem);
}

// combined input-projection GEMM: 3 segments in one launch (N=64 each)
__global__ void __launch_bounds__(512) proj_cp(const float* __restrict__ fcb0,
                                               const float* __restrict__ fcb1,
                                               const float* __restrict__ fcb2) {
    extern __shared__ char smem[];
    const int NB0 = (N0 + 127) / 128;              // 157
    const int NB01 = NB0 + (N1 + 127) / 128;       // 157+133=290
    int by = blockIdx.y;
    if (by < NB0) {
        gemm_body<2, true>(g_x0h, g_x0l, g_wh + OFF_FCW0, g_wl + OFF_FCW0, fcb0,
                           nullptr, g_h0h, g_h0l, N0, 64, 128, by * 128, 0, smem);
    } else if (by < NB01) {
        gemm_body<2, true>(g_x1h, g_x1l, g_wh + OFF_FCW1, g_wl + OFF_FCW1, fcb1,
                           nullptr, g_h0h + (size_t)N0 * 64, g_h0l + (size_t)N0 * 64,
                           N1, 64, 256, (by - NB0) * 128, 0, smem);
    } else {
        gemm_body<2, true>(g_x2h, g_x2l, g_wh + OFF_FCW2, g_wl + OFF_FCW2, fcb2,
                           nullptr, g_h0h + (size_t)(N0 + N1) * 64,
                           g_h0l + (size_t)(N0 + N1) * 64,
                           N2, 64, 64, (by - NB01) * 128, 0, smem);
    }
}

// ------------------------------ CSR build ----------------------------------
__global__ void hist_kernel(const int* __restrict__ dst) {
    int e = blockIdx.x * blockDim.x + threadIdx.x;
    if (e < N_EDGES) atomicAdd(&g_cnt[dst[e]], 1);
}

__global__ void scan_block_kernel() {
    __shared__ int sh[SCAN_B];
    int t = threadIdx.x;
    int i = blockIdx.x * SCAN_B + t;
    int v = (i < N_NODES) ? g_cnt[i] : 0;
    sh[t] = v;
    __syncthreads();
    #pragma unroll
    for (int off = 1; off < SCAN_B; off <<= 1) {
        int tmp = (t >= off) ? sh[t - off] : 0;
        __syncthreads();
        sh[t] += tmp;
        __syncthreads();
    }
    if (i < N_NODES) g_rowptr[i + 1] = sh[t];
    if (t == SCAN_B - 1) g_bsum[blockIdx.x] = sh[t];
}

__global__ void scan_top_kernel() {
    __shared__ int sh[128];
    int t = threadIdx.x;
    int v = (t < SCAN_NB) ? g_bsum[t] : 0;
    sh[t] = v;
    __syncthreads();
    #pragma unroll
    for (int off = 1; off < 128; off <<= 1) {
        int tmp = (t >= off) ? sh[t - off] : 0;
        __syncthreads();
        sh[t] += tmp;
        __syncthreads();
    }
    if (t < SCAN_NB) g_boff[t] = sh[t] - v;
}

__global__ void scan_add_kernel() {
    int t = threadIdx.x;
    int i = blockIdx.x * SCAN_B + t;
    if (i < N_NODES) {
        int v = g_rowptr[i + 1] + g_boff[blockIdx.x];
        g_rowptr[i + 1] = v;
        g_cursor[i] = v - g_cnt[i];
    }
    if (i == 0) g_rowptr[0] = 0;
}

__global__ void scatter_kernel(const int* __restrict__ src, const int* __restrict__ dst,
                               const int* __restrict__ et) {
    int e = blockIdx.x * blockDim.x + threadIdx.x;
    if (e >= N_EDGES) return;
    int d = dst[e];
    int pos = atomicAdd(&g_cursor[d], 1);
    g_srcS[pos] = src[e];
    g_dstS[pos] = d;
    g_etS[pos]  = et[e];
}

// ------------------------------ edge-type attention ------------------------
__global__ void etype_att_kernel(const float* __restrict__ eemb, const float* __restrict__ We,
                                 const float* __restrict__ ae, float* __restrict__ out, int H) {
    int t = blockIdx.x / H;
    int h = blockIdx.x % H;
    int d = threadIdx.x;
    int Wcols = H * 64;
    float v = 0.f;
    #pragma unroll 4
    for (int k = 0; k < 64; k++)
        v += eemb[t * 64 + k] * We[k * Wcols + h * 64 + d];
    v *= ae[h * 64 + d];
    __shared__ float sh[64];
    sh[d] = v;
    __syncthreads();
    #pragma unroll
    for (int o = 32; o > 0; o >>= 1) {
        if (d < o) sh[d] += sh[d + o];
        __syncthreads();
    }
    if (d == 0) out[t * H + h] = sh[0];
}

// ------------------------------ per-node el/er -----------------------------
template <int H, int OUT, int STRIDE>
__global__ void node_attn_kernel(const float* __restrict__ feat, const float* __restrict__ al,
                                 const float* __restrict__ ar, float* __restrict__ el,
                                 float* __restrict__ er) {
    int warp = (blockIdx.x * blockDim.x + threadIdx.x) >> 5;
    int lane = threadIdx.x & 31;
    if (warp >= N_NODES) return;
    const float* f = feat + (size_t)warp * STRIDE;
    #pragma unroll
    for (int h = 0; h < H; h++) {
        float v = 0.f, w = 0.f;
        if (lane < OUT) {
            float x = f[h * OUT + lane];
            v = x * al[h * OUT + lane];
            w = x * ar[h * OUT + lane];
        }
        #pragma unroll
        for (int o = 16; o > 0; o >>= 1) {
            v += __shfl_down_sync(0xffffffffu, v, o);
            w += __shfl_down_sync(0xffffffffu, w, o);
        }
        if (lane == 0) {
            el[warp * H + h] = v;
            er[warp * H + h] = w;
        }
    }
}

// ------------------------------ fused GAT edge kernel (H=8) ----------------
// warp per dst: online softmax + (blend/save) + aggregate + residual + ELU;
// output written as bf16 hi/lo planes (consumed only by next GEMM).
template <bool BLEND, bool SAVE_A, bool RES>
__global__ void fused_gat8(const float* __restrict__ feat, const float* __restrict__ el,
                           const float* __restrict__ er, const float* __restrict__ etatt,
                           const float* __restrict__ res, float* __restrict__ a0,
                           uint16_t* __restrict__ outh, uint16_t* __restrict__ outl) {
    int warp = (blockIdx.x * blockDim.x + threadIdx.x) >> 5;
    int lane = threadIdx.x & 31;
    if (warp >= N_NODES) return;
    int n = warp;
    int h = lane & 7, eslot = lane >> 3;
    float er_n = er[n * 8 + h];
    float eat[6];
    #pragma unroll
    for (int t = 0; t < 6; t++) eat[t] = etatt[t * 8 + h];
    int b = g_rowptr[n], e = g_rowptr[n + 1];

    float m = -1e30f, s = 0.f;
    for (int i0 = b; i0 < e; i0 += 4) {
        int i = i0 + eslot;
        if (i < e) {
            float ev = el[g_srcS[i] * 8 + h] + er_n + eat[g_etS[i]];
            ev = (ev > 0.f) ? ev : 0.2f * ev;
            float nm = fmaxf(m, ev);
            s = s * __expf(m - nm) + __expf(ev - nm);
            m = nm;
        }
    }
    #pragma unroll
    for (int off = 8; off <= 16; off <<= 1) {
        float om = __shfl_xor_sync(0xffffffffu, m, off);
        float os = __shfl_xor_sync(0xffffffffu, s, off);
        float nm = fmaxf(m, om);
        s = s * __expf(m - nm) + os * __expf(om - nm);
        m = nm;
    }

    float acc[8];
    #pragma unroll
    for (int h2 = 0; h2 < 8; h2++)
        acc[h2] = RES ? res[(size_t)n * 256 + h2 * 32 + lane] : 0.f;

    for (int i0 = b; i0 < e; i0 += 4) {
        int i = i0 + eslot;
        float a = 0.f;
        int sidx = 0;
        if (i < e) {
            sidx = g_srcS[i];
            float ev = el[sidx * 8 + h] + er_n + eat[g_etS[i]];
            ev = (ev > 0.f) ? ev : 0.2f * ev;
            a = __expf(ev - m) / s;
            if (BLEND) a = a * 0.95f + 0.05f * a0[(size_t)i * 8 + h];
            if (SAVE_A) a0[(size_t)i * 8 + h] = a;
        }
        #pragma unroll
        for (int e2 = 0; e2 < 4; e2++) {
            if (i0 + e2 < e) {
                int s2 = __shfl_sync(0xffffffffu, sidx, e2 * 8);
                const float* f = feat + (size_t)s2 * 256;
                #pragma unroll
                for (int h2 = 0; h2 < 8; h2++) {
                    float ah = __shfl_sync(0xffffffffu, a, e2 * 8 + h2);
                    acc[h2] += ah * f[h2 * 32 + lane];
                }
            }
        }
    }
    #pragma unroll
    for (int h2 = 0; h2 < 8; h2++) {
        float v = acc[h2];
        v = (v > 0.f) ? v : expm1f(v);       // ELU (both layers activate)
        uint16_t hb, lb;
        split_bf16(v, hb, lb);
        outh[(size_t)n * 256 + h2 * 32 + lane] = hb;
        outl[(size_t)n * 256 + h2 * 32 + lane] = lb;
    }
}

// ------------------------------ fused GAT edge kernel (H=1, out 16) --------
__global__ void fused_gat1(const float* __restrict__ f2, const float* __restrict__ el,
                           const float* __restrict__ er, const float* __restrict__ etatt,
                           float* __restrict__ out) {
    int warp = (blockIdx.x * blockDim.x + threadIdx.x) >> 5;
    int lane = threadIdx.x & 31;
    if (warp >= N_NODES) return;
    int n = warp;
    float er_n = er[n];
    float eat[6];
    #pragma unroll
    for (int t = 0; t < 6; t++) eat[t] = etatt[t];
    int b = g_rowptr[n], e = g_rowptr[n + 1];

    float m = -1e30f, s = 0.f;
    for (int i0 = b; i0 < e; i0 += 32) {
        int i = i0 + lane;
        if (i < e) {
            float ev = el[g_srcS[i]] + er_n + eat[g_etS[i]];
            ev = (ev > 0.f) ? ev : 0.2f * ev;
            float nm = fmaxf(m, ev);
            s = s * __expf(m - nm) + __expf(ev - nm);
            m = nm;
        }
    }
    #pragma unroll
    for (int off = 16; off > 0; off >>= 1) {
        float om = __shfl_xor_sync(0xffffffffu, m, off);
        float os = __shfl_xor_sync(0xffffffffu, s, off);
        float nm = fmaxf(m, om);
        s = s * __expf(m - nm) + os * __expf(om - nm);
        m = nm;
    }

    float acc = 0.f;
    if (lane < 16) acc = f2[(size_t)n * 32 + 16 + lane];
    for (int i = b; i < e; i++) {
        int s2 = g_srcS[i];
        float ev = el[s2] + er_n + eat[g_etS[i]];
        ev = (ev > 0.f) ? ev : 0.2f * ev;
        float a = __expf(ev - m) / s;
        if (lane < 16) acc += a * f2[(size_t)s2 * 32 + lane];
    }
    if (lane < 16) out[(size_t)n * 16 + lane] = acc;
}

// ---------------------------------------------------------------------------
static inline int cdiv(int a, int b) { return (a + b - 1) / b; }
static inline int stage_bytes(int NT) { return 2 * (128 * 20 * 4) + 2 * (NT * 32 * 20 * 4); }

extern "C" void kernel_launch(void* const* d_in, const int* in_sizes, int n_in,
                              void* d_out, int out_size) {
    const float* x0    = (const float*)d_in[0];
    const float* x1    = (const float*)d_in[1];
    const float* x2    = (const float*)d_in[2];
    const float* fcw0  = (const float*)d_in[3];
    const float* fcb0  = (const float*)d_in[4];
    const float* fcw1  = (const float*)d_in[5];
    const float* fcb1  = (const float*)d_in[6];
    const float* fcw2  = (const float*)d_in[7];
    const float* fcb2  = (const float*)d_in[8];
    const float* W0    = (const float*)d_in[9];
    const float* We0   = (const float*)d_in[10];
    const float* eemb0 = (const float*)d_in[11];
    const float* al0   = (const float*)d_in[12];
    const float* ar0   = (const float*)d_in[13];
    const float* ae0   = (const float*)d_in[14];
    const float* W1    = (const float*)d_in[15];
    const float* We1   = (const float*)d_in[16];
    const float* eemb1 = (const float*)d_in[17];
    const float* al1   = (const float*)d_in[18];
    const float* ar1   = (const float*)d_in[19];
    const float* ae1   = (const float*)d_in[20];
    const float* resW1 = (const float*)d_in[21];
    const float* W2    = (const float*)d_in[22];
    const float* We2   = (const float*)d_in[23];
    const float* eemb2 = (const float*)d_in[24];
    const float* al2   = (const float*)d_in[25];
    const float* ar2   = (const float*)d_in[26];
    const float* ae2   = (const float*)d_in[27];
    const float* resW2 = (const float*)d_in[28];
    const int*   src   = (const int*)d_in[29];
    const int*   dst   = (const int*)d_in[30];
    const int*   etype = (const int*)d_in[31];
    float* out = (float*)d_out;

    float *p_feat, *p_res, *p_f2, *p_a0, *p_el, *p_er, *p_etatt;
    uint16_t *p_wh, *p_wl, *p_h0h, *p_h0l, *p_hAh, *p_hAl, *p_hBh, *p_hBl;
    int* p_cnt;
    cudaGetSymbolAddress((void**)&p_cnt, g_cnt);
    cudaGetSymbolAddress((void**)&p_feat, g_feat);
    cudaGetSymbolAddress((void**)&p_res, g_res);
    cudaGetSymbolAddress((void**)&p_f2, g_f2);
    cudaGetSymbolAddress((void**)&p_a0, g_a0);
    cudaGetSymbolAddress((void**)&p_el, g_el);
    cudaGetSymbolAddress((void**)&p_er, g_er);
    cudaGetSymbolAddress((void**)&p_etatt, g_etatt);
    cudaGetSymbolAddress((void**)&p_wh, g_wh);
    cudaGetSymbolAddress((void**)&p_wl, g_wl);
    cudaGetSymbolAddress((void**)&p_h0h, g_h0h);
    cudaGetSymbolAddress((void**)&p_h0l, g_h0l);
    cudaGetSymbolAddress((void**)&p_hAh, g_hAh);
    cudaGetSymbolAddress((void**)&p_hAl, g_hAl);
    cudaGetSymbolAddress((void**)&p_hBh, g_hBh);
    cudaGetSymbolAddress((void**)&p_hBl, g_hBl);

    cudaFuncSetAttribute(gemm_cp<8, false>, cudaFuncAttributeMaxDynamicSharedMemorySize,
                         2 * stage_bytes(8));
    cudaFuncSetAttribute(gemm_cp<1, false>, cudaFuncAttributeMaxDynamicSharedMemorySize,
                         2 * stage_bytes(1));
    cudaFuncSetAttribute(proj_cp, cudaFuncAttributeMaxDynamicSharedMemorySize,
                         2 * stage_bytes(2));

    const int WB = cdiv(N_NODES * 32, 256);
    const int GY = cdiv(N_NODES, 128);      // 391
    const int PROJ_BLKS = cdiv(N0, 128) + cdiv(N1, 128) + cdiv(N2, 128);  // 392

    // 1 memset, 2 conv_x, 3 prep_all, 4 proj, 5 layer-0 GEMM (profiled slot)
    cudaMemsetAsync(p_cnt, 0, N_NODES * sizeof(int));
    conv_x<<<2048, 256>>>(x0, x1, x2);
    prep_all<<<cdiv(W_TOTAL, 256), 256>>>(fcw0, fcw1, fcw2, W0, W1, resW1, W2, resW2);
    proj_cp<<<dim3(1, PROJ_BLKS), 512, 2 * stage_bytes(2)>>>(fcb0, fcb1, fcb2);
    gemm_cp<8, false><<<dim3(1, GY), 512, 2 * stage_bytes(8)>>>(
        p_h0h, p_h0l, p_wh + OFF_W0, p_wl + OFF_W0, nullptr, p_feat, nullptr, nullptr,
        N_NODES, 256, 64);

    // CSR build
    hist_kernel<<<cdiv(N_EDGES, 256), 256>>>(dst);
    scan_block_kernel<<<SCAN_NB, SCAN_B>>>();
    scan_top_kernel<<<1, 128>>>();
    scan_add_kernel<<<SCAN_NB, SCAN_B>>>();
    scatter_kernel<<<cdiv(N_EDGES, 256), 256>>>(src, dst, etype);

    // tiny preps
    etype_att_kernel<<<6 * 8, 64>>>(eemb0, We0, ae0, p_etatt + 0, 8);
    etype_att_kernel<<<6 * 8, 64>>>(eemb1, We1, ae1, p_etatt + 48, 8);
    etype_att_kernel<<<6 * 1, 64>>>(eemb2, We2, ae2, p_etatt + 96, 1);

    // ---- layer 0 ----
    node_attn_kernel<8, 32, 256><<<WB, 256>>>(p_feat, al0, ar0, p_el, p_er);
    fused_gat8<false, true, false><<<WB, 256>>>(p_feat, p_el, p_er, p_etatt + 0,
                                                nullptr, p_a0, p_hAh, p_hAl);

    // ---- layer 1 ----
    gemm_cp<8, false><<<dim3(1, GY), 512, 2 * stage_bytes(8)>>>(
        p_hAh, p_hAl, p_wh + OFF_W1, p_wl + OFF_W1, nullptr, p_feat, nullptr, nullptr,
        N_NODES, 256, 256);
    gemm_cp<8, false><<<dim3(1, GY), 512, 2 * stage_bytes(8)>>>(
        p_hAh, p_hAl, p_wh + OFF_RW1, p_wl + OFF_RW1, nullptr, p_res, nullptr, nullptr,
        N_NODES, 256, 256);
    node_attn_kernel<8, 32, 256><<<WB, 256>>>(p_feat, al1, ar1, p_el, p_er);
    fused_gat8<true, false, true><<<WB, 256>>>(p_feat, p_el, p_er, p_etatt + 48,
                                               p_res, p_a0, p_hBh, p_hBl);

    // ---- layer 2 ----
    gemm_cp<1, false><<<dim3(1, GY), 512, 2 * stage_bytes(1)>>>(
        p_hBh, p_hBl, p_wh + OFF_BCAT, p_wl + OFF_BCAT, nullptr, p_f2, nullptr, nullptr,
        N_NODES, 32, 256);
    node_attn_kernel<1, 16, 32><<<WB, 256>>>(p_f2, al2, ar2, p_el, p_er);
    fused_gat1<<<WB, 256>>>(p_f2, p_el, p_er, p_etatt + 96, out);
}

// round 8
// speedup vs baseline: 1.8010x; 1.0580x over previous
#include <cuda_runtime.h>
#include <cuda_bf16.h>
#include <math.h>
#include <stdint.h>
#include <string.h>

// ---------------------------------------------------------------------------
// SimpleHGN forward, round 8:
//  - GEMM mainloop: cp.async double-buffer + ldmatrix.x4 fragments (4x fewer
//    shared-pipe issues) + mma.sync m16n8k16, 3-term bf16 hi/lo split
//  - layer-1 W1/resW1 fused into one [256,512] GEMM -> g_fr[N,512] feat|res
//  - producers emit bf16 planes; all operands pre-converted once
// ---------------------------------------------------------------------------

#define N_NODES 50000
#define N_EDGES 800000
#define N0 20000
#define N1 17000
#define N2 13000
#define SCAN_B 512
#define SCAN_NB ((N_NODES + SCAN_B - 1) / SCAN_B)

// weight scratch offsets (bf16 elements, pair-packed layout)
#define OFF_FCW0 0
#define OFF_FCW1 8192
#define OFF_FCW2 24576
#define OFF_W0   28672
#define OFF_W1C  45056          // W1|resW1 concat: 256x512
#define OFF_BCAT 176128
#define W_TOTAL  184320

// ------------------------------ scratch ------------------------------------
__device__ int   g_cnt[N_NODES];
__device__ int   g_rowptr[N_NODES + 1];
__device__ int   g_cursor[N_NODES];
__device__ int   g_bsum[SCAN_NB];
__device__ int   g_boff[SCAN_NB];
__device__ int   g_srcS[N_EDGES];
__device__ int   g_dstS[N_EDGES];
__device__ int   g_etS[N_EDGES];

__device__ float g_fr[(size_t)N_NODES * 512];   // feat (0..255) | res (256..511)
__device__ float g_f2[N_NODES * 32];
__device__ float g_a0[N_EDGES * 8];
__device__ float g_el[N_NODES * 8];
__device__ float g_er[N_NODES * 8];
__device__ float g_etatt[3 * 6 * 8];
__device__ uint16_t g_wh[W_TOTAL];
__device__ uint16_t g_wl[W_TOTAL];

__device__ uint16_t g_x0h[N0 * 128], g_x0l[N0 * 128];
__device__ uint16_t g_x1h[N1 * 256], g_x1l[N1 * 256];
__device__ uint16_t g_x2h[N2 * 64],  g_x2l[N2 * 64];
__device__ uint16_t g_h0h[N_NODES * 64],  g_h0l[N_NODES * 64];
__device__ uint16_t g_hAh[N_NODES * 256], g_hAl[N_NODES * 256];
__device__ uint16_t g_hBh[N_NODES * 256], g_hBl[N_NODES * 256];

// ------------------------------ helpers ------------------------------------
__device__ __forceinline__ uint32_t smem_u32(const void* p) {
    uint32_t a;
    asm("{ .reg .u64 t; cvta.to.shared.u64 t, %1; cvt.u32.u64 %0, t; }"
        : "=r"(a) : "l"(p));
    return a;
}

__device__ __forceinline__ void cp16(uint32_t dst, const void* src, int sz) {
    asm volatile("cp.async.cg.shared.global [%0], [%1], 16, %2;"
                 :: "r"(dst), "l"(src), "r"(sz) : "memory");
}
#define CP_COMMIT() asm volatile("cp.async.commit_group;" ::: "memory")
#define CP_WAIT1()  asm volatile("cp.async.wait_group 1;" ::: "memory")

#define LDSM_X4(r, addr) \
    asm volatile("ldmatrix.sync.aligned.m8n8.x4.shared.b16 {%0,%1,%2,%3}, [%4];" \
                 : "=r"((r)[0]), "=r"((r)[1]), "=r"((r)[2]), "=r"((r)[3]) \
                 : "r"(addr))

__device__ __forceinline__ void mma_bf16(float* c, uint32_t a0, uint32_t a1,
                                         uint32_t a2, uint32_t a3,
                                         uint32_t b0, uint32_t b1) {
    asm volatile(
        "mma.sync.aligned.m16n8k16.row.col.f32.bf16.bf16.f32 "
        "{%0,%1,%2,%3}, {%4,%5,%6,%7}, {%8,%9}, {%0,%1,%2,%3};"
        : "+f"(c[0]), "+f"(c[1]), "+f"(c[2]), "+f"(c[3])
        : "r"(a0), "r"(a1), "r"(a2), "r"(a3), "r"(b0), "r"(b1));
}

__device__ __forceinline__ uint16_t bf_bits(__nv_bfloat16 h) {
    uint16_t b;
    memcpy(&b, &h, 2);
    return b;
}

__device__ __forceinline__ void split_bf16(float v, uint16_t& hb, uint16_t& lb) {
    __nv_bfloat16 h = __float2bfloat16(v);
    float hf = __bfloat162float(h);
    __nv_bfloat16 l = __float2bfloat16(v - hf);
    hb = bf_bits(h);
    lb = bf_bits(l);
}

// ------------------------------ converts & weight prep ---------------------
__global__ void conv_x(const float* __restrict__ x0, const float* __restrict__ x1,
                       const float* __restrict__ x2) {
    const int S0 = N0 * 128, S1 = N1 * 256, S2 = N2 * 64;
    for (int i = blockIdx.x * blockDim.x + threadIdx.x; i < S0 + S1 + S2;
         i += gridDim.x * blockDim.x) {
        float v;
        uint16_t *ph, *pl;
        int j;
        if (i < S0)            { j = i;            v = x0[j]; ph = g_x0h; pl = g_x0l; }
        else if (i < S0 + S1)  { j = i - S0;       v = x1[j]; ph = g_x1h; pl = g_x1l; }
        else                   { j = i - S0 - S1;  v = x2[j]; ph = g_x2h; pl = g_x2l; }
        uint16_t hb, lb;
        split_bf16(v, hb, lb);
        ph[j] = hb;
        pl[j] = lb;
    }
}

// all weights -> pair-packed [chunk][n][kpair] bf16 hi/lo images
__global__ void prep_all(const float* __restrict__ fcw0, const float* __restrict__ fcw1,
                         const float* __restrict__ fcw2, const float* __restrict__ W0,
                         const float* __restrict__ W1, const float* __restrict__ resW1,
                         const float* __restrict__ W2, const float* __restrict__ resW2) {
    int idx = blockIdx.x * blockDim.x + threadIdx.x;
    if (idx >= W_TOTAL) return;
    int N, base, rel;
    int mode = 0;   // 0 plain, 1 = W1cat, 2 = bcat
    const float* src = nullptr;
    if (idx < 8192)        { src = fcw0; N = 64;  base = OFF_FCW0; rel = idx; }
    else if (idx < 24576)  { src = fcw1; N = 64;  base = OFF_FCW1; rel = idx - 8192; }
    else if (idx < 28672)  { src = fcw2; N = 64;  base = OFF_FCW2; rel = idx - 24576; }
    else if (idx < 45056)  { src = W0;   N = 256; base = OFF_W0;   rel = idx - 28672; }
    else if (idx < 176128) { N = 512; base = OFF_W1C;  rel = idx - 45056; mode = 1; }
    else                   { N = 32;  base = OFF_BCAT; rel = idx - 176128; mode = 2; }
    int k = rel / N, n = rel - k * N;
    float v;
    if (mode == 1)      v = (n < 256) ? W1[k * 256 + n] : resW1[k * 256 + (n - 256)];
    else if (mode == 2) v = (n < 16) ? W2[k * 16 + n] : resW2[k * 16 + (n - 16)];
    else                v = src[rel];
    uint16_t hb, lb;
    split_bf16(v, hb, lb);
    int c = k >> 5, kp = (k & 31) >> 1;
    size_t word = (size_t)c * (N * 16) + (size_t)n * 16 + kp;
    g_wh[base + word * 2 + (k & 1)] = hb;
    g_wl[base + word * 2 + (k & 1)] = lb;
}

// ------------------------------ GEMM body (cp.async + ldmatrix + mma) ------
// C[M, ldc] (cols [col0, col0+BN)) = A[M,K] @ B-image[K,Ntot].
// BM=128, BN=NT*32, BK=32. 512 threads = 16 warps (4M x 4N).
template <int NT, bool PLANES>
__device__ __forceinline__ void gemm_body(
    const uint16_t* __restrict__ AhG, const uint16_t* __restrict__ AlG,
    const uint16_t* __restrict__ BhG, const uint16_t* __restrict__ BlG,
    const float* __restrict__ bias, float* __restrict__ C,
    uint16_t* __restrict__ Ch, uint16_t* __restrict__ Cl,
    int M, int Ntot, int K, int ldc, int row0, int col0, char* smem) {
    constexpr int BN = NT * 32;
    constexpr int PAD = 20;
    constexpr int A_PLANE = 128 * PAD * 4;
    constexpr int B_PLANE = BN * PAD * 4;
    constexpr int OFF_AL2 = A_PLANE;
    constexpr int OFF_BH2 = 2 * A_PLANE;
    constexpr int OFF_BL2 = 2 * A_PLANE + B_PLANE;
    constexpr int STAGE = 2 * A_PLANE + 2 * B_PLANE;

    uint32_t sb = smem_u32(smem);
    int tid = threadIdx.x, wid = tid >> 5, lane = tid & 31;
    int g = lane >> 2, tig = lane & 3;
    int warpM = wid & 3, warpN = wid >> 2;

    float acc[2][NT][4];
    #pragma unroll
    for (int mt = 0; mt < 2; mt++)
        #pragma unroll
        for (int nt = 0; nt < NT; nt++)
            #pragma unroll
            for (int j = 0; j < 4; j++) acc[mt][nt][j] = 0.f;

    auto load_stage = [&](int s, int kt) {
        uint32_t base = sb + s * STAGE;
        {   // A: 128 rows x 32 k (64B/row = 4x16B), hi + lo
            int r = tid >> 2, c4 = tid & 3;
            int gr = row0 + r;
            int sz = (gr < M) ? 16 : 0;
            size_t boff = ((size_t)gr * K + kt * 32) * 2 + c4 * 16;
            cp16(base + (r * PAD + c4 * 4) * 4, (const char*)AhG + boff, sz);
            cp16(base + OFF_AL2 + (r * PAD + c4 * 4) * 4, (const char*)AlG + boff, sz);
        }
        {   // B: BN cols x 16 pair-words (64B/col = 4x16B), hi + lo
            #pragma unroll
            for (int lin = tid; lin < BN * 4; lin += 512) {
                int n = lin >> 2, c4 = lin & 3;
                size_t boff = ((size_t)kt * Ntot * 16 + (size_t)(col0 + n) * 16) * 4 + c4 * 16;
                cp16(base + OFF_BH2 + (n * PAD + c4 * 4) * 4, (const char*)BhG + boff, 16);
                cp16(base + OFF_BL2 + (n * PAD + c4 * 4) * 4, (const char*)BlG + boff, 16);
            }
        }
    };

    // per-lane ldmatrix base byte-offsets within a plane
    uint32_t a_base = (uint32_t)((warpM * 32 + (lane & 15)) * PAD +
                                 ((lane & 16) ? 4 : 0)) * 4;
    uint32_t b_base = (uint32_t)((warpN * (NT * 8) + (lane & 7) +
                                  ((lane & 16) ? 8 : 0)) * PAD +
                                 ((lane & 8) ? 4 : 0)) * 4;

    int nk = K >> 5;
    load_stage(0, 0);
    CP_COMMIT();
    load_stage(1, 1);
    CP_COMMIT();

    for (int kt = 0; kt < nk; kt++) {
        CP_WAIT1();
        __syncthreads();
        int s = kt & 1;
        uint32_t sA  = sb + s * STAGE;
        uint32_t sAl = sA + OFF_AL2;
        uint32_t sBh = sA + OFF_BH2;
        uint32_t sBl = sA + OFF_BL2;

        #pragma unroll
        for (int kh = 0; kh < 2; kh++) {
            uint32_t ko = kh * 32;
            uint32_t aH[2][4], aL[2][4];
            #pragma unroll
            for (int mt = 0; mt < 2; mt++) {
                LDSM_X4(aH[mt], sA + a_base + mt * 16 * PAD * 4 + ko);
                LDSM_X4(aL[mt], sAl + a_base + mt * 16 * PAD * 4 + ko);
            }
            if (NT >= 2) {
                #pragma unroll
                for (int nt2 = 0; nt2 < NT / 2; nt2++) {
                    uint32_t bh[4], bl[4];
                    LDSM_X4(bh, sBh + b_base + nt2 * 16 * PAD * 4 + ko);
                    LDSM_X4(bl, sBl + b_base + nt2 * 16 * PAD * 4 + ko);
                    #pragma unroll
                    for (int half = 0; half < 2; half++) {
                        int nt = nt2 * 2 + half;
                        uint32_t bh0 = bh[half * 2], bh1 = bh[half * 2 + 1];
                        uint32_t bl0 = bl[half * 2], bl1 = bl[half * 2 + 1];
                        #pragma unroll
                        for (int mt = 0; mt < 2; mt++) {
                            mma_bf16(acc[mt][nt], aH[mt][0], aH[mt][1], aH[mt][2], aH[mt][3], bh0, bh1);
                            mma_bf16(acc[mt][nt], aL[mt][0], aL[mt][1], aL[mt][2], aL[mt][3], bh0, bh1);
                            mma_bf16(acc[mt][nt], aH[mt][0], aH[mt][1], aH[mt][2], aH[mt][3], bl0, bl1);
                        }
                    }
                }
            } else {
                // NT==1: scalar fragment loads (tiny kernel)
                const uint32_t* BsH = (const uint32_t*)(smem + s * STAGE + OFF_BH2);
                const uint32_t* BsL = (const uint32_t*)(smem + s * STAGE + OFF_BL2);
                int kp0 = kh * 8;
                int n0 = warpN * 8;
                int bbase = (n0 + g) * PAD + kp0 + tig;
                uint32_t bh0 = BsH[bbase], bh1 = BsH[bbase + 4];
                uint32_t bl0 = BsL[bbase], bl1 = BsL[bbase + 4];
                #pragma unroll
                for (int mt = 0; mt < 2; mt++) {
                    mma_bf16(acc[mt][0], aH[mt][0], aH[mt][1], aH[mt][2], aH[mt][3], bh0, bh1);
                    mma_bf16(acc[mt][0], aL[mt][0], aL[mt][1], aL[mt][2], aL[mt][3], bh0, bh1);
                    mma_bf16(acc[mt][0], aH[mt][0], aH[mt][1], aH[mt][2], aH[mt][3], bl0, bl1);
                }
            }
        }
        __syncthreads();
        if (kt + 2 < nk) load_stage(s, kt + 2);
        CP_COMMIT();
    }

    // epilogue
    #pragma unroll
    for (int mt = 0; mt < 2; mt++) {
        #pragma unroll
        for (int nt = 0; nt < NT; nt++) {
            int r0 = row0 + warpM * 32 + mt * 16 + g;
            int c = col0 + warpN * (NT * 8) + nt * 8 + tig * 2;
            #pragma unroll
            for (int half = 0; half < 2; half++) {
                int r = r0 + half * 8;
                if (r >= M) continue;
                float v0 = acc[mt][nt][half * 2 + 0];
                float v1 = acc[mt][nt][half * 2 + 1];
                if (PLANES) {
                    v0 += bias[c];
                    v1 += bias[c + 1];
                    uint16_t h0b, l0b, h1b, l1b;
                    split_bf16(v0, h0b, l0b);
                    split_bf16(v1, h1b, l1b);
                    *(uint32_t*)&Ch[(size_t)r * ldc + c] =
                        (uint32_t)h0b | ((uint32_t)h1b << 16);
                    *(uint32_t*)&Cl[(size_t)r * ldc + c] =
                        (uint32_t)l0b | ((uint32_t)l1b << 16);
                } else {
                    *(float2*)&C[(size_t)r * ldc + c] = make_float2(v0, v1);
                }
            }
        }
    }
}

template <int NT, bool PLANES>
__global__ void __launch_bounds__(512) gemm_cp(
    const uint16_t* __restrict__ AhG, const uint16_t* __restrict__ AlG,
    const uint16_t* __restrict__ BhG, const uint16_t* __restrict__ BlG,
    const float* __restrict__ bias, float* __restrict__ C,
    uint16_t* __restrict__ Ch, uint16_t* __restrict__ Cl,
    int M, int Ntot, int K, int ldc) {
    extern __shared__ char smem[];
    gemm_body<NT, PLANES>(AhG, AlG, BhG, BlG, bias, C, Ch, Cl,
                          M, Ntot, K, ldc, blockIdx.y * 128, blockIdx.x * NT * 32, smem);
}

// combined input-projection GEMM: 3 segments in one launch (N=64 each)
__global__ void __launch_bounds__(512) proj_cp(const float* __restrict__ fcb0,
                                               const float* __restrict__ fcb1,
                                               const float* __restrict__ fcb2) {
    extern __shared__ char smem[];
    const int NB0 = (N0 + 127) / 128;
    const int NB01 = NB0 + (N1 + 127) / 128;
    int by = blockIdx.y;
    if (by < NB0) {
        gemm_body<2, true>(g_x0h, g_x0l, g_wh + OFF_FCW0, g_wl + OFF_FCW0, fcb0,
                           nullptr, g_h0h, g_h0l, N0, 64, 128, 64, by * 128, 0, smem);
    } else if (by < NB01) {
        gemm_body<2, true>(g_x1h, g_x1l, g_wh + OFF_FCW1, g_wl + OFF_FCW1, fcb1,
                           nullptr, g_h0h + (size_t)N0 * 64, g_h0l + (size_t)N0 * 64,
                           N1, 64, 256, 64, (by - NB0) * 128, 0, smem);
    } else {
        gemm_body<2, true>(g_x2h, g_x2l, g_wh + OFF_FCW2, g_wl + OFF_FCW2, fcb2,
                           nullptr, g_h0h + (size_t)(N0 + N1) * 64,
                           g_h0l + (size_t)(N0 + N1) * 64,
                           N2, 64, 64, 64, (by - NB01) * 128, 0, smem);
    }
}

// ------------------------------ CSR build ----------------------------------
__global__ void hist_kernel(const int* __restrict__ dst) {
    int e = blockIdx.x * blockDim.x + threadIdx.x;
    if (e < N_EDGES) atomicAdd(&g_cnt[dst[e]], 1);
}

__global__ void scan_block_kernel() {
    __shared__ int sh[SCAN_B];
    int t = threadIdx.x;
    int i = blockIdx.x * SCAN_B + t;
    int v = (i < N_NODES) ? g_cnt[i] : 0;
    sh[t] = v;
    __syncthreads();
    #pragma unroll
    for (int off = 1; off < SCAN_B; off <<= 1) {
        int tmp = (t >= off) ? sh[t - off] : 0;
        __syncthreads();
        sh[t] += tmp;
        __syncthreads();
    }
    if (i < N_NODES) g_rowptr[i + 1] = sh[t];
    if (t == SCAN_B - 1) g_bsum[blockIdx.x] = sh[t];
}

__global__ void scan_top_kernel() {
    __shared__ int sh[128];
    int t = threadIdx.x;
    int v = (t < SCAN_NB) ? g_bsum[t] : 0;
    sh[t] = v;
    __syncthreads();
    #pragma unroll
    for (int off = 1; off < 128; off <<= 1) {
        int tmp = (t >= off) ? sh[t - off] : 0;
        __syncthreads();
        sh[t] += tmp;
        __syncthreads();
    }
    if (t < SCAN_NB) g_boff[t] = sh[t] - v;
}

__global__ void scan_add_kernel() {
    int t = threadIdx.x;
    int i = blockIdx.x * SCAN_B + t;
    if (i < N_NODES) {
        int v = g_rowptr[i + 1] + g_boff[blockIdx.x];
        g_rowptr[i + 1] = v;
        g_cursor[i] = v - g_cnt[i];
    }
    if (i == 0) g_rowptr[0] = 0;
}

__global__ void scatter_kernel(const int* __restrict__ src, const int* __restrict__ dst,
                               const int* __restrict__ et) {
    int e = blockIdx.x * blockDim.x + threadIdx.x;
    if (e >= N_EDGES) return;
    int d = dst[e];
    int pos = atomicAdd(&g_cursor[d], 1);
    g_srcS[pos] = src[e];
    g_dstS[pos] = d;
    g_etS[pos]  = et[e];
}

// ------------------------------ edge-type attention ------------------------
__global__ void etype_att_kernel(const float* __restrict__ eemb, const float* __restrict__ We,
                                 const float* __restrict__ ae, float* __restrict__ out, int H) {
    int t = blockIdx.x / H;
    int h = blockIdx.x % H;
    int d = threadIdx.x;
    int Wcols = H * 64;
    float v = 0.f;
    #pragma unroll 4
    for (int k = 0; k < 64; k++)
        v += eemb[t * 64 + k] * We[k * Wcols + h * 64 + d];
    v *= ae[h * 64 + d];
    __shared__ float sh[64];
    sh[d] = v;
    __syncthreads();
    #pragma unroll
    for (int o = 32; o > 0; o >>= 1) {
        if (d < o) sh[d] += sh[d + o];
        __syncthreads();
    }
    if (d == 0) out[t * H + h] = sh[0];
}

// ------------------------------ per-node el/er -----------------------------
template <int H, int OUT, int STRIDE>
__global__ void node_attn_kernel(const float* __restrict__ feat, const float* __restrict__ al,
                                 const float* __restrict__ ar, float* __restrict__ el,
                                 float* __restrict__ er) {
    int warp = (blockIdx.x * blockDim.x + threadIdx.x) >> 5;
    int lane = threadIdx.x & 31;
    if (warp >= N_NODES) return;
    const float* f = feat + (size_t)warp * STRIDE;
    #pragma unroll
    for (int h = 0; h < H; h++) {
        float v = 0.f, w = 0.f;
        if (lane < OUT) {
            float x = f[h * OUT + lane];
            v = x * al[h * OUT + lane];
            w = x * ar[h * OUT + lane];
        }
        #pragma unroll
        for (int o = 16; o > 0; o >>= 1) {
            v += __shfl_down_sync(0xffffffffu, v, o);
            w += __shfl_down_sync(0xffffffffu, w, o);
        }
        if (lane == 0) {
            el[warp * H + h] = v;
            er[warp * H + h] = w;
        }
    }
}

// ------------------------------ fused GAT edge kernel (H=8, feat stride 512)
template <bool BLEND, bool SAVE_A, bool RES>
__global__ void fused_gat8(const float* __restrict__ feat, const float* __restrict__ el,
                           const float* __restrict__ er, const float* __restrict__ etatt,
                           float* __restrict__ a0,
                           uint16_t* __restrict__ outh, uint16_t* __restrict__ outl) {
    int warp = (blockIdx.x * blockDim.x + threadIdx.x) >> 5;
    int lane = threadIdx.x & 31;
    if (warp >= N_NODES) return;
    int n = warp;
    int h = lane & 7, eslot = lane >> 3;
    float er_n = er[n * 8 + h];
    float eat[6];
    #pragma unroll
    for (int t = 0; t < 6; t++) eat[t] = etatt[t * 8 + h];
    int b = g_rowptr[n], e = g_rowptr[n + 1];

    float m = -1e30f, s = 0.f;
    for (int i0 = b; i0 < e; i0 += 4) {
        int i = i0 + eslot;
        if (i < e) {
            float ev = el[g_srcS[i] * 8 + h] + er_n + eat[g_etS[i]];
            ev = (ev > 0.f) ? ev : 0.2f * ev;
            float nm = fmaxf(m, ev);
            s = s * __expf(m - nm) + __expf(ev - nm);
            m = nm;
        }
    }
    #pragma unroll
    for (int off = 8; off <= 16; off <<= 1) {
        float om = __shfl_xor_sync(0xffffffffu, m, off);
        float os = __shfl_xor_sync(0xffffffffu, s, off);
        float nm = fmaxf(m, om);
        s = s * __expf(m - nm) + os * __expf(om - nm);
        m = nm;
    }

    float acc[8];
    #pragma unroll
    for (int h2 = 0; h2 < 8; h2++)
        acc[h2] = RES ? feat[(size_t)n * 512 + 256 + h2 * 32 + lane] : 0.f;

    for (int i0 = b; i0 < e; i0 += 4) {
        int i = i0 + eslot;
        float a = 0.f;
        int sidx = 0;
        if (i < e) {
            sidx = g_srcS[i];
            float ev = el[sidx * 8 + h] + er_n + eat[g_etS[i]];
            ev = (ev > 0.f) ? ev : 0.2f * ev;
            a = __expf(ev - m) / s;
            if (BLEND) a = a * 0.95f + 0.05f * a0[(size_t)i * 8 + h];
            if (SAVE_A) a0[(size_t)i * 8 + h] = a;
        }
        #pragma unroll
        for (int e2 = 0; e2 < 4; e2++) {
            if (i0 + e2 < e) {
                int s2 = __shfl_sync(0xffffffffu, sidx, e2 * 8);
                const float* f = feat + (size_t)s2 * 512;
                #pragma unroll
                for (int h2 = 0; h2 < 8; h2++) {
                    float ah = __shfl_sync(0xffffffffu, a, e2 * 8 + h2);
                    acc[h2] += ah * f[h2 * 32 + lane];
                }
            }
        }
    }
    #pragma unroll
    for (int h2 = 0; h2 < 8; h2++) {
        float v = acc[h2];
        v = (v > 0.f) ? v : expm1f(v);       // ELU
        uint16_t hb, lb;
        split_bf16(v, hb, lb);
        outh[(size_t)n * 256 + h2 * 32 + lane] = hb;
        outl[(size_t)n * 256 + h2 * 32 + lane] = lb;
    }
}

// ------------------------------ fused GAT edge kernel (H=1, out 16) --------
__global__ void fused_gat1(const float* __restrict__ f2, const float* __restrict__ el,
                           const float* __restrict__ er, const float* __restrict__ etatt,
                           float* __restrict__ out) {
    int warp = (blockIdx.x * blockDim.x + threadIdx.x) >> 5;
    int lane = threadIdx.x & 31;
    if (warp >= N_NODES) return;
    int n = warp;
    float er_n = er[n];
    float eat[6];
    #pragma unroll
    for (int t = 0; t < 6; t++) eat[t] = etatt[t];
    int b = g_rowptr[n], e = g_rowptr[n + 1];

    float m = -1e30f, s = 0.f;
    for (int i0 = b; i0 < e; i0 += 32) {
        int i = i0 + lane;
        if (i < e) {
            float ev = el[g_srcS[i]] + er_n + eat[g_etS[i]];
            ev = (ev > 0.f) ? ev : 0.2f * ev;
            float nm = fmaxf(m, ev);
            s = s * __expf(m - nm) + __expf(ev - nm);
            m = nm;
        }
    }
    #pragma unroll
    for (int off = 16; off > 0; off >>= 1) {
        float om = __shfl_xor_sync(0xffffffffu, m, off);
        float os = __shfl_xor_sync(0xffffffffu, s, off);
        float nm = fmaxf(m, om);
        s = s * __expf(m - nm) + os * __expf(om - nm);
        m = nm;
    }

    float acc = 0.f;
    if (lane < 16) acc = f2[(size_t)n * 32 + 16 + lane];
    for (int i = b; i < e; i++) {
        int s2 = g_srcS[i];
        float ev = el[s2] + er_n + eat[g_etS[i]];
        ev = (ev > 0.f) ? ev : 0.2f * ev;
        float a = __expf(ev - m) / s;
        if (lane < 16) acc += a * f2[(size_t)s2 * 32 + lane];
    }
    if (lane < 16) out[(size_t)n * 16 + lane] = acc;
}

// ---------------------------------------------------------------------------
static inline int cdiv(int a, int b) { return (a + b - 1) / b; }
static inline int stage_bytes(int NT) { return 2 * (128 * 20 * 4) + 2 * (NT * 32 * 20 * 4); }

extern "C" void kernel_launch(void* const* d_in, const int* in_sizes, int n_in,
                              void* d_out, int out_size) {
    const float* x0    = (const float*)d_in[0];
    const float* x1    = (const float*)d_in[1];
    const float* x2    = (const float*)d_in[2];
    const float* fcw0  = (const float*)d_in[3];
    const float* fcb0  = (const float*)d_in[4];
    const float* fcw1  = (const float*)d_in[5];
    const float* fcb1  = (const float*)d_in[6];
    const float* fcw2  = (const float*)d_in[7];
    const float* fcb2  = (const float*)d_in[8];
    const float* W0    = (const float*)d_in[9];
    const float* We0   = (const float*)d_in[10];
    const float* eemb0 = (const float*)d_in[11];
    const float* al0   = (const float*)d_in[12];
    const float* ar0   = (const float*)d_in[13];
    const float* ae0   = (const float*)d_in[14];
    const float* W1    = (const float*)d_in[15];
    const float* We1   = (const float*)d_in[16];
    const float* eemb1 = (const float*)d_in[17];
    const float* al1   = (const float*)d_in[18];
    const float* ar1   = (const float*)d_in[19];
    const float* ae1   = (const float*)d_in[20];
    const float* resW1 = (const float*)d_in[21];
    const float* W2    = (const float*)d_in[22];
    const float* We2   = (const float*)d_in[23];
    const float* eemb2 = (const float*)d_in[24];
    const float* al2   = (const float*)d_in[25];
    const float* ar2   = (const float*)d_in[26];
    const float* ae2   = (const float*)d_in[27];
    const float* resW2 = (const float*)d_in[28];
    const int*   src   = (const int*)d_in[29];
    const int*   dst   = (const int*)d_in[30];
    const int*   etype = (const int*)d_in[31];
    float* out = (float*)d_out;

    float *p_fr, *p_f2, *p_a0, *p_el, *p_er, *p_etatt;
    uint16_t *p_wh, *p_wl, *p_h0h, *p_h0l, *p_hAh, *p_hAl, *p_hBh, *p_hBl;
    int* p_cnt;
    cudaGetSymbolAddress((void**)&p_cnt, g_cnt);
    cudaGetSymbolAddress((void**)&p_fr, g_fr);
    cudaGetSymbolAddress((void**)&p_f2, g_f2);
    cudaGetSymbolAddress((void**)&p_a0, g_a0);
    cudaGetSymbolAddress((void**)&p_el, g_el);
    cudaGetSymbolAddress((void**)&p_er, g_er);
    cudaGetSymbolAddress((void**)&p_etatt, g_etatt);
    cudaGetSymbolAddress((void**)&p_wh, g_wh);
    cudaGetSymbolAddress((void**)&p_wl, g_wl);
    cudaGetSymbolAddress((void**)&p_h0h, g_h0h);
    cudaGetSymbolAddress((void**)&p_h0l, g_h0l);
    cudaGetSymbolAddress((void**)&p_hAh, g_hAh);
    cudaGetSymbolAddress((void**)&p_hAl, g_hAl);
    cudaGetSymbolAddress((void**)&p_hBh, g_hBh);
    cudaGetSymbolAddress((void**)&p_hBl, g_hBl);

    cudaFuncSetAttribute(gemm_cp<8, false>, cudaFuncAttributeMaxDynamicSharedMemorySize,
                         2 * stage_bytes(8));
    cudaFuncSetAttribute(gemm_cp<1, false>, cudaFuncAttributeMaxDynamicSharedMemorySize,
                         2 * stage_bytes(1));
    cudaFuncSetAttribute(proj_cp, cudaFuncAttributeMaxDynamicSharedMemorySize,
                         2 * stage_bytes(2));

    const int WB = cdiv(N_NODES * 32, 256);
    const int GY = cdiv(N_NODES, 128);
    const int PROJ_BLKS = cdiv(N0, 128) + cdiv(N1, 128) + cdiv(N2, 128);

    // 1 memset, 2 conv_x, 3 prep_all, 4 proj, 5 layer-0 GEMM (profiled slot)
    cudaMemsetAsync(p_cnt, 0, N_NODES * sizeof(int));
    conv_x<<<2048, 256>>>(x0, x1, x2);
    prep_all<<<cdiv(W_TOTAL, 256), 256>>>(fcw0, fcw1, fcw2, W0, W1, resW1, W2, resW2);
    proj_cp<<<dim3(1, PROJ_BLKS), 512, 2 * stage_bytes(2)>>>(fcb0, fcb1, fcb2);
    gemm_cp<8, false><<<dim3(1, GY), 512, 2 * stage_bytes(8)>>>(
        p_h0h, p_h0l, p_wh + OFF_W0, p_wl + OFF_W0, nullptr, p_fr, nullptr, nullptr,
        N_NODES, 256, 64, 512);

    // CSR build
    hist_kernel<<<cdiv(N_EDGES, 256), 256>>>(dst);
    scan_block_kernel<<<SCAN_NB, SCAN_B>>>();
    scan_top_kernel<<<1, 128>>>();
    scan_add_kernel<<<SCAN_NB, SCAN_B>>>();
    scatter_kernel<<<cdiv(N_EDGES, 256), 256>>>(src, dst, etype);

    // tiny preps
    etype_att_kernel<<<6 * 8, 64>>>(eemb0, We0, ae0, p_etatt + 0, 8);
    etype_att_kernel<<<6 * 8, 64>>>(eemb1, We1, ae1, p_etatt + 48, 8);
    etype_att_kernel<<<6 * 1, 64>>>(eemb2, We2, ae2, p_etatt + 96, 1);

    // ---- layer 0 ----
    node_attn_kernel<8, 32, 512><<<WB, 256>>>(p_fr, al0, ar0, p_el, p_er);
    fused_gat8<false, true, false><<<WB, 256>>>(p_fr, p_el, p_er, p_etatt + 0,
                                                p_a0, p_hAh, p_hAl);

    // ---- layer 1 (fused W1|resW1 -> g_fr[N,512]) ----
    gemm_cp<8, false><<<dim3(2, GY), 512, 2 * stage_bytes(8)>>>(
        p_hAh, p_hAl, p_wh + OFF_W1C, p_wl + OFF_W1C, nullptr, p_fr, nullptr, nullptr,
        N_NODES, 512, 256, 512);
    node_attn_kernel<8, 32, 512><<<WB, 256>>>(p_fr, al1, ar1, p_el, p_er);
    fused_gat8<true, false, true><<<WB, 256>>>(p_fr, p_el, p_er, p_etatt + 48,
                                               p_a0, p_hBh, p_hBl);

    // ---- layer 2 ----
    gemm_cp<1, false><<<dim3(1, GY), 512, 2 * stage_bytes(1)>>>(
        p_hBh, p_hBl, p_wh + OFF_BCAT, p_wl + OFF_BCAT, nullptr, p_f2, nullptr, nullptr,
        N_NODES, 32, 256, 32);
    node_attn_kernel<1, 16, 32><<<WB, 256>>>(p_f2, al2, ar2, p_el, p_er);
    fused_gat1<<<WB, 256>>>(p_f2, p_el, p_er, p_etatt + 96, out);
}

// round 9
// speedup vs baseline: 2.0223x; 1.1229x over previous
#include <cuda_runtime.h>
#include <cuda_bf16.h>
#include <math.h>
#include <stdint.h>
#include <string.h>

// ---------------------------------------------------------------------------
// SimpleHGN forward, round 9:
//  - fused_gat8: branch-free quad fast-path, 32 front-batched feat loads
//  - el/er computed in GEMM epilogue (atomics), node_attn<8> removed
//  - 3-stage cp.async pipeline, single __syncthreads per k-iter
// ---------------------------------------------------------------------------

#define N_NODES 50000
#define N_EDGES 800000
#define N0 20000
#define N1 17000
#define N2 13000
#define SCAN_B 512
#define SCAN_NB ((N_NODES + SCAN_B - 1) / SCAN_B)

#define OFF_FCW0 0
#define OFF_FCW1 8192
#define OFF_FCW2 24576
#define OFF_W0   28672
#define OFF_W1C  45056
#define OFF_BCAT 176128
#define W_TOTAL  184320

// ------------------------------ scratch ------------------------------------
__device__ int   g_cnt[N_NODES];
__device__ int   g_rowptr[N_NODES + 1];
__device__ int   g_cursor[N_NODES];
__device__ int   g_bsum[SCAN_NB];
__device__ int   g_boff[SCAN_NB];
__device__ int   g_srcS[N_EDGES];
__device__ int   g_dstS[N_EDGES];
__device__ int   g_etS[N_EDGES];

__device__ float g_fr[(size_t)N_NODES * 512];
__device__ float g_f2[N_NODES * 32];
__device__ float g_a0[N_EDGES * 8];
__device__ float g_el[N_NODES * 8];
__device__ float g_er[N_NODES * 8];
__device__ float g_etatt[3 * 6 * 8];
__device__ uint16_t g_wh[W_TOTAL];
__device__ uint16_t g_wl[W_TOTAL];

__device__ uint16_t g_x0h[N0 * 128], g_x0l[N0 * 128];
__device__ uint16_t g_x1h[N1 * 256], g_x1l[N1 * 256];
__device__ uint16_t g_x2h[N2 * 64],  g_x2l[N2 * 64];
__device__ uint16_t g_h0h[N_NODES * 64],  g_h0l[N_NODES * 64];
__device__ uint16_t g_hAh[N_NODES * 256], g_hAl[N_NODES * 256];
__device__ uint16_t g_hBh[N_NODES * 256], g_hBl[N_NODES * 256];

// ------------------------------ helpers ------------------------------------
__device__ __forceinline__ uint32_t smem_u32(const void* p) {
    uint32_t a;
    asm("{ .reg .u64 t; cvta.to.shared.u64 t, %1; cvt.u32.u64 %0, t; }"
        : "=r"(a) : "l"(p));
    return a;
}

__device__ __forceinline__ void cp16(uint32_t dst, const void* src, int sz) {
    asm volatile("cp.async.cg.shared.global [%0], [%1], 16, %2;"
                 :: "r"(dst), "l"(src), "r"(sz) : "memory");
}
#define CP_COMMIT() asm volatile("cp.async.commit_group;" ::: "memory")
#define CP_WAIT1()  asm volatile("cp.async.wait_group 1;" ::: "memory")

#define LDSM_X4(r, addr) \
    asm volatile("ldmatrix.sync.aligned.m8n8.x4.shared.b16 {%0,%1,%2,%3}, [%4];" \
                 : "=r"((r)[0]), "=r"((r)[1]), "=r"((r)[2]), "=r"((r)[3]) \
                 : "r"(addr))

__device__ __forceinline__ void mma_bf16(float* c, uint32_t a0, uint32_t a1,
                                         uint32_t a2, uint32_t a3,
                                         uint32_t b0, uint32_t b1) {
    asm volatile(
        "mma.sync.aligned.m16n8k16.row.col.f32.bf16.bf16.f32 "
        "{%0,%1,%2,%3}, {%4,%5,%6,%7}, {%8,%9}, {%0,%1,%2,%3};"
        : "+f"(c[0]), "+f"(c[1]), "+f"(c[2]), "+f"(c[3])
        : "r"(a0), "r"(a1), "r"(a2), "r"(a3), "r"(b0), "r"(b1));
}

__device__ __forceinline__ uint16_t bf_bits(__nv_bfloat16 h) {
    uint16_t b;
    memcpy(&b, &h, 2);
    return b;
}

__device__ __forceinline__ void split_bf16(float v, uint16_t& hb, uint16_t& lb) {
    __nv_bfloat16 h = __float2bfloat16(v);
    float hf = __bfloat162float(h);
    __nv_bfloat16 l = __float2bfloat16(v - hf);
    hb = bf_bits(h);
    lb = bf_bits(l);
}

// ------------------------------ converts & weight prep ---------------------
__global__ void conv_x(const float* __restrict__ x0, const float* __restrict__ x1,
                       const float* __restrict__ x2) {
    const int S0 = N0 * 128, S1 = N1 * 256, S2 = N2 * 64;
    for (int i = blockIdx.x * blockDim.x + threadIdx.x; i < S0 + S1 + S2;
         i += gridDim.x * blockDim.x) {
        float v;
        uint16_t *ph, *pl;
        int j;
        if (i < S0)            { j = i;            v = x0[j]; ph = g_x0h; pl = g_x0l; }
        else if (i < S0 + S1)  { j = i - S0;       v = x1[j]; ph = g_x1h; pl = g_x1l; }
        else                   { j = i - S0 - S1;  v = x2[j]; ph = g_x2h; pl = g_x2l; }
        uint16_t hb, lb;
        split_bf16(v, hb, lb);
        ph[j] = hb;
        pl[j] = lb;
    }
}

__global__ void prep_all(const float* __restrict__ fcw0, const float* __restrict__ fcw1,
                         const float* __restrict__ fcw2, const float* __restrict__ W0,
                         const float* __restrict__ W1, const float* __restrict__ resW1,
                         const float* __restrict__ W2, const float* __restrict__ resW2) {
    int idx = blockIdx.x * blockDim.x + threadIdx.x;
    if (idx >= W_TOTAL) return;
    int N, base, rel;
    int mode = 0;
    const float* src = nullptr;
    if (idx < 8192)        { src = fcw0; N = 64;  base = OFF_FCW0; rel = idx; }
    else if (idx < 24576)  { src = fcw1; N = 64;  base = OFF_FCW1; rel = idx - 8192; }
    else if (idx < 28672)  { src = fcw2; N = 64;  base = OFF_FCW2; rel = idx - 24576; }
    else if (idx < 45056)  { src = W0;   N = 256; base = OFF_W0;   rel = idx - 28672; }
    else if (idx < 176128) { N = 512; base = OFF_W1C;  rel = idx - 45056; mode = 1; }
    else                   { N = 32;  base = OFF_BCAT; rel = idx - 176128; mode = 2; }
    int k = rel / N, n = rel - k * N;
    float v;
    if (mode == 1)      v = (n < 256) ? W1[k * 256 + n] : resW1[k * 256 + (n - 256)];
    else if (mode == 2) v = (n < 16) ? W2[k * 16 + n] : resW2[k * 16 + (n - 16)];
    else                v = src[rel];
    uint16_t hb, lb;
    split_bf16(v, hb, lb);
    int c = k >> 5, kp = (k & 31) >> 1;
    size_t word = (size_t)c * (N * 16) + (size_t)n * 16 + kp;
    g_wh[base + word * 2 + (k & 1)] = hb;
    g_wl[base + word * 2 + (k & 1)] = lb;
}

// ------------------------------ GEMM body ----------------------------------
// 3-stage cp.async + ldmatrix + mma, bf16 3-term split.
// EL: epilogue computes el/er partials vs al/ar and atomically accumulates.
template <int NT, bool PLANES, bool EL>
__device__ __forceinline__ void gemm_body(
    const uint16_t* __restrict__ AhG, const uint16_t* __restrict__ AlG,
    const uint16_t* __restrict__ BhG, const uint16_t* __restrict__ BlG,
    const float* __restrict__ bias, float* __restrict__ C,
    uint16_t* __restrict__ Ch, uint16_t* __restrict__ Cl,
    const float* __restrict__ al, const float* __restrict__ ar,
    float* __restrict__ elp, float* __restrict__ erp,
    int M, int Ntot, int K, int ldc, int row0, int col0, char* smem) {
    constexpr int BN = NT * 32;
    constexpr int PAD = 20;
    constexpr int A_PLANE = 128 * PAD * 4;
    constexpr int B_PLANE = BN * PAD * 4;
    constexpr int OFF_AL2 = A_PLANE;
    constexpr int OFF_BH2 = 2 * A_PLANE;
    constexpr int OFF_BL2 = 2 * A_PLANE + B_PLANE;
    constexpr int STAGE = 2 * A_PLANE + 2 * B_PLANE;

    uint32_t sb = smem_u32(smem);
    int tid = threadIdx.x, wid = tid >> 5, lane = tid & 31;
    int g = lane >> 2, tig = lane & 3;
    int warpM = wid & 3, warpN = wid >> 2;

    float acc[2][NT][4];
    #pragma unroll
    for (int mt = 0; mt < 2; mt++)
        #pragma unroll
        for (int nt = 0; nt < NT; nt++)
            #pragma unroll
            for (int j = 0; j < 4; j++) acc[mt][nt][j] = 0.f;

    auto load_stage = [&](int s, int kt) {
        uint32_t base = sb + s * STAGE;
        {
            int r = tid >> 2, c4 = tid & 3;
            int gr = row0 + r;
            int sz = (gr < M) ? 16 : 0;
            size_t boff = ((size_t)gr * K + kt * 32) * 2 + c4 * 16;
            cp16(base + (r * PAD + c4 * 4) * 4, (const char*)AhG + boff, sz);
            cp16(base + OFF_AL2 + (r * PAD + c4 * 4) * 4, (const char*)AlG + boff, sz);
        }
        {
            #pragma unroll
            for (int lin = tid; lin < BN * 4; lin += 512) {
                int n = lin >> 2, c4 = lin & 3;
                size_t boff = ((size_t)kt * Ntot * 16 + (size_t)(col0 + n) * 16) * 4 + c4 * 16;
                cp16(base + OFF_BH2 + (n * PAD + c4 * 4) * 4, (const char*)BhG + boff, 16);
                cp16(base + OFF_BL2 + (n * PAD + c4 * 4) * 4, (const char*)BlG + boff, 16);
            }
        }
    };

    uint32_t a_base = (uint32_t)((warpM * 32 + (lane & 15)) * PAD +
                                 ((lane & 16) ? 4 : 0)) * 4;
    uint32_t b_base = (uint32_t)((warpN * (NT * 8) + (lane & 7) +
                                  ((lane & 16) ? 8 : 0)) * PAD +
                                 ((lane & 8) ? 4 : 0)) * 4;

    int nk = K >> 5;
    load_stage(0, 0);
    CP_COMMIT();
    load_stage(1, 1);
    CP_COMMIT();

    for (int kt = 0; kt < nk; kt++) {
        CP_WAIT1();
        __syncthreads();
        if (kt + 2 < nk) load_stage((kt + 2) % 3, kt + 2);
        CP_COMMIT();
        int s = kt % 3;
        uint32_t sA  = sb + s * STAGE;
        uint32_t sAl = sA + OFF_AL2;
        uint32_t sBh = sA + OFF_BH2;
        uint32_t sBl = sA + OFF_BL2;

        #pragma unroll
        for (int kh = 0; kh < 2; kh++) {
            uint32_t ko = kh * 32;
            uint32_t aH[2][4], aL[2][4];
            #pragma unroll
            for (int mt = 0; mt < 2; mt++) {
                LDSM_X4(aH[mt], sA + a_base + mt * 16 * PAD * 4 + ko);
                LDSM_X4(aL[mt], sAl + a_base + mt * 16 * PAD * 4 + ko);
            }
            if (NT >= 2) {
                #pragma unroll
                for (int nt2 = 0; nt2 < NT / 2; nt2++) {
                    uint32_t bh[4], bl[4];
                    LDSM_X4(bh, sBh + b_base + nt2 * 16 * PAD * 4 + ko);
                    LDSM_X4(bl, sBl + b_base + nt2 * 16 * PAD * 4 + ko);
                    #pragma unroll
                    for (int half = 0; half < 2; half++) {
                        int nt = nt2 * 2 + half;
                        uint32_t bh0 = bh[half * 2], bh1 = bh[half * 2 + 1];
                        uint32_t bl0 = bl[half * 2], bl1 = bl[half * 2 + 1];
                        #pragma unroll
                        for (int mt = 0; mt < 2; mt++) {
                            mma_bf16(acc[mt][nt], aH[mt][0], aH[mt][1], aH[mt][2], aH[mt][3], bh0, bh1);
                            mma_bf16(acc[mt][nt], aL[mt][0], aL[mt][1], aL[mt][2], aL[mt][3], bh0, bh1);
                            mma_bf16(acc[mt][nt], aH[mt][0], aH[mt][1], aH[mt][2], aH[mt][3], bl0, bl1);
                        }
                    }
                }
            } else {
                const uint32_t* BsH = (const uint32_t*)(smem + s * STAGE + OFF_BH2);
                const uint32_t* BsL = (const uint32_t*)(smem + s * STAGE + OFF_BL2);
                int kp0 = kh * 8;
                int n0 = warpN * 8;
                int bbase = (n0 + g) * PAD + kp0 + tig;
                uint32_t bh0 = BsH[bbase], bh1 = BsH[bbase + 4];
                uint32_t bl0 = BsL[bbase], bl1 = BsL[bbase + 4];
                #pragma unroll
                for (int mt = 0; mt < 2; mt++) {
                    mma_bf16(acc[mt][0], aH[mt][0], aH[mt][1], aH[mt][2], aH[mt][3], bh0, bh1);
                    mma_bf16(acc[mt][0], aL[mt][0], aL[mt][1], aL[mt][2], aL[mt][3], bh0, bh1);
                    mma_bf16(acc[mt][0], aH[mt][0], aH[mt][1], aH[mt][2], aH[mt][3], bl0, bl1);
                }
            }
        }
        __syncthreads();
    }

    // ---- store epilogue ----
    #pragma unroll
    for (int mt = 0; mt < 2; mt++) {
        #pragma unroll
        for (int nt = 0; nt < NT; nt++) {
            int r0 = row0 + warpM * 32 + mt * 16 + g;
            int c = col0 + warpN * (NT * 8) + nt * 8 + tig * 2;
            #pragma unroll
            for (int half = 0; half < 2; half++) {
                int r = r0 + half * 8;
                if (r >= M) continue;
                float v0 = acc[mt][nt][half * 2 + 0];
                float v1 = acc[mt][nt][half * 2 + 1];
                if (PLANES) {
                    v0 += bias[c];
                    v1 += bias[c + 1];
                    uint16_t h0b, l0b, h1b, l1b;
                    split_bf16(v0, h0b, l0b);
                    split_bf16(v1, h1b, l1b);
                    *(uint32_t*)&Ch[(size_t)r * ldc + c] =
                        (uint32_t)h0b | ((uint32_t)h1b << 16);
                    *(uint32_t*)&Cl[(size_t)r * ldc + c] =
                        (uint32_t)l0b | ((uint32_t)l1b << 16);
                } else {
                    *(float2*)&C[(size_t)r * ldc + c] = make_float2(v0, v1);
                }
            }
        }
    }

    // ---- el/er epilogue (feat cols only; our EL launches have feat at col0==0) ----
    if (EL && col0 == 0) {
        float elacc[2][2][2], eracc[2][2][2];
        #pragma unroll
        for (int mt = 0; mt < 2; mt++)
            #pragma unroll
            for (int half = 0; half < 2; half++)
                #pragma unroll
                for (int hl = 0; hl < 2; hl++) {
                    elacc[mt][half][hl] = 0.f;
                    eracc[mt][half][hl] = 0.f;
                }
        #pragma unroll
        for (int nt = 0; nt < NT; nt++) {
            int hl = nt >> 2;
            int h = (warpN * (NT * 8) + nt * 8) >> 5;
            int o = (nt * 8 + tig * 2) & 31;
            float al0v = al[h * 32 + o], al1v = al[h * 32 + o + 1];
            float ar0v = ar[h * 32 + o], ar1v = ar[h * 32 + o + 1];
            #pragma unroll
            for (int mt = 0; mt < 2; mt++)
                #pragma unroll
                for (int half = 0; half < 2; half++) {
                    float v0 = acc[mt][nt][half * 2 + 0];
                    float v1 = acc[mt][nt][half * 2 + 1];
                    elacc[mt][half][hl] += v0 * al0v + v1 * al1v;
                    eracc[mt][half][hl] += v0 * ar0v + v1 * ar1v;
                }
        }
        #pragma unroll
        for (int mt = 0; mt < 2; mt++)
            #pragma unroll
            for (int half = 0; half < 2; half++)
                #pragma unroll
                for (int hl = 0; hl < 2; hl++) {
                    float ev = elacc[mt][half][hl];
                    float rv = eracc[mt][half][hl];
                    ev += __shfl_xor_sync(0xffffffffu, ev, 1);
                    ev += __shfl_xor_sync(0xffffffffu, ev, 2);
                    rv += __shfl_xor_sync(0xffffffffu, rv, 1);
                    rv += __shfl_xor_sync(0xffffffffu, rv, 2);
                    if (tig == 0) {
                        int r = row0 + warpM * 32 + mt * 16 + g + half * 8;
                        int h2 = warpN * ((NT * 8) / 32) + hl;
                        if (r < M) {
                            atomicAdd(&elp[r * 8 + h2], ev);
                            atomicAdd(&erp[r * 8 + h2], rv);
                        }
                    }
                }
    }
}

template <int NT, bool PLANES, bool EL>
__global__ void __launch_bounds__(512) gemm_cp(
    const uint16_t* __restrict__ AhG, const uint16_t* __restrict__ AlG,
    const uint16_t* __restrict__ BhG, const uint16_t* __restrict__ BlG,
    const float* __restrict__ bias, float* __restrict__ C,
    uint16_t* __restrict__ Ch, uint16_t* __restrict__ Cl,
    const float* al, const float* ar, float* elp, float* erp,
    int M, int Ntot, int K, int ldc) {
    extern __shared__ char smem[];
    gemm_body<NT, PLANES, EL>(AhG, AlG, BhG, BlG, bias, C, Ch, Cl, al, ar, elp, erp,
                              M, Ntot, K, ldc, blockIdx.y * 128, blockIdx.x * NT * 32, smem);
}

__global__ void __launch_bounds__(512) proj_cp(const float* __restrict__ fcb0,
                                               const float* __restrict__ fcb1,
                                               const float* __restrict__ fcb2) {
    extern __shared__ char smem[];
    const int NB0 = (N0 + 127) / 128;
    const int NB01 = NB0 + (N1 + 127) / 128;
    int by = blockIdx.y;
    if (by < NB0) {
        gemm_body<2, true, false>(g_x0h, g_x0l, g_wh + OFF_FCW0, g_wl + OFF_FCW0, fcb0,
                                  nullptr, g_h0h, g_h0l, nullptr, nullptr, nullptr, nullptr,
                                  N0, 64, 128, 64, by * 128, 0, smem);
    } else if (by < NB01) {
        gemm_body<2, true, false>(g_x1h, g_x1l, g_wh + OFF_FCW1, g_wl + OFF_FCW1, fcb1,
                                  nullptr, g_h0h + (size_t)N0 * 64, g_h0l + (size_t)N0 * 64,
                                  nullptr, nullptr, nullptr, nullptr,
                                  N1, 64, 256, 64, (by - NB0) * 128, 0, smem);
    } else {
        gemm_body<2, true, false>(g_x2h, g_x2l, g_wh + OFF_FCW2, g_wl + OFF_FCW2, fcb2,
                                  nullptr, g_h0h + (size_t)(N0 + N1) * 64,
                                  g_h0l + (size_t)(N0 + N1) * 64,
                                  nullptr, nullptr, nullptr, nullptr,
                                  N2, 64, 64, 64, (by - NB01) * 128, 0, smem);
    }
}

// ------------------------------ CSR build ----------------------------------
__global__ void hist_kernel(const int* __restrict__ dst) {
    int e = blockIdx.x * blockDim.x + threadIdx.x;
    if (e < N_EDGES) atomicAdd(&g_cnt[dst[e]], 1);
}

__global__ void scan_block_kernel() {
    __shared__ int sh[SCAN_B];
    int t = threadIdx.x;
    int i = blockIdx.x * SCAN_B + t;
    int v = (i < N_NODES) ? g_cnt[i] : 0;
    sh[t] = v;
    __syncthreads();
    #pragma unroll
    for (int off = 1; off < SCAN_B; off <<= 1) {
        int tmp = (t >= off) ? sh[t - off] : 0;
        __syncthreads();
        sh[t] += tmp;
        __syncthreads();
    }
    if (i < N_NODES) g_rowptr[i + 1] = sh[t];
    if (t == SCAN_B - 1) g_bsum[blockIdx.x] = sh[t];
}

__global__ void scan_top_kernel() {
    __shared__ int sh[128];
    int t = threadIdx.x;
    int v = (t < SCAN_NB) ? g_bsum[t] : 0;
    sh[t] = v;
    __syncthreads();
    #pragma unroll
    for (int off = 1; off < 128; off <<= 1) {
        int tmp = (t >= off) ? sh[t - off] : 0;
        __syncthreads();
        sh[t] += tmp;
        __syncthreads();
    }
    if (t < SCAN_NB) g_boff[t] = sh[t] - v;
}

__global__ void scan_add_kernel() {
    int t = threadIdx.x;
    int i = blockIdx.x * SCAN_B + t;
    if (i < N_NODES) {
        int v = g_rowptr[i + 1] + g_boff[blockIdx.x];
        g_rowptr[i + 1] = v;
        g_cursor[i] = v - g_cnt[i];
    }
    if (i == 0) g_rowptr[0] = 0;
}

__global__ void scatter_kernel(const int* __restrict__ src, const int* __restrict__ dst,
                               const int* __restrict__ et) {
    int e = blockIdx.x * blockDim.x + threadIdx.x;
    if (e >= N_EDGES) return;
    int d = dst[e];
    int pos = atomicAdd(&g_cursor[d], 1);
    g_srcS[pos] = src[e];
    g_dstS[pos] = d;
    g_etS[pos]  = et[e];
}

// ------------------------------ edge-type attention ------------------------
__global__ void etype_att_kernel(const float* __restrict__ eemb, const float* __restrict__ We,
                                 const float* __restrict__ ae, float* __restrict__ out, int H) {
    int t = blockIdx.x / H;
    int h = blockIdx.x % H;
    int d = threadIdx.x;
    int Wcols = H * 64;
    float v = 0.f;
    #pragma unroll 4
    for (int k = 0; k < 64; k++)
        v += eemb[t * 64 + k] * We[k * Wcols + h * 64 + d];
    v *= ae[h * 64 + d];
    __shared__ float sh[64];
    sh[d] = v;
    __syncthreads();
    #pragma unroll
    for (int o = 32; o > 0; o >>= 1) {
        if (d < o) sh[d] += sh[d + o];
        __syncthreads();
    }
    if (d == 0) out[t * H + h] = sh[0];
}

// ------------------------------ per-node el/er (layer 2 only) --------------
template <int H, int OUT, int STRIDE>
__global__ void node_attn_kernel(const float* __restrict__ feat, const float* __restrict__ al,
                                 const float* __restrict__ ar, float* __restrict__ el,
                                 float* __restrict__ er) {
    int warp = (blockIdx.x * blockDim.x + threadIdx.x) >> 5;
    int lane = threadIdx.x & 31;
    if (warp >= N_NODES) return;
    const float* f = feat + (size_t)warp * STRIDE;
    #pragma unroll
    for (int h = 0; h < H; h++) {
        float v = 0.f, w = 0.f;
        if (lane < OUT) {
            float x = f[h * OUT + lane];
            v = x * al[h * OUT + lane];
            w = x * ar[h * OUT + lane];
        }
        #pragma unroll
        for (int o = 16; o > 0; o >>= 1) {
            v += __shfl_down_sync(0xffffffffu, v, o);
            w += __shfl_down_sync(0xffffffffu, w, o);
        }
        if (lane == 0) {
            el[warp * H + h] = v;
            er[warp * H + h] = w;
        }
    }
}

// ------------------------------ fused GAT edge kernel (H=8) ----------------
template <bool BLEND, bool SAVE_A, bool RES>
__global__ void fused_gat8(const float* __restrict__ feat, const float* __restrict__ el,
                           const float* __restrict__ er, const float* __restrict__ etatt,
                           float* __restrict__ a0,
                           uint16_t* __restrict__ outh, uint16_t* __restrict__ outl) {
    int warp = (blockIdx.x * blockDim.x + threadIdx.x) >> 5;
    int lane = threadIdx.x & 31;
    if (warp >= N_NODES) return;
    int n = warp;
    int h = lane & 7, eslot = lane >> 3;
    float er_n = er[n * 8 + h];
    float eat[6];
    #pragma unroll
    for (int t = 0; t < 6; t++) eat[t] = etatt[t * 8 + h];
    int b = g_rowptr[n], e = g_rowptr[n + 1];

    float m = -1e30f, s = 0.f;
    for (int i0 = b; i0 < e; i0 += 4) {
        int i = i0 + eslot;
        if (i < e) {
            float ev = el[g_srcS[i] * 8 + h] + er_n + eat[g_etS[i]];
            ev = (ev > 0.f) ? ev : 0.2f * ev;
            float nm = fmaxf(m, ev);
            s = s * __expf(m - nm) + __expf(ev - nm);
            m = nm;
        }
    }
    #pragma unroll
    for (int off = 8; off <= 16; off <<= 1) {
        float om = __shfl_xor_sync(0xffffffffu, m, off);
        float os = __shfl_xor_sync(0xffffffffu, s, off);
        float nm = fmaxf(m, om);
        s = s * __expf(m - nm) + os * __expf(om - nm);
        m = nm;
    }

    float acc[8];
    #pragma unroll
    for (int h2 = 0; h2 < 8; h2++)
        acc[h2] = RES ? feat[(size_t)n * 512 + 256 + h2 * 32 + lane] : 0.f;

    int i0 = b;
    // fast path: full quads, branch-free, front-batched loads
    for (; i0 + 4 <= e; i0 += 4) {
        int i = i0 + eslot;
        int sidx = g_srcS[i];
        float ev = el[sidx * 8 + h] + er_n + eat[g_etS[i]];
        ev = (ev > 0.f) ? ev : 0.2f * ev;
        float a = __expf(ev - m) / s;
        if (BLEND) a = a * 0.95f + 0.05f * a0[(size_t)i * 8 + h];
        if (SAVE_A) a0[(size_t)i * 8 + h] = a;

        int s2[4];
        #pragma unroll
        for (int e2 = 0; e2 < 4; e2++)
            s2[e2] = __shfl_sync(0xffffffffu, sidx, e2 * 8);
        float tmp[4][8];
        #pragma unroll
        for (int e2 = 0; e2 < 4; e2++) {
            const float* f = feat + (size_t)s2[e2] * 512;
            #pragma unroll
            for (int h2 = 0; h2 < 8; h2++)
                tmp[e2][h2] = f[h2 * 32 + lane];
        }
        #pragma unroll
        for (int e2 = 0; e2 < 4; e2++)
            #pragma unroll
            for (int h2 = 0; h2 < 8; h2++) {
                float ah = __shfl_sync(0xffffffffu, a, e2 * 8 + h2);
                acc[h2] += ah * tmp[e2][h2];
            }
    }
    // tail (<4 edges)
    if (i0 < e) {
        int i = i0 + eslot;
        float a = 0.f;
        int sidx = 0;
        if (i < e) {
            sidx = g_srcS[i];
            float ev = el[sidx * 8 + h] + er_n + eat[g_etS[i]];
            ev = (ev > 0.f) ? ev : 0.2f * ev;
            a = __expf(ev - m) / s;
            if (BLEND) a = a * 0.95f + 0.05f * a0[(size_t)i * 8 + h];
            if (SAVE_A) a0[(size_t)i * 8 + h] = a;
        }
        #pragma unroll
        for (int e2 = 0; e2 < 4; e2++) {
            if (i0 + e2 < e) {
                int s2 = __shfl_sync(0xffffffffu, sidx, e2 * 8);
                const float* f = feat + (size_t)s2 * 512;
                #pragma unroll
                for (int h2 = 0; h2 < 8; h2++) {
                    float ah = __shfl_sync(0xffffffffu, a, e2 * 8 + h2);
                    acc[h2] += ah * f[h2 * 32 + lane];
                }
            }
        }
    }

    #pragma unroll
    for (int h2 = 0; h2 < 8; h2++) {
        float v = acc[h2];
        v = (v > 0.f) ? v : expm1f(v);
        uint16_t hb, lb;
        split_bf16(v, hb, lb);
        outh[(size_t)n * 256 + h2 * 32 + lane] = hb;
        outl[(size_t)n * 256 + h2 * 32 + lane] = lb;
    }
}

// ------------------------------ fused GAT edge kernel (H=1, out 16) --------
__global__ void fused_gat1(const float* __restrict__ f2, const float* __restrict__ el,
                           const float* __restrict__ er, const float* __restrict__ etatt,
                           float* __restrict__ out) {
    int warp = (blockIdx.x * blockDim.x + threadIdx.x) >> 5;
    int lane = threadIdx.x & 31;
    if (warp >= N_NODES) return;
    int n = warp;
    float er_n = er[n];
    float eat[6];
    #pragma unroll
    for (int t = 0; t < 6; t++) eat[t] = etatt[t];
    int b = g_rowptr[n], e = g_rowptr[n + 1];

    float m = -1e30f, s = 0.f;
    for (int i0 = b; i0 < e; i0 += 32) {
        int i = i0 + lane;
        if (i < e) {
            float ev = el[g_srcS[i]] + er_n + eat[g_etS[i]];
            ev = (ev > 0.f) ? ev : 0.2f * ev;
            float nm = fmaxf(m, ev);
            s = s * __expf(m - nm) + __expf(ev - nm);
            m = nm;
        }
    }
    #pragma unroll
    for (int off = 16; off > 0; off >>= 1) {
        float om = __shfl_xor_sync(0xffffffffu, m, off);
        float os = __shfl_xor_sync(0xffffffffu, s, off);
        float nm = fmaxf(m, om);
        s = s * __expf(m - nm) + os * __expf(om - nm);
        m = nm;
    }

    float acc = 0.f;
    if (lane < 16) acc = f2[(size_t)n * 32 + 16 + lane];
    for (int i = b; i < e; i++) {
        int s2 = g_srcS[i];
        float ev = el[s2] + er_n + eat[g_etS[i]];
        ev = (ev > 0.f) ? ev : 0.2f * ev;
        float a = __expf(ev - m) / s;
        if (lane < 16) acc += a * f2[(size_t)s2 * 32 + lane];
    }
    if (lane < 16) out[(size_t)n * 16 + lane] = acc;
}

// ---------------------------------------------------------------------------
static inline int cdiv(int a, int b) { return (a + b - 1) / b; }
static inline int stage_bytes(int NT) { return 2 * (128 * 20 * 4) + 2 * (NT * 32 * 20 * 4); }

extern "C" void kernel_launch(void* const* d_in, const int* in_sizes, int n_in,
                              void* d_out, int out_size) {
    const float* x0    = (const float*)d_in[0];
    const float* x1    = (const float*)d_in[1];
    const float* x2    = (const float*)d_in[2];
    const float* fcw0  = (const float*)d_in[3];
    const float* fcb0  = (const float*)d_in[4];
    const float* fcw1  = (const float*)d_in[5];
    const float* fcb1  = (const float*)d_in[6];
    const float* fcw2  = (const float*)d_in[7];
    const float* fcb2  = (const float*)d_in[8];
    const float* W0    = (const float*)d_in[9];
    const float* We0   = (const float*)d_in[10];
    const float* eemb0 = (const float*)d_in[11];
    const float* al0   = (const float*)d_in[12];
    const float* ar0   = (const float*)d_in[13];
    const float* ae0   = (const float*)d_in[14];
    const float* W1    = (const float*)d_in[15];
    const float* We1   = (const float*)d_in[16];
    const float* eemb1 = (const float*)d_in[17];
    const float* al1   = (const float*)d_in[18];
    const float* ar1   = (const float*)d_in[19];
    const float* ae1   = (const float*)d_in[20];
    const float* resW1 = (const float*)d_in[21];
    const float* W2    = (const float*)d_in[22];
    const float* We2   = (const float*)d_in[23];
    const float* eemb2 = (const float*)d_in[24];
    const float* al2   = (const float*)d_in[25];
    const float* ar2   = (const float*)d_in[26];
    const float* ae2   = (const float*)d_in[27];
    const float* resW2 = (const float*)d_in[28];
    const int*   src   = (const int*)d_in[29];
    const int*   dst   = (const int*)d_in[30];
    const int*   etype = (const int*)d_in[31];
    float* out = (float*)d_out;

    float *p_fr, *p_f2, *p_a0, *p_el, *p_er, *p_etatt;
    uint16_t *p_wh, *p_wl, *p_h0h, *p_h0l, *p_hAh, *p_hAl, *p_hBh, *p_hBl;
    int* p_cnt;
    cudaGetSymbolAddress((void**)&p_cnt, g_cnt);
    cudaGetSymbolAddress((void**)&p_fr, g_fr);
    cudaGetSymbolAddress((void**)&p_f2, g_f2);
    cudaGetSymbolAddress((void**)&p_a0, g_a0);
    cudaGetSymbolAddress((void**)&p_el, g_el);
    cudaGetSymbolAddress((void**)&p_er, g_er);
    cudaGetSymbolAddress((void**)&p_etatt, g_etatt);
    cudaGetSymbolAddress((void**)&p_wh, g_wh);
    cudaGetSymbolAddress((void**)&p_wl, g_wl);
    cudaGetSymbolAddress((void**)&p_h0h, g_h0h);
    cudaGetSymbolAddress((void**)&p_h0l, g_h0l);
    cudaGetSymbolAddress((void**)&p_hAh, g_hAh);
    cudaGetSymbolAddress((void**)&p_hAl, g_hAl);
    cudaGetSymbolAddress((void**)&p_hBh, g_hBh);
    cudaGetSymbolAddress((void**)&p_hBl, g_hBl);

    cudaFuncSetAttribute(gemm_cp<8, false, true>, cudaFuncAttributeMaxDynamicSharedMemorySize,
                         3 * stage_bytes(8));
    cudaFuncSetAttribute(gemm_cp<1, false, false>, cudaFuncAttributeMaxDynamicSharedMemorySize,
                         3 * stage_bytes(1));
    cudaFuncSetAttribute(proj_cp, cudaFuncAttributeMaxDynamicSharedMemorySize,
                         3 * stage_bytes(2));

    const int WB = cdiv(N_NODES * 32, 256);
    const int GY = cdiv(N_NODES, 128);
    const int PROJ_BLKS = cdiv(N0, 128) + cdiv(N1, 128) + cdiv(N2, 128);

    cudaMemsetAsync(p_cnt, 0, N_NODES * sizeof(int));
    cudaMemsetAsync(p_el, 0, N_NODES * 8 * sizeof(float));
    cudaMemsetAsync(p_er, 0, N_NODES * 8 * sizeof(float));
    conv_x<<<2048, 256>>>(x0, x1, x2);
    prep_all<<<cdiv(W_TOTAL, 256), 256>>>(fcw0, fcw1, fcw2, W0, W1, resW1, W2, resW2);
    proj_cp<<<dim3(1, PROJ_BLKS), 512, 3 * stage_bytes(2)>>>(fcb0, fcb1, fcb2);
    gemm_cp<8, false, true><<<dim3(1, GY), 512, 3 * stage_bytes(8)>>>(
        p_h0h, p_h0l, p_wh + OFF_W0, p_wl + OFF_W0, nullptr, p_fr, nullptr, nullptr,
        al0, ar0, p_el, p_er, N_NODES, 256, 64, 512);

    // CSR build
    hist_kernel<<<cdiv(N_EDGES, 256), 256>>>(dst);
    scan_block_kernel<<<SCAN_NB, SCAN_B>>>();
    scan_top_kernel<<<1, 128>>>();
    scan_add_kernel<<<SCAN_NB, SCAN_B>>>();
    scatter_kernel<<<cdiv(N_EDGES, 256), 256>>>(src, dst, etype);

    etype_att_kernel<<<6 * 8, 64>>>(eemb0, We0, ae0, p_etatt + 0, 8);
    etype_att_kernel<<<6 * 8, 64>>>(eemb1, We1, ae1, p_etatt + 48, 8);
    etype_att_kernel<<<6 * 1, 64>>>(eemb2, We2, ae2, p_etatt + 96, 1);

    // ---- layer 0 ----
    fused_gat8<false, true, false><<<WB, 256>>>(p_fr, p_el, p_er, p_etatt + 0,
                                                p_a0, p_hAh, p_hAl);

    // ---- layer 1 ----
    cudaMemsetAsync(p_el, 0, N_NODES * 8 * sizeof(float));
    cudaMemsetAsync(p_er, 0, N_NODES * 8 * sizeof(float));
    gemm_cp<8, false, true><<<dim3(2, GY), 512, 3 * stage_bytes(8)>>>(
        p_hAh, p_hAl, p_wh + OFF_W1C, p_wl + OFF_W1C, nullptr, p_fr, nullptr, nullptr,
        al1, ar1, p_el, p_er, N_NODES, 512, 256, 512);
    fused_gat8<true, false, true><<<WB, 256>>>(p_fr, p_el, p_er, p_etatt + 48,
                                               p_a0, p_hBh, p_hBl);

    // ---- layer 2 ----
    gemm_cp<1, false, false><<<dim3(1, GY), 512, 3 * stage_bytes(1)>>>(
        p_hBh, p_hBl, p_wh + OFF_BCAT, p_wl + OFF_BCAT, nullptr, p_f2, nullptr, nullptr,
        nullptr, nullptr, nullptr, nullptr, N_NODES, 32, 256, 32);
    node_attn_kernel<1, 16, 32><<<WB, 256>>>(p_f2, al2, ar2, p_el, p_er);
    fused_gat1<<<WB, 256>>>(p_f2, p_el, p_er, p_etatt + 96, out);
}

// round 10
// speedup vs baseline: 2.1266x; 1.0516x over previous
#include <cuda_runtime.h>
#include <cuda_bf16.h>
#include <math.h>
#include <stdint.h>
#include <string.h>

// ---------------------------------------------------------------------------
// SimpleHGN forward, round 10:
//  - CSR build + etype_att forked onto a side stream (graph-capture branch),
//    hidden under the conv/prep/proj/gemm0 chain
//  - layer-2 el/er fused into gemm<1> epilogue (node_attn removed entirely)
//  - GEMM: cp.async 3-stage + ldmatrix + mma.sync bf16 3-term (unchanged)
//  - fused GAT kernels unchanged
// ---------------------------------------------------------------------------

#define N_NODES 50000
#define N_EDGES 800000
#define N0 20000
#define N1 17000
#define N2 13000
#define SCAN_B 512
#define SCAN_NB ((N_NODES + SCAN_B - 1) / SCAN_B)

#define OFF_FCW0 0
#define OFF_FCW1 8192
#define OFF_FCW2 24576
#define OFF_W0   28672
#define OFF_W1C  45056
#define OFF_BCAT 176128
#define W_TOTAL  184320

// ------------------------------ side stream (created at library load) ------
struct StreamHolder {
    cudaStream_t s;
    cudaEvent_t a, b;
    StreamHolder() {
        cudaStreamCreateWithFlags(&s, cudaStreamNonBlocking);
        cudaEventCreateWithFlags(&a, cudaEventDisableTiming);
        cudaEventCreateWithFlags(&b, cudaEventDisableTiming);
    }
};
static StreamHolder g_sh;

// ------------------------------ scratch ------------------------------------
__device__ int   g_cnt[N_NODES];
__device__ int   g_rowptr[N_NODES + 1];
__device__ int   g_cursor[N_NODES];
__device__ int   g_bsum[SCAN_NB];
__device__ int   g_boff[SCAN_NB];
__device__ int   g_srcS[N_EDGES];
__device__ int   g_dstS[N_EDGES];
__device__ int   g_etS[N_EDGES];

__device__ float g_fr[(size_t)N_NODES * 512];
__device__ float g_f2[N_NODES * 32];
__device__ float g_a0[N_EDGES * 8];
__device__ float g_el[N_NODES * 8];
__device__ float g_er[N_NODES * 8];
__device__ float g_etatt[3 * 6 * 8];
__device__ uint16_t g_wh[W_TOTAL];
__device__ uint16_t g_wl[W_TOTAL];

__device__ uint16_t g_x0h[N0 * 128], g_x0l[N0 * 128];
__device__ uint16_t g_x1h[N1 * 256], g_x1l[N1 * 256];
__device__ uint16_t g_x2h[N2 * 64],  g_x2l[N2 * 64];
__device__ uint16_t g_h0h[N_NODES * 64],  g_h0l[N_NODES * 64];
__device__ uint16_t g_hAh[N_NODES * 256], g_hAl[N_NODES * 256];
__device__ uint16_t g_hBh[N_NODES * 256], g_hBl[N_NODES * 256];

// ------------------------------ helpers ------------------------------------
__device__ __forceinline__ uint32_t smem_u32(const void* p) {
    uint32_t a;
    asm("{ .reg .u64 t; cvta.to.shared.u64 t, %1; cvt.u32.u64 %0, t; }"
        : "=r"(a) : "l"(p));
    return a;
}

__device__ __forceinline__ void cp16(uint32_t dst, const void* src, int sz) {
    asm volatile("cp.async.cg.shared.global [%0], [%1], 16, %2;"
                 :: "r"(dst), "l"(src), "r"(sz) : "memory");
}
#define CP_COMMIT() asm volatile("cp.async.commit_group;" ::: "memory")
#define CP_WAIT1()  asm volatile("cp.async.wait_group 1;" ::: "memory")

#define LDSM_X4(r, addr) \
    asm volatile("ldmatrix.sync.aligned.m8n8.x4.shared.b16 {%0,%1,%2,%3}, [%4];" \
                 : "=r"((r)[0]), "=r"((r)[1]), "=r"((r)[2]), "=r"((r)[3]) \
                 : "r"(addr))

__device__ __forceinline__ void mma_bf16(float* c, uint32_t a0, uint32_t a1,
                                         uint32_t a2, uint32_t a3,
                                         uint32_t b0, uint32_t b1) {
    asm volatile(
        "mma.sync.aligned.m16n8k16.row.col.f32.bf16.bf16.f32 "
        "{%0,%1,%2,%3}, {%4,%5,%6,%7}, {%8,%9}, {%0,%1,%2,%3};"
        : "+f"(c[0]), "+f"(c[1]), "+f"(c[2]), "+f"(c[3])
        : "r"(a0), "r"(a1), "r"(a2), "r"(a3), "r"(b0), "r"(b1));
}

__device__ __forceinline__ uint16_t bf_bits(__nv_bfloat16 h) {
    uint16_t b;
    memcpy(&b, &h, 2);
    return b;
}

__device__ __forceinline__ void split_bf16(float v, uint16_t& hb, uint16_t& lb) {
    __nv_bfloat16 h = __float2bfloat16(v);
    float hf = __bfloat162float(h);
    __nv_bfloat16 l = __float2bfloat16(v - hf);
    hb = bf_bits(h);
    lb = bf_bits(l);
}

// ------------------------------ converts & weight prep ---------------------
__global__ void conv_x(const float* __restrict__ x0, const float* __restrict__ x1,
                       const float* __restrict__ x2) {
    const int S0 = N0 * 128, S1 = N1 * 256, S2 = N2 * 64;
    for (int i = blockIdx.x * blockDim.x + threadIdx.x; i < S0 + S1 + S2;
         i += gridDim.x * blockDim.x) {
        float v;
        uint16_t *ph, *pl;
        int j;
        if (i < S0)            { j = i;            v = x0[j]; ph = g_x0h; pl = g_x0l; }
        else if (i < S0 + S1)  { j = i - S0;       v = x1[j]; ph = g_x1h; pl = g_x1l; }
        else                   { j = i - S0 - S1;  v = x2[j]; ph = g_x2h; pl = g_x2l; }
        uint16_t hb, lb;
        split_bf16(v, hb, lb);
        ph[j] = hb;
        pl[j] = lb;
    }
}

__global__ void prep_all(const float* __restrict__ fcw0, const float* __restrict__ fcw1,
                         const float* __restrict__ fcw2, const float* __restrict__ W0,
                         const float* __restrict__ W1, const float* __restrict__ resW1,
                         const float* __restrict__ W2, const float* __restrict__ resW2) {
    int idx = blockIdx.x * blockDim.x + threadIdx.x;
    if (idx >= W_TOTAL) return;
    int N, base, rel;
    int mode = 0;
    const float* src = nullptr;
    if (idx < 8192)        { src = fcw0; N = 64;  base = OFF_FCW0; rel = idx; }
    else if (idx < 24576)  { src = fcw1; N = 64;  base = OFF_FCW1; rel = idx - 8192; }
    else if (idx < 28672)  { src = fcw2; N = 64;  base = OFF_FCW2; rel = idx - 24576; }
    else if (idx < 45056)  { src = W0;   N = 256; base = OFF_W0;   rel = idx - 28672; }
    else if (idx < 176128) { N = 512; base = OFF_W1C;  rel = idx - 45056; mode = 1; }
    else                   { N = 32;  base = OFF_BCAT; rel = idx - 176128; mode = 2; }
    int k = rel / N, n = rel - k * N;
    float v;
    if (mode == 1)      v = (n < 256) ? W1[k * 256 + n] : resW1[k * 256 + (n - 256)];
    else if (mode == 2) v = (n < 16) ? W2[k * 16 + n] : resW2[k * 16 + (n - 16)];
    else                v = src[rel];
    uint16_t hb, lb;
    split_bf16(v, hb, lb);
    int c = k >> 5, kp = (k & 31) >> 1;
    size_t word = (size_t)c * (N * 16) + (size_t)n * 16 + kp;
    g_wh[base + word * 2 + (k & 1)] = hb;
    g_wl[base + word * 2 + (k & 1)] = lb;
}

// ------------------------------ GEMM body ----------------------------------
// ELMODE: 0 = none, 1 = H=8 el/er epilogue (feat cols, col0==0),
//         2 = H=1 el/er epilogue (cols 0..15 of 32)
template <int NT, bool PLANES, int ELMODE>
__device__ __forceinline__ void gemm_body(
    const uint16_t* __restrict__ AhG, const uint16_t* __restrict__ AlG,
    const uint16_t* __restrict__ BhG, const uint16_t* __restrict__ BlG,
    const float* __restrict__ bias, float* __restrict__ C,
    uint16_t* __restrict__ Ch, uint16_t* __restrict__ Cl,
    const float* __restrict__ al, const float* __restrict__ ar,
    float* __restrict__ elp, float* __restrict__ erp,
    int M, int Ntot, int K, int ldc, int row0, int col0, char* smem) {
    constexpr int BN = NT * 32;
    constexpr int PAD = 20;
    constexpr int A_PLANE = 128 * PAD * 4;
    constexpr int B_PLANE = BN * PAD * 4;
    constexpr int OFF_AL2 = A_PLANE;
    constexpr int OFF_BH2 = 2 * A_PLANE;
    constexpr int OFF_BL2 = 2 * A_PLANE + B_PLANE;
    constexpr int STAGE = 2 * A_PLANE + 2 * B_PLANE;

    uint32_t sb = smem_u32(smem);
    int tid = threadIdx.x, wid = tid >> 5, lane = tid & 31;
    int g = lane >> 2, tig = lane & 3;
    int warpM = wid & 3, warpN = wid >> 2;

    float acc[2][NT][4];
    #pragma unroll
    for (int mt = 0; mt < 2; mt++)
        #pragma unroll
        for (int nt = 0; nt < NT; nt++)
            #pragma unroll
            for (int j = 0; j < 4; j++) acc[mt][nt][j] = 0.f;

    auto load_stage = [&](int s, int kt) {
        uint32_t base = sb + s * STAGE;
        {
            int r = tid >> 2, c4 = tid & 3;
            int gr = row0 + r;
            int sz = (gr < M) ? 16 : 0;
            size_t boff = ((size_t)gr * K + kt * 32) * 2 + c4 * 16;
            cp16(base + (r * PAD + c4 * 4) * 4, (const char*)AhG + boff, sz);
            cp16(base + OFF_AL2 + (r * PAD + c4 * 4) * 4, (const char*)AlG + boff, sz);
        }
        {
            #pragma unroll
            for (int lin = tid; lin < BN * 4; lin += 512) {
                int n = lin >> 2, c4 = lin & 3;
                size_t boff = ((size_t)kt * Ntot * 16 + (size_t)(col0 + n) * 16) * 4 + c4 * 16;
                cp16(base + OFF_BH2 + (n * PAD + c4 * 4) * 4, (const char*)BhG + boff, 16);
                cp16(base + OFF_BL2 + (n * PAD + c4 * 4) * 4, (const char*)BlG + boff, 16);
            }
        }
    };

    uint32_t a_base = (uint32_t)((warpM * 32 + (lane & 15)) * PAD +
                                 ((lane & 16) ? 4 : 0)) * 4;
    uint32_t b_base = (uint32_t)((warpN * (NT * 8) + (lane & 7) +
                                  ((lane & 16) ? 8 : 0)) * PAD +
                                 ((lane & 8) ? 4 : 0)) * 4;

    int nk = K >> 5;
    load_stage(0, 0);
    CP_COMMIT();
    load_stage(1, 1);
    CP_COMMIT();

    for (int kt = 0; kt < nk; kt++) {
        CP_WAIT1();
        __syncthreads();
        if (kt + 2 < nk) load_stage((kt + 2) % 3, kt + 2);
        CP_COMMIT();
        int s = kt % 3;
        uint32_t sA  = sb + s * STAGE;
        uint32_t sAl = sA + OFF_AL2;
        uint32_t sBh = sA + OFF_BH2;
        uint32_t sBl = sA + OFF_BL2;

        #pragma unroll
        for (int kh = 0; kh < 2; kh++) {
            uint32_t ko = kh * 32;
            uint32_t aH[2][4], aL[2][4];
            #pragma unroll
            for (int mt = 0; mt < 2; mt++) {
                LDSM_X4(aH[mt], sA + a_base + mt * 16 * PAD * 4 + ko);
                LDSM_X4(aL[mt], sAl + a_base + mt * 16 * PAD * 4 + ko);
            }
            if (NT >= 2) {
                #pragma unroll
                for (int nt2 = 0; nt2 < NT / 2; nt2++) {
                    uint32_t bh[4], bl[4];
                    LDSM_X4(bh, sBh + b_base + nt2 * 16 * PAD * 4 + ko);
                    LDSM_X4(bl, sBl + b_base + nt2 * 16 * PAD * 4 + ko);
                    #pragma unroll
                    for (int half = 0; half < 2; half++) {
                        int nt = nt2 * 2 + half;
                        uint32_t bh0 = bh[half * 2], bh1 = bh[half * 2 + 1];
                        uint32_t bl0 = bl[half * 2], bl1 = bl[half * 2 + 1];
                        #pragma unroll
                        for (int mt = 0; mt < 2; mt++) {
                            mma_bf16(acc[mt][nt], aH[mt][0], aH[mt][1], aH[mt][2], aH[mt][3], bh0, bh1);
                            mma_bf16(acc[mt][nt], aL[mt][0], aL[mt][1], aL[mt][2], aL[mt][3], bh0, bh1);
                            mma_bf16(acc[mt][nt], aH[mt][0], aH[mt][1], aH[mt][2], aH[mt][3], bl0, bl1);
                        }
                    }
                }
            } else {
                const uint32_t* BsH = (const uint32_t*)(smem + s * STAGE + OFF_BH2);
                const uint32_t* BsL = (const uint32_t*)(smem + s * STAGE + OFF_BL2);
                int kp0 = kh * 8;
                int n0 = warpN * 8;
                int bbase = (n0 + g) * PAD + kp0 + tig;
                uint32_t bh0 = BsH[bbase], bh1 = BsH[bbase + 4];
                uint32_t bl0 = BsL[bbase], bl1 = BsL[bbase + 4];
                #pragma unroll
                for (int mt = 0; mt < 2; mt++) {
                    mma_bf16(acc[mt][0], aH[mt][0], aH[mt][1], aH[mt][2], aH[mt][3], bh0, bh1);
                    mma_bf16(acc[mt][0], aL[mt][0], aL[mt][1], aL[mt][2], aL[mt][3], bh0, bh1);
                    mma_bf16(acc[mt][0], aH[mt][0], aH[mt][1], aH[mt][2], aH[mt][3], bl0, bl1);
                }
            }
        }
        __syncthreads();
    }

    // ---- store epilogue ----
    #pragma unroll
    for (int mt = 0; mt < 2; mt++) {
        #pragma unroll
        for (int nt = 0; nt < NT; nt++) {
            int r0 = row0 + warpM * 32 + mt * 16 + g;
            int c = col0 + warpN * (NT * 8) + nt * 8 + tig * 2;
            #pragma unroll
            for (int half = 0; half < 2; half++) {
                int r = r0 + half * 8;
                if (r >= M) continue;
                float v0 = acc[mt][nt][half * 2 + 0];
                float v1 = acc[mt][nt][half * 2 + 1];
                if (PLANES) {
                    v0 += bias[c];
                    v1 += bias[c + 1];
                    uint16_t h0b, l0b, h1b, l1b;
                    split_bf16(v0, h0b, l0b);
                    split_bf16(v1, h1b, l1b);
                    *(uint32_t*)&Ch[(size_t)r * ldc + c] =
                        (uint32_t)h0b | ((uint32_t)h1b << 16);
                    *(uint32_t*)&Cl[(size_t)r * ldc + c] =
                        (uint32_t)l0b | ((uint32_t)l1b << 16);
                } else {
                    *(float2*)&C[(size_t)r * ldc + c] = make_float2(v0, v1);
                }
            }
        }
    }

    // ---- el/er epilogue, H=8 (feat cols live in the col0==0 launch block) ----
    if (ELMODE == 1 && col0 == 0) {
        float elacc[2][2][2], eracc[2][2][2];
        #pragma unroll
        for (int mt = 0; mt < 2; mt++)
            #pragma unroll
            for (int half = 0; half < 2; half++)
                #pragma unroll
                for (int hl = 0; hl < 2; hl++) {
                    elacc[mt][half][hl] = 0.f;
                    eracc[mt][half][hl] = 0.f;
                }
        #pragma unroll
        for (int nt = 0; nt < NT; nt++) {
            int hl = nt >> 2;
            int h = (warpN * (NT * 8) + nt * 8) >> 5;
            int o = (nt * 8 + tig * 2) & 31;
            float al0v = al[h * 32 + o], al1v = al[h * 32 + o + 1];
            float ar0v = ar[h * 32 + o], ar1v = ar[h * 32 + o + 1];
            #pragma unroll
            for (int mt = 0; mt < 2; mt++)
                #pragma unroll
                for (int half = 0; half < 2; half++) {
                    float v0 = acc[mt][nt][half * 2 + 0];
                    float v1 = acc[mt][nt][half * 2 + 1];
                    elacc[mt][half][hl] += v0 * al0v + v1 * al1v;
                    eracc[mt][half][hl] += v0 * ar0v + v1 * ar1v;
                }
        }
        #pragma unroll
        for (int mt = 0; mt < 2; mt++)
            #pragma unroll
            for (int half = 0; half < 2; half++)
                #pragma unroll
                for (int hl = 0; hl < 2; hl++) {
                    float ev = elacc[mt][half][hl];
                    float rv = eracc[mt][half][hl];
                    ev += __shfl_xor_sync(0xffffffffu, ev, 1);
                    ev += __shfl_xor_sync(0xffffffffu, ev, 2);
                    rv += __shfl_xor_sync(0xffffffffu, rv, 1);
                    rv += __shfl_xor_sync(0xffffffffu, rv, 2);
                    if (tig == 0) {
                        int r = row0 + warpM * 32 + mt * 16 + g + half * 8;
                        int h2 = warpN * ((NT * 8) / 32) + hl;
                        if (r < M) {
                            atomicAdd(&elp[r * 8 + h2], ev);
                            atomicAdd(&erp[r * 8 + h2], rv);
                        }
                    }
                }
    }

    // ---- el/er epilogue, H=1 (f2 layout: cols 0..15 feat, 16..31 res) ----
    if (ELMODE == 2) {
        if (warpN < 2) {   // warp-uniform: cols warpN*8+tig*2 in [0,16)
            #pragma unroll
            for (int mt = 0; mt < 2; mt++)
                #pragma unroll
                for (int half = 0; half < 2; half++) {
                    int c = warpN * 8 + tig * 2;
                    float v0 = acc[mt][0][half * 2 + 0];
                    float v1 = acc[mt][0][half * 2 + 1];
                    float ev = v0 * al[c] + v1 * al[c + 1];
                    float rv = v0 * ar[c] + v1 * ar[c + 1];
                    ev += __shfl_xor_sync(0xffffffffu, ev, 1);
                    ev += __shfl_xor_sync(0xffffffffu, ev, 2);
                    rv += __shfl_xor_sync(0xffffffffu, rv, 1);
                    rv += __shfl_xor_sync(0xffffffffu, rv, 2);
                    if (tig == 0) {
                        int r = row0 + warpM * 32 + mt * 16 + g + half * 8;
                        if (r < M) {
                            atomicAdd(&elp[r], ev);
                            atomicAdd(&erp[r], rv);
                        }
                    }
                }
        }
    }
}

template <int NT, bool PLANES, int ELMODE>
__global__ void __launch_bounds__(512) gemm_cp(
    const uint16_t* __restrict__ AhG, const uint16_t* __restrict__ AlG,
    const uint16_t* __restrict__ BhG, const uint16_t* __restrict__ BlG,
    const float* __restrict__ bias, float* __restrict__ C,
    uint16_t* __restrict__ Ch, uint16_t* __restrict__ Cl,
    const float* al, const float* ar, float* elp, float* erp,
    int M, int Ntot, int K, int ldc) {
    extern __shared__ char smem[];
    gemm_body<NT, PLANES, ELMODE>(AhG, AlG, BhG, BlG, bias, C, Ch, Cl, al, ar, elp, erp,
                                  M, Ntot, K, ldc, blockIdx.y * 128, blockIdx.x * NT * 32, smem);
}

__global__ void __launch_bounds__(512) proj_cp(const float* __restrict__ fcb0,
                                               const float* __restrict__ fcb1,
                                               const float* __restrict__ fcb2) {
    extern __shared__ char smem[];
    const int NB0 = (N0 + 127) / 128;
    const int NB01 = NB0 + (N1 + 127) / 128;
    int by = blockIdx.y;
    if (by < NB0) {
        gemm_body<2, true, 0>(g_x0h, g_x0l, g_wh + OFF_FCW0, g_wl + OFF_FCW0, fcb0,
                              nullptr, g_h0h, g_h0l, nullptr, nullptr, nullptr, nullptr,
                              N0, 64, 128, 64, by * 128, 0, smem);
    } else if (by < NB01) {
        gemm_body<2, true, 0>(g_x1h, g_x1l, g_wh + OFF_FCW1, g_wl + OFF_FCW1, fcb1,
                              nullptr, g_h0h + (size_t)N0 * 64, g_h0l + (size_t)N0 * 64,
                              nullptr, nullptr, nullptr, nullptr,
                              N1, 64, 256, 64, (by - NB0) * 128, 0, smem);
    } else {
        gemm_body<2, true, 0>(g_x2h, g_x2l, g_wh + OFF_FCW2, g_wl + OFF_FCW2, fcb2,
                              nullptr, g_h0h + (size_t)(N0 + N1) * 64,
                              g_h0l + (size_t)(N0 + N1) * 64,
                              nullptr, nullptr, nullptr, nullptr,
                              N2, 64, 64, 64, (by - NB01) * 128, 0, smem);
    }
}

// ------------------------------ CSR build ----------------------------------
__global__ void hist_kernel(const int* __restrict__ dst) {
    int e = blockIdx.x * blockDim.x + threadIdx.x;
    if (e < N_EDGES) atomicAdd(&g_cnt[dst[e]], 1);
}

__global__ void scan_block_kernel() {
    __shared__ int sh[SCAN_B];
    int t = threadIdx.x;
    int i = blockIdx.x * SCAN_B + t;
    int v = (i < N_NODES) ? g_cnt[i] : 0;
    sh[t] = v;
    __syncthreads();
    #pragma unroll
    for (int off = 1; off < SCAN_B; off <<= 1) {
        int tmp = (t >= off) ? sh[t - off] : 0;
        __syncthreads();
        sh[t] += tmp;
        __syncthreads();
    }
    if (i < N_NODES) g_rowptr[i + 1] = sh[t];
    if (t == SCAN_B - 1) g_bsum[blockIdx.x] = sh[t];
}

__global__ void scan_top_kernel() {
    __shared__ int sh[128];
    int t = threadIdx.x;
    int v = (t < SCAN_NB) ? g_bsum[t] : 0;
    sh[t] = v;
    __syncthreads();
    #pragma unroll
    for (int off = 1; off < 128; off <<= 1) {
        int tmp = (t >= off) ? sh[t - off] : 0;
        __syncthreads();
        sh[t] += tmp;
        __syncthreads();
    }
    if (t < SCAN_NB) g_boff[t] = sh[t] - v;
}

__global__ void scan_add_kernel() {
    int t = threadIdx.x;
    int i = blockIdx.x * SCAN_B + t;
    if (i < N_NODES) {
        int v = g_rowptr[i + 1] + g_boff[blockIdx.x];
        g_rowptr[i + 1] = v;
        g_cursor[i] = v - g_cnt[i];
    }
    if (i == 0) g_rowptr[0] = 0;
}

__global__ void scatter_kernel(const int* __restrict__ src, const int* __restrict__ dst,
                               const int* __restrict__ et) {
    int e = blockIdx.x * blockDim.x + threadIdx.x;
    if (e >= N_EDGES) return;
    int d = dst[e];
    int pos = atomicAdd(&g_cursor[d], 1);
    g_srcS[pos] = src[e];
    g_dstS[pos] = d;
    g_etS[pos]  = et[e];
}

// ------------------------------ edge-type attention ------------------------
__global__ void etype_att_kernel(const float* __restrict__ eemb, const float* __restrict__ We,
                                 const float* __restrict__ ae, float* __restrict__ out, int H) {
    int t = blockIdx.x / H;
    int h = blockIdx.x % H;
    int d = threadIdx.x;
    int Wcols = H * 64;
    float v = 0.f;
    #pragma unroll 4
    for (int k = 0; k < 64; k++)
        v += eemb[t * 64 + k] * We[k * Wcols + h * 64 + d];
    v *= ae[h * 64 + d];
    __shared__ float sh[64];
    sh[d] = v;
    __syncthreads();
    #pragma unroll
    for (int o = 32; o > 0; o >>= 1) {
        if (d < o) sh[d] += sh[d + o];
        __syncthreads();
    }
    if (d == 0) out[t * H + h] = sh[0];
}

// ------------------------------ fused GAT edge kernel (H=8) ----------------
template <bool BLEND, bool SAVE_A, bool RES>
__global__ void fused_gat8(const float* __restrict__ feat, const float* __restrict__ el,
                           const float* __restrict__ er, const float* __restrict__ etatt,
                           float* __restrict__ a0,
                           uint16_t* __restrict__ outh, uint16_t* __restrict__ outl) {
    int warp = (blockIdx.x * blockDim.x + threadIdx.x) >> 5;
    int lane = threadIdx.x & 31;
    if (warp >= N_NODES) return;
    int n = warp;
    int h = lane & 7, eslot = lane >> 3;
    float er_n = er[n * 8 + h];
    float eat[6];
    #pragma unroll
    for (int t = 0; t < 6; t++) eat[t] = etatt[t * 8 + h];
    int b = g_rowptr[n], e = g_rowptr[n + 1];

    float m = -1e30f, s = 0.f;
    for (int i0 = b; i0 < e; i0 += 4) {
        int i = i0 + eslot;
        if (i < e) {
            float ev = el[g_srcS[i] * 8 + h] + er_n + eat[g_etS[i]];
            ev = (ev > 0.f) ? ev : 0.2f * ev;
            float nm = fmaxf(m, ev);
            s = s * __expf(m - nm) + __expf(ev - nm);
            m = nm;
        }
    }
    #pragma unroll
    for (int off = 8; off <= 16; off <<= 1) {
        float om = __shfl_xor_sync(0xffffffffu, m, off);
        float os = __shfl_xor_sync(0xffffffffu, s, off);
        float nm = fmaxf(m, om);
        s = s * __expf(m - nm) + os * __expf(om - nm);
        m = nm;
    }

    float acc[8];
    #pragma unroll
    for (int h2 = 0; h2 < 8; h2++)
        acc[h2] = RES ? feat[(size_t)n * 512 + 256 + h2 * 32 + lane] : 0.f;

    int i0 = b;
    for (; i0 + 4 <= e; i0 += 4) {
        int i = i0 + eslot;
        int sidx = g_srcS[i];
        float ev = el[sidx * 8 + h] + er_n + eat[g_etS[i]];
        ev = (ev > 0.f) ? ev : 0.2f * ev;
        float a = __expf(ev - m) / s;
        if (BLEND) a = a * 0.95f + 0.05f * a0[(size_t)i * 8 + h];
        if (SAVE_A) a0[(size_t)i * 8 + h] = a;

        int s2[4];
        #pragma unroll
        for (int e2 = 0; e2 < 4; e2++)
            s2[e2] = __shfl_sync(0xffffffffu, sidx, e2 * 8);
        float tmp[4][8];
        #pragma unroll
        for (int e2 = 0; e2 < 4; e2++) {
            const float* f = feat + (size_t)s2[e2] * 512;
            #pragma unroll
            for (int h2 = 0; h2 < 8; h2++)
                tmp[e2][h2] = f[h2 * 32 + lane];
        }
        #pragma unroll
        for (int e2 = 0; e2 < 4; e2++)
            #pragma unroll
            for (int h2 = 0; h2 < 8; h2++) {
                float ah = __shfl_sync(0xffffffffu, a, e2 * 8 + h2);
                acc[h2] += ah * tmp[e2][h2];
            }
    }
    if (i0 < e) {
        int i = i0 + eslot;
        float a = 0.f;
        int sidx = 0;
        if (i < e) {
            sidx = g_srcS[i];
            float ev = el[sidx * 8 + h] + er_n + eat[g_etS[i]];
            ev = (ev > 0.f) ? ev : 0.2f * ev;
            a = __expf(ev - m) / s;
            if (BLEND) a = a * 0.95f + 0.05f * a0[(size_t)i * 8 + h];
            if (SAVE_A) a0[(size_t)i * 8 + h] = a;
        }
        #pragma unroll
        for (int e2 = 0; e2 < 4; e2++) {
            if (i0 + e2 < e) {
                int s2 = __shfl_sync(0xffffffffu, sidx, e2 * 8);
                const float* f = feat + (size_t)s2 * 512;
                #pragma unroll
                for (int h2 = 0; h2 < 8; h2++) {
                    float ah = __shfl_sync(0xffffffffu, a, e2 * 8 + h2);
                    acc[h2] += ah * f[h2 * 32 + lane];
                }
            }
        }
    }

    #pragma unroll
    for (int h2 = 0; h2 < 8; h2++) {
        float v = acc[h2];
        v = (v > 0.f) ? v : expm1f(v);
        uint16_t hb, lb;
        split_bf16(v, hb, lb);
        outh[(size_t)n * 256 + h2 * 32 + lane] = hb;
        outl[(size_t)n * 256 + h2 * 32 + lane] = lb;
    }
}

// ------------------------------ fused GAT edge kernel (H=1, out 16) --------
__global__ void fused_gat1(const float* __restrict__ f2, const float* __restrict__ el,
                           const float* __restrict__ er, const float* __restrict__ etatt,
                           float* __restrict__ out) {
    int warp = (blockIdx.x * blockDim.x + threadIdx.x) >> 5;
    int lane = threadIdx.x & 31;
    if (warp >= N_NODES) return;
    int n = warp;
    float er_n = er[n];
    float eat[6];
    #pragma unroll
    for (int t = 0; t < 6; t++) eat[t] = etatt[t];
    int b = g_rowptr[n], e = g_rowptr[n + 1];

    float m = -1e30f, s = 0.f;
    for (int i0 = b; i0 < e; i0 += 32) {
        int i = i0 + lane;
        if (i < e) {
            float ev = el[g_srcS[i]] + er_n + eat[g_etS[i]];
            ev = (ev > 0.f) ? ev : 0.2f * ev;
            float nm = fmaxf(m, ev);
            s = s * __expf(m - nm) + __expf(ev - nm);
            m = nm;
        }
    }
    #pragma unroll
    for (int off = 16; off > 0; off >>= 1) {
        float om = __shfl_xor_sync(0xffffffffu, m, off);
        float os = __shfl_xor_sync(0xffffffffu, s, off);
        float nm = fmaxf(m, om);
        s = s * __expf(m - nm) + os * __expf(om - nm);
        m = nm;
    }

    float acc = 0.f;
    if (lane < 16) acc = f2[(size_t)n * 32 + 16 + lane];
    for (int i = b; i < e; i++) {
        int s2 = g_srcS[i];
        float ev = el[s2] + er_n + eat[g_etS[i]];
        ev = (ev > 0.f) ? ev : 0.2f * ev;
        float a = __expf(ev - m) / s;
        if (lane < 16) acc += a * f2[(size_t)s2 * 32 + lane];
    }
    if (lane < 16) out[(size_t)n * 16 + lane] = acc;
}

// ---------------------------------------------------------------------------
static inline int cdiv(int a, int b) { return (a + b - 1) / b; }
static inline int stage_bytes(int NT) { return 2 * (128 * 20 * 4) + 2 * (NT * 32 * 20 * 4); }

extern "C" void kernel_launch(void* const* d_in, const int* in_sizes, int n_in,
                              void* d_out, int out_size) {
    const float* x0    = (const float*)d_in[0];
    const float* x1    = (const float*)d_in[1];
    const float* x2    = (const float*)d_in[2];
    const float* fcw0  = (const float*)d_in[3];
    const float* fcb0  = (const float*)d_in[4];
    const float* fcw1  = (const float*)d_in[5];
    const float* fcb1  = (const float*)d_in[6];
    const float* fcw2  = (const float*)d_in[7];
    const float* fcb2  = (const float*)d_in[8];
    const float* W0    = (const float*)d_in[9];
    const float* We0   = (const float*)d_in[10];
    const float* eemb0 = (const float*)d_in[11];
    const float* al0   = (const float*)d_in[12];
    const float* ar0   = (const float*)d_in[13];
    const float* ae0   = (const float*)d_in[14];
    const float* W1    = (const float*)d_in[15];
    const float* We1   = (const float*)d_in[16];
    const float* eemb1 = (const float*)d_in[17];
    const float* al1   = (const float*)d_in[18];
    const float* ar1   = (const float*)d_in[19];
    const float* ae1   = (const float*)d_in[20];
    const float* resW1 = (const float*)d_in[21];
    const float* W2    = (const float*)d_in[22];
    const float* We2   = (const float*)d_in[23];
    const float* eemb2 = (const float*)d_in[24];
    const float* al2   = (const float*)d_in[25];
    const float* ar2   = (const float*)d_in[26];
    const float* ae2   = (const float*)d_in[27];
    const float* resW2 = (const float*)d_in[28];
    const int*   src   = (const int*)d_in[29];
    const int*   dst   = (const int*)d_in[30];
    const int*   etype = (const int*)d_in[31];
    float* out = (float*)d_out;

    float *p_fr, *p_f2, *p_a0, *p_el, *p_er, *p_etatt;
    uint16_t *p_wh, *p_wl, *p_h0h, *p_h0l, *p_hAh, *p_hAl, *p_hBh, *p_hBl;
    int* p_cnt;
    cudaGetSymbolAddress((void**)&p_cnt, g_cnt);
    cudaGetSymbolAddress((void**)&p_fr, g_fr);
    cudaGetSymbolAddress((void**)&p_f2, g_f2);
    cudaGetSymbolAddress((void**)&p_a0, g_a0);
    cudaGetSymbolAddress((void**)&p_el, g_el);
    cudaGetSymbolAddress((void**)&p_er, g_er);
    cudaGetSymbolAddress((void**)&p_etatt, g_etatt);
    cudaGetSymbolAddress((void**)&p_wh, g_wh);
    cudaGetSymbolAddress((void**)&p_wl, g_wl);
    cudaGetSymbolAddress((void**)&p_h0h, g_h0h);
    cudaGetSymbolAddress((void**)&p_h0l, g_h0l);
    cudaGetSymbolAddress((void**)&p_hAh, g_hAh);
    cudaGetSymbolAddress((void**)&p_hAl, g_hAl);
    cudaGetSymbolAddress((void**)&p_hBh, g_hBh);
    cudaGetSymbolAddress((void**)&p_hBl, g_hBl);

    cudaFuncSetAttribute(gemm_cp<8, false, 1>, cudaFuncAttributeMaxDynamicSharedMemorySize,
                         3 * stage_bytes(8));
    cudaFuncSetAttribute(gemm_cp<1, false, 2>, cudaFuncAttributeMaxDynamicSharedMemorySize,
                         3 * stage_bytes(1));
    cudaFuncSetAttribute(proj_cp, cudaFuncAttributeMaxDynamicSharedMemorySize,
                         3 * stage_bytes(2));

    const int WB = cdiv(N_NODES * 32, 256);
    const int GY = cdiv(N_NODES, 128);
    const int PROJ_BLKS = cdiv(N0, 128) + cdiv(N1, 128) + cdiv(N2, 128);
    cudaStream_t s2 = g_sh.s;

    // ---- fork: CSR build + etype_att on side stream ----
    cudaEventRecord(g_sh.a, 0);
    cudaStreamWaitEvent(s2, g_sh.a, 0);
    cudaMemsetAsync(p_cnt, 0, N_NODES * sizeof(int), s2);

    // ---- main chain: converts -> proj -> layer-0 GEMM ----
    cudaMemsetAsync(p_el, 0, N_NODES * 8 * sizeof(float));
    cudaMemsetAsync(p_er, 0, N_NODES * 8 * sizeof(float));
    conv_x<<<2048, 256>>>(x0, x1, x2);
    prep_all<<<cdiv(W_TOTAL, 256), 256>>>(fcw0, fcw1, fcw2, W0, W1, resW1, W2, resW2);
    proj_cp<<<dim3(1, PROJ_BLKS), 512, 3 * stage_bytes(2)>>>(fcb0, fcb1, fcb2);
    gemm_cp<8, false, 1><<<dim3(1, GY), 512, 3 * stage_bytes(8)>>>(
        p_h0h, p_h0l, p_wh + OFF_W0, p_wl + OFF_W0, nullptr, p_fr, nullptr, nullptr,
        al0, ar0, p_el, p_er, N_NODES, 256, 64, 512);

    // ---- side stream: CSR build + edge-type attention ----
    hist_kernel<<<cdiv(N_EDGES, 256), 256, 0, s2>>>(dst);
    scan_block_kernel<<<SCAN_NB, SCAN_B, 0, s2>>>();
    scan_top_kernel<<<1, 128, 0, s2>>>();
    scan_add_kernel<<<SCAN_NB, SCAN_B, 0, s2>>>();
    scatter_kernel<<<cdiv(N_EDGES, 256), 256, 0, s2>>>(src, dst, etype);
    etype_att_kernel<<<6 * 8, 64, 0, s2>>>(eemb0, We0, ae0, p_etatt + 0, 8);
    etype_att_kernel<<<6 * 8, 64, 0, s2>>>(eemb1, We1, ae1, p_etatt + 48, 8);
    etype_att_kernel<<<6 * 1, 64, 0, s2>>>(eemb2, We2, ae2, p_etatt + 96, 1);
    cudaEventRecord(g_sh.b, s2);
    cudaStreamWaitEvent(0, g_sh.b, 0);

    // ---- layer 0 ----
    fused_gat8<false, true, false><<<WB, 256>>>(p_fr, p_el, p_er, p_etatt + 0,
                                                p_a0, p_hAh, p_hAl);

    // ---- layer 1 ----
    cudaMemsetAsync(p_el, 0, N_NODES * 8 * sizeof(float));
    cudaMemsetAsync(p_er, 0, N_NODES * 8 * sizeof(float));
    gemm_cp<8, false, 1><<<dim3(2, GY), 512, 3 * stage_bytes(8)>>>(
        p_hAh, p_hAl, p_wh + OFF_W1C, p_wl + OFF_W1C, nullptr, p_fr, nullptr, nullptr,
        al1, ar1, p_el, p_er, N_NODES, 512, 256, 512);
    fused_gat8<true, false, true><<<WB, 256>>>(p_fr, p_el, p_er, p_etatt + 48,
                                               p_a0, p_hBh, p_hBl);

    // ---- layer 2 (el/er fused into gemm epilogue, ELMODE=2) ----
    cudaMemsetAsync(p_el, 0, N_NODES * sizeof(float));
    cudaMemsetAsync(p_er, 0, N_NODES * sizeof(float));
    gemm_cp<1, false, 2><<<dim3(1, GY), 512, 3 * stage_bytes(1)>>>(
        p_hBh, p_hBl, p_wh + OFF_BCAT, p_wl + OFF_BCAT, nullptr, p_f2, nullptr, nullptr,
        al2, ar2, p_el, p_er, N_NODES, 32, 256, 32);
    fused_gat1<<<WB, 256>>>(p_f2, p_el, p_er, p_etatt + 96, out);
}